// round 4
// baseline (speedup 1.0000x reference)
#include <cuda_runtime.h>
#include <cuda_bf16.h>
#include <cstdint>

#define NP 100000
#define NA 50000
#define DIM 128
#define EE  500000

#if defined(__CUDA_ARCH__) && defined(__CUDA_ARCH_FEAT_SM103_ALL)
#define USE_TC 1
#else
#define USE_TC 0
#endif

// ---------------------------------------------------------------------------
// Scratch (allocation-guard-safe __device__ globals)
__device__ float g_Hc[(size_t)NP * DIM];          // x_paper  @ W_cites
__device__ float g_Hw[(size_t)NA * DIM];          // x_author @ W_writes
__device__ float g_deg[NP];                       // deg_c + deg_w
// Pre-swizzled bf16 operand images of W^T: [matrix][hi|lo][128*128]
__device__ __nv_bfloat16 g_WT[3][2][DIM * DIM];

// ---------------------------------------------------------------------------
// Swizzled byte offset of element (r,k) in a 128x128 bf16 K-major blocked-atom
// tile: atom = 8 rows x 64 bf16 (1024B), tiling (16 atom-rows, 2 atom-cols),
// atom_offset = atom_row + atom_col*16. SW128 swizzle on top.
__device__ __forceinline__ uint32_t bf16_off(int r, int k) {
    uint32_t b = (uint32_t)(((r >> 3) + (k >> 6) * 16) * 1024
                            + (r & 7) * 128 + (k & 63) * 2);
    return b ^ ((b >> 3) & 0x70);
}

#if USE_TC
// ---------------------------------------------------------------------------
// PTX helpers (sm_103a tcgen05, cg1) — only compiled on the 'a' target.
__device__ __forceinline__ uint32_t s2u(const void* p) {
    uint32_t a;
    asm("{ .reg .u64 t; cvta.to.shared.u64 t, %1; cvt.u32.u64 %0, t; }"
        : "=r"(a) : "l"(p));
    return a;
}
__device__ __forceinline__ bool elect1() {
    uint32_t p;
    asm volatile("{ .reg .pred p; elect.sync _|p, 0xFFFFFFFF; selp.b32 %0,1,0,p; }"
                 : "=r"(p));
    return p != 0;
}
__device__ __forceinline__ void mma_bf16_ss(uint32_t d, uint64_t a, uint64_t b,
                                            uint32_t idesc, uint32_t en) {
    asm volatile(
        "{\n\t.reg .pred p;\n\tsetp.ne.u32 p, %4, 0;\n\t"
        "tcgen05.mma.cta_group::1.kind::f16 [%0], %1, %2, %3, {%5,%5,%5,%5}, p;\n\t}"
        :: "r"(d), "l"(a), "l"(b), "r"(idesc), "r"(en), "r"(0u) : "memory");
}
#define TC_ALLOC(sa, n)  asm volatile("tcgen05.alloc.cta_group::1.sync.aligned.shared::cta.b32 [%0], %1;" :: "r"(sa), "r"(n) : "memory")
#define TC_DEALLOC(t, n) asm volatile("tcgen05.dealloc.cta_group::1.sync.aligned.b32 %0, %1;" :: "r"(t), "r"(n))
#define TC_RELINQ()      asm volatile("tcgen05.relinquish_alloc_permit.cta_group::1.sync.aligned;")
#define TC_COMMIT(mb)    asm volatile("tcgen05.commit.cta_group::1.mbarrier::arrive::one.shared::cluster.b64 [%0];" :: "r"(mb) : "memory")
#define TC_WAIT_LD()     asm volatile("tcgen05.wait::ld.sync.aligned;" ::: "memory")
#define TC_FENCE_AFTER() asm volatile("tcgen05.fence::after_thread_sync;" ::: "memory")
#define MBAR_INIT(mb, c) asm volatile("mbarrier.init.shared.b64 [%0], %1;" :: "r"(mb), "r"(c) : "memory")
#define MBAR_INVAL(mb)   asm volatile("mbarrier.inval.shared.b64 [%0];" :: "r"(mb) : "memory")
#define MBAR_WAIT(mb, ph) do {                                                      \
    uint32_t _m = (mb), _p = (ph), _d;                                              \
    asm volatile("{ .reg .pred p; mbarrier.try_wait.parity.acquire.cta.shared::cta.b64 p, [%1], %2; selp.b32 %0,1,0,p; }" \
                 : "=r"(_d) : "r"(_m), "r"(_p) : "memory");                         \
    if (!_d) {                                                                      \
        asm volatile("{ .reg .pred P1; WL_%=: mbarrier.try_wait.parity.acquire.cta.shared::cta.b64 P1, [%0], %1, 0x989680; @P1 bra.uni WD_%=; bra.uni WL_%=; WD_%=: }" \
                     :: "r"(_m), "r"(_p) : "memory");                               \
    }                                                                               \
} while (0)
#define LDTM_X32(r, a)                                                              \
    asm volatile("tcgen05.ld.sync.aligned.32x32b.x32.b32 "                          \
        "{%0,%1,%2,%3,%4,%5,%6,%7,%8,%9,%10,%11,%12,%13,%14,%15,"                   \
        "%16,%17,%18,%19,%20,%21,%22,%23,%24,%25,%26,%27,%28,%29,%30,%31}, [%32];"  \
        : "=r"((r)[0]),"=r"((r)[1]),"=r"((r)[2]),"=r"((r)[3]),                      \
          "=r"((r)[4]),"=r"((r)[5]),"=r"((r)[6]),"=r"((r)[7]),                      \
          "=r"((r)[8]),"=r"((r)[9]),"=r"((r)[10]),"=r"((r)[11]),                    \
          "=r"((r)[12]),"=r"((r)[13]),"=r"((r)[14]),"=r"((r)[15]),                  \
          "=r"((r)[16]),"=r"((r)[17]),"=r"((r)[18]),"=r"((r)[19]),                  \
          "=r"((r)[20]),"=r"((r)[21]),"=r"((r)[22]),"=r"((r)[23]),                  \
          "=r"((r)[24]),"=r"((r)[25]),"=r"((r)[26]),"=r"((r)[27]),                  \
          "=r"((r)[28]),"=r"((r)[29]),"=r"((r)[30]),"=r"((r)[31])                   \
        : "r"(a))

// SMEM descriptor: SW128, version=1(Blackwell), LBO=1, SBO=64 (K-major)
static __device__ __forceinline__ uint64_t smem_desc(uint32_t addr) {
    const uint64_t base = (uint64_t(2) << 61) | (uint64_t(1) << 46)
                        | (uint64_t(64) << 32) | (uint64_t(1) << 16);
    return base | ((uint64_t)(addr >> 4) & 0x3FFF);
}
#endif // USE_TC

// ---------------------------------------------------------------------------
__global__ void __launch_bounds__(256) zero_deg_kernel() {
    int i = blockIdx.x * 256 + threadIdx.x;
    if (i < NP) g_deg[i] = 0.0f;
}

// ---------------------------------------------------------------------------
// Convert one W[128,128] (stored W[k][n]) into swizzled bf16 hi/lo images of
// W^T (operand B rows = n, cols = k).
__global__ void __launch_bounds__(256) wconv_kernel(
    const float* __restrict__ W, __nv_bfloat16* __restrict__ hi,
    __nv_bfloat16* __restrict__ lo)
{
    for (int i = threadIdx.x; i < DIM * DIM; i += 256) {
        int k = i >> 7, n = i & 127;
        float x = W[i];                               // W[k*128 + n]
        __nv_bfloat16 h = __float2bfloat16(x);
        __nv_bfloat16 l = __float2bfloat16(x - __bfloat162float(h));
        uint32_t e = bf16_off(n, k) >> 1;             // element index
        hi[e] = h;
        lo[e] = l;
    }
}

// ---------------------------------------------------------------------------
// Y[n_rows,128] = X[n_rows,128] @ W[128,128].
// tcgen05 path: bf16 3-pass split (hi*hi + hi*lo + lo*hi), fp32 TMEM accum.
// Fallback path (non-'a' PTX target): SIMT smem-tiled GEMM on float W.
// Both: 128 rows/CTA, 256 threads, dynamic smem.
#define SM_TMEM 0
#define SM_MBAR 8
#define SM_AHI  1024
#define SM_ALO  (SM_AHI + 32768)
#define SM_BHI  (SM_ALO + 32768)
#define SM_BLO  (SM_BHI + 32768)
#define SM_TOTAL (SM_BLO + 32768)   // 132096 >= fallback's 131072

// idesc kind::f16: dtype=F32(1<<4), atype=BF16(1<<7), btype=BF16(1<<10),
// (N/8)<<17, (M/16)<<24  -> M=128, N=128
#define IDESC_BF16_128 0x8200490u

__global__ void __launch_bounds__(256, 1) gemm_kernel(
    const float* __restrict__ X, const float* __restrict__ Wf,
    const __nv_bfloat16* __restrict__ Bhi_img,
    const __nv_bfloat16* __restrict__ Blo_img,
    float* __restrict__ Y, int n_rows)
{
    extern __shared__ char smem[];
    const int tid = threadIdx.x, w = tid >> 5, lane = tid & 31;
    const int row0 = blockIdx.x * 128;

#if USE_TC
    uint32_t sb = s2u(smem);

    if (w == 0) TC_ALLOC(sb + SM_TMEM, 128);
    if (tid == 0) MBAR_INIT(sb + SM_MBAR, 1);

    // Stage B (pre-swizzled images): straight float4 copies
    for (int i = tid; i < 2048; i += 256) {
        ((float4*)(smem + SM_BHI))[i] = ((const float4*)Bhi_img)[i];
        ((float4*)(smem + SM_BLO))[i] = ((const float4*)Blo_img)[i];
    }

    // Stage A: coalesced float4 loads of X, split to bf16 hi/lo, store
    // swizzled (8B-aligned chunks; swizzle only touches bits [6:4]).
    for (int i = tid; i < 4096; i += 256) {
        int r = i >> 5, c4 = i & 31, gr = row0 + r;
        float4 v = make_float4(0.f, 0.f, 0.f, 0.f);
        if (gr < n_rows) v = ((const float4*)(X + (size_t)gr * DIM))[c4];

        __nv_bfloat16 hx = __float2bfloat16(v.x), hy = __float2bfloat16(v.y);
        __nv_bfloat16 hz = __float2bfloat16(v.z), hw = __float2bfloat16(v.w);
        __nv_bfloat16 lx = __float2bfloat16(v.x - __bfloat162float(hx));
        __nv_bfloat16 ly = __float2bfloat16(v.y - __bfloat162float(hy));
        __nv_bfloat16 lz = __float2bfloat16(v.z - __bfloat162float(hz));
        __nv_bfloat16 lw = __float2bfloat16(v.w - __bfloat162float(hw));

        __nv_bfloat162 h01 = __halves2bfloat162(hx, hy);
        __nv_bfloat162 h23 = __halves2bfloat162(hz, hw);
        __nv_bfloat162 l01 = __halves2bfloat162(lx, ly);
        __nv_bfloat162 l23 = __halves2bfloat162(lz, lw);

        uint32_t off = bf16_off(r, c4 * 4);
        *(uint2*)(smem + SM_AHI + off) =
            make_uint2(*(uint32_t*)&h01, *(uint32_t*)&h23);
        *(uint2*)(smem + SM_ALO + off) =
            make_uint2(*(uint32_t*)&l01, *(uint32_t*)&l23);
    }

    asm volatile("fence.proxy.async.shared::cta;" ::: "memory");
    __syncthreads();

    uint32_t tmem;
    asm volatile("ld.shared.b32 %0, [%1];" : "=r"(tmem) : "r"(sb + SM_TMEM));

    // MMA: 3 passes (hi*hi, hi*lo, lo*hi), 8 K-steps each, fp32 TMEM accum
    if (w == 0 && elect1()) {
        uint64_t dAh = smem_desc(sb + SM_AHI), dAl = smem_desc(sb + SM_ALO);
        uint64_t dBh = smem_desc(sb + SM_BHI), dBl = smem_desc(sb + SM_BLO);
        uint64_t pa[3] = {dAh, dAh, dAl};
        uint64_t pb[3] = {dBh, dBl, dBh};
        // K-step desc offsets (16B units): 4 steps in atom_col0 (+0,2,4,6),
        // 4 in atom_col1 at byte 16384 (+1024,...)
        const int koff[8] = {0, 2, 4, 6, 1024, 1026, 1028, 1030};
        uint32_t en = 0;
        for (int p = 0; p < 3; p++)
            for (int ks = 0; ks < 8; ks++) {
                mma_bf16_ss(tmem, pa[p] + koff[ks], pb[p] + koff[ks],
                            IDESC_BF16_128, en);
                en = 1;
            }
        TC_COMMIT(sb + SM_MBAR);
    }

    __syncthreads();
    MBAR_WAIT(sb + SM_MBAR, 0);
    TC_FENCE_AFTER();

    // Epilogue: warps 0-3 -> cols 0..63, warps 4-7 -> cols 64..127.
    // Each warp reads its hw subpartition = rows (w&3)*32 + lane.
    {
        uint32_t d[64];
        uint32_t c0 = (uint32_t)(w >> 2) * 64;
        LDTM_X32(d, tmem + c0);
        LDTM_X32(d + 32, tmem + c0 + 32);
        TC_WAIT_LD();
        int gr = row0 + (w & 3) * 32 + lane;
        if (gr < n_rows) {
            float4* yp = (float4*)(Y + (size_t)gr * DIM + c0);
            #pragma unroll
            for (int j = 0; j < 16; j++)
                yp[j] = make_float4(__uint_as_float(d[4 * j + 0]),
                                    __uint_as_float(d[4 * j + 1]),
                                    __uint_as_float(d[4 * j + 2]),
                                    __uint_as_float(d[4 * j + 3]));
        }
    }

    __syncthreads();
    if (tid == 0) MBAR_INVAL(sb + SM_MBAR);
    __syncthreads();
    if (w == 0) {
        TC_RELINQ();
        TC_DEALLOC(tmem, 128);
    }
#else
    // ---------------- SIMT fallback (non-'a' target) ----------------
    float*  smf = (float*)smem;
    float4* Ws4 = (float4*)smf;                     // 128 x 32 float4
    float4* Xs4 = (float4*)(smf + DIM * DIM);       // 128 x 32 float4

    for (int i = tid; i < DIM * 32; i += 256)
        Ws4[i] = ((const float4*)Wf)[i];
    for (int i = tid; i < 128 * 32; i += 256) {
        int gr = row0 + (i >> 5);
        float4 v = make_float4(0.f, 0.f, 0.f, 0.f);
        if (gr < n_rows) v = ((const float4*)(X + (size_t)gr * DIM))[i & 31];
        Xs4[i] = v;
    }
    __syncthreads();

    float acc[16][4];
    #pragma unroll
    for (int i = 0; i < 16; i++)
        acc[i][0] = acc[i][1] = acc[i][2] = acc[i][3] = 0.f;

    for (int k4 = 0; k4 < 32; k4++) {
        float4 w0 = Ws4[(k4 * 4 + 0) * 32 + lane];
        float4 w1 = Ws4[(k4 * 4 + 1) * 32 + lane];
        float4 w2 = Ws4[(k4 * 4 + 2) * 32 + lane];
        float4 w3 = Ws4[(k4 * 4 + 3) * 32 + lane];
        #pragma unroll
        for (int i = 0; i < 16; i++) {
            float4 xv = Xs4[(w + 8 * i) * 32 + k4];
            acc[i][0] += xv.x * w0.x + xv.y * w1.x + xv.z * w2.x + xv.w * w3.x;
            acc[i][1] += xv.x * w0.y + xv.y * w1.y + xv.z * w2.y + xv.w * w3.y;
            acc[i][2] += xv.x * w0.z + xv.y * w1.z + xv.z * w2.z + xv.w * w3.z;
            acc[i][3] += xv.x * w0.w + xv.y * w1.w + xv.z * w2.w + xv.w * w3.w;
        }
    }

    #pragma unroll
    for (int i = 0; i < 16; i++) {
        int gr = row0 + w + 8 * i;
        if (gr < n_rows)
            ((float4*)(Y + (size_t)gr * DIM))[lane] =
                make_float4(acc[i][0], acc[i][1], acc[i][2], acc[i][3]);
    }
#endif
}

// ---------------------------------------------------------------------------
// One warp per edge: gather 512B row H[src]; one red.v4 per lane into out[dst].
__global__ void __launch_bounds__(256) scatter_kernel(
    const float* __restrict__ H, const int* __restrict__ src,
    const int* __restrict__ dst, float* __restrict__ out, int nE)
{
    int e    = (blockIdx.x * 256 + threadIdx.x) >> 5;
    int lane = threadIdx.x & 31;
    if (e >= nE) return;

    int s = __ldg(src + e);
    int d = __ldg(dst + e);

    float4 v = ((const float4*)(H + (size_t)s * DIM))[lane];
    float* op = out + (size_t)d * DIM + lane * 4;
    asm volatile("red.global.add.v4.f32 [%0], {%1, %2, %3, %4};"
                 :: "l"(op), "f"(v.x), "f"(v.y), "f"(v.z), "f"(v.w)
                 : "memory");

    if (lane == 0)
        asm volatile("red.global.add.f32 [%0], %1;"
                     :: "l"(&g_deg[d]), "f"(1.0f) : "memory");
}

// ---------------------------------------------------------------------------
__global__ void __launch_bounds__(256) finalize_kernel(
    float* __restrict__ out, const float* __restrict__ bias)
{
    int i = blockIdx.x * 256 + threadIdx.x;
    if (i >= NP * 32) return;
    int row = i >> 5;
    int c4  = i & 31;

    float inv = 1.0f / (g_deg[row] + 1.0f);
    float4 v = ((float4*)out)[i];
    float4 b = ((const float4*)bias)[c4];
    v.x = fmaxf(fmaf(v.x, inv, b.x), 0.f);
    v.y = fmaxf(fmaf(v.y, inv, b.y), 0.f);
    v.z = fmaxf(fmaf(v.z, inv, b.z), 0.f);
    v.w = fmaxf(fmaf(v.w, inv, b.w), 0.f);
    ((float4*)out)[i] = v;
}

// ---------------------------------------------------------------------------
extern "C" void kernel_launch(void* const* d_in, const int* in_sizes, int n_in,
                              void* d_out, int out_size)
{
    const float* x_paper    = (const float*)d_in[0];
    const float* x_author   = (const float*)d_in[1];
    const float* W_cites    = (const float*)d_in[2];
    const float* W_writes   = (const float*)d_in[3];
    const float* W_self     = (const float*)d_in[4];
    const float* bias       = (const float*)d_in[5];
    const int*   cites_src  = (const int*)d_in[6];
    const int*   cites_dst  = (const int*)d_in[7];
    const int*   writes_src = (const int*)d_in[8];
    const int*   writes_dst = (const int*)d_in[9];
    float*       out        = (float*)d_out;

    cudaFuncSetAttribute(gemm_kernel,
                         cudaFuncAttributeMaxDynamicSharedMemorySize, SM_TOTAL);

    void *pHc = nullptr, *pHw = nullptr, *pWT = nullptr;
    cudaGetSymbolAddress(&pHc, g_Hc);
    cudaGetSymbolAddress(&pHw, g_Hw);
    cudaGetSymbolAddress(&pWT, g_WT);
    __nv_bfloat16* WT = (__nv_bfloat16*)pWT;
    const int WSZ = DIM * DIM;
    __nv_bfloat16 *Wc_h = WT + 0 * WSZ, *Wc_l = WT + 1 * WSZ;
    __nv_bfloat16 *Ww_h = WT + 2 * WSZ, *Ww_l = WT + 3 * WSZ;
    __nv_bfloat16 *Ws_h = WT + 4 * WSZ, *Ws_l = WT + 5 * WSZ;

    // 1. degree accumulator -> 0; W -> swizzled bf16 hi/lo images
    zero_deg_kernel<<<(NP + 255) / 256, 256>>>();
    wconv_kernel<<<1, 256>>>(W_cites,  Wc_h, Wc_l);
    wconv_kernel<<<1, 256>>>(W_writes, Ww_h, Ww_l);
    wconv_kernel<<<1, 256>>>(W_self,   Ws_h, Ws_l);

    // 2. GEMMs (self-transform writes d_out = accumulator init)
    gemm_kernel<<<(NP + 127) / 128, 256, SM_TOTAL>>>(x_paper,  W_self,   Ws_h, Ws_l, out,         NP);
    gemm_kernel<<<(NP + 127) / 128, 256, SM_TOTAL>>>(x_paper,  W_cites,  Wc_h, Wc_l, (float*)pHc, NP);
    gemm_kernel<<<(NA + 127) / 128, 256, SM_TOTAL>>>(x_author, W_writes, Ww_h, Ww_l, (float*)pHw, NA);

    // 3. edge scatter (vectorized L2 atomics) + fused degree counting
    scatter_kernel<<<EE / 8, 256>>>((const float*)pHc, cites_src,  cites_dst,  out, EE);
    scatter_kernel<<<EE / 8, 256>>>((const float*)pHw, writes_src, writes_dst, out, EE);

    // 4. mean + bias + relu
    finalize_kernel<<<(NP * 32 + 255) / 256, 256>>>(out, bias);
}

// round 5
// speedup vs baseline: 1.4203x; 1.4203x over previous
#include <cuda_runtime.h>
#include <cuda_bf16.h>
#include <cstdint>

#define NP 100000
#define NA 50000
#define DIM 128
#define EE  500000

#if defined(__CUDA_ARCH__) && defined(__CUDA_ARCH_FEAT_SM103_ALL)
#define USE_TC 1
#else
#define USE_TC 0
#endif

// ---------------------------------------------------------------------------
// Scratch (allocation-guard-safe __device__ globals)
__device__ float g_Hc[(size_t)NP * DIM];          // x_paper  @ W_cites
__device__ float g_Hw[(size_t)NA * DIM];          // x_author @ W_writes
__device__ float g_deg[NP];                       // deg_c + deg_w
// Pre-swizzled bf16 operand images of W^T: [matrix][hi|lo][128*128]
__device__ __nv_bfloat16 g_WT[3][2][DIM * DIM];

// ---------------------------------------------------------------------------
// Swizzled byte offset of element (r,k) in a 128x128 bf16 K-major blocked-atom
// tile: atom = 8 rows x 64 bf16 (1024B), 16 atom-rows x 2 atom-cols.
__device__ __forceinline__ uint32_t bf16_off(int r, int k) {
    uint32_t b = (uint32_t)(((r >> 3) + (k >> 6) * 16) * 1024
                            + (r & 7) * 128 + (k & 63) * 2);
    return b ^ ((b >> 3) & 0x70);
}

#if USE_TC
// ---------------------------------------------------------------------------
// PTX helpers (sm_103a tcgen05, cg1) — only on the 'a' target.
__device__ __forceinline__ uint32_t s2u(const void* p) {
    uint32_t a;
    asm("{ .reg .u64 t; cvta.to.shared.u64 t, %1; cvt.u32.u64 %0, t; }"
        : "=r"(a) : "l"(p));
    return a;
}
__device__ __forceinline__ bool elect1() {
    uint32_t p;
    asm volatile("{ .reg .pred p; elect.sync _|p, 0xFFFFFFFF; selp.b32 %0,1,0,p; }"
                 : "=r"(p));
    return p != 0;
}
// TS form: A in TMEM, B in SMEM
__device__ __forceinline__ void mma_bf16_ts(uint32_t d, uint32_t a, uint64_t b,
                                            uint32_t idesc, uint32_t en) {
    asm volatile(
        "{\n\t.reg .pred p;\n\tsetp.ne.u32 p, %4, 0;\n\t"
        "tcgen05.mma.cta_group::1.kind::f16 [%0], [%1], %2, %3, {%5,%5,%5,%5}, p;\n\t}"
        :: "r"(d), "r"(a), "l"(b), "r"(idesc), "r"(en), "r"(0u) : "memory");
}
#define TC_ALLOC(sa, n)  asm volatile("tcgen05.alloc.cta_group::1.sync.aligned.shared::cta.b32 [%0], %1;" :: "r"(sa), "r"(n) : "memory")
#define TC_DEALLOC(t, n) asm volatile("tcgen05.dealloc.cta_group::1.sync.aligned.b32 %0, %1;" :: "r"(t), "r"(n))
#define TC_RELINQ()      asm volatile("tcgen05.relinquish_alloc_permit.cta_group::1.sync.aligned;")
#define TC_COMMIT(mb)    asm volatile("tcgen05.commit.cta_group::1.mbarrier::arrive::one.shared::cluster.b64 [%0];" :: "r"(mb) : "memory")
#define TC_WAIT_LD()     asm volatile("tcgen05.wait::ld.sync.aligned;" ::: "memory")
#define TC_WAIT_ST()     asm volatile("tcgen05.wait::st.sync.aligned;" ::: "memory")
#define TC_FENCE_BEFORE() asm volatile("tcgen05.fence::before_thread_sync;" ::: "memory")
#define TC_FENCE_AFTER()  asm volatile("tcgen05.fence::after_thread_sync;" ::: "memory")
#define MBAR_INIT(mb, c) asm volatile("mbarrier.init.shared.b64 [%0], %1;" :: "r"(mb), "r"(c) : "memory")
#define MBAR_INVAL(mb)   asm volatile("mbarrier.inval.shared.b64 [%0];" :: "r"(mb) : "memory")
#define MBAR_WAIT(mb, ph) do {                                                      \
    uint32_t _m = (mb), _p = (ph), _d;                                              \
    asm volatile("{ .reg .pred p; mbarrier.try_wait.parity.acquire.cta.shared::cta.b64 p, [%1], %2; selp.b32 %0,1,0,p; }" \
                 : "=r"(_d) : "r"(_m), "r"(_p) : "memory");                         \
    if (!_d) {                                                                      \
        asm volatile("{ .reg .pred P1; WL_%=: mbarrier.try_wait.parity.acquire.cta.shared::cta.b64 P1, [%0], %1, 0x989680; @P1 bra.uni WD_%=; bra.uni WL_%=; WD_%=: }" \
                     :: "r"(_m), "r"(_p) : "memory");                               \
    }                                                                               \
} while (0)
#define LDTM_X32(r, a)                                                              \
    asm volatile("tcgen05.ld.sync.aligned.32x32b.x32.b32 "                          \
        "{%0,%1,%2,%3,%4,%5,%6,%7,%8,%9,%10,%11,%12,%13,%14,%15,"                   \
        "%16,%17,%18,%19,%20,%21,%22,%23,%24,%25,%26,%27,%28,%29,%30,%31}, [%32];"  \
        : "=r"((r)[0]),"=r"((r)[1]),"=r"((r)[2]),"=r"((r)[3]),                      \
          "=r"((r)[4]),"=r"((r)[5]),"=r"((r)[6]),"=r"((r)[7]),                      \
          "=r"((r)[8]),"=r"((r)[9]),"=r"((r)[10]),"=r"((r)[11]),                    \
          "=r"((r)[12]),"=r"((r)[13]),"=r"((r)[14]),"=r"((r)[15]),                  \
          "=r"((r)[16]),"=r"((r)[17]),"=r"((r)[18]),"=r"((r)[19]),                  \
          "=r"((r)[20]),"=r"((r)[21]),"=r"((r)[22]),"=r"((r)[23]),                  \
          "=r"((r)[24]),"=r"((r)[25]),"=r"((r)[26]),"=r"((r)[27]),                  \
          "=r"((r)[28]),"=r"((r)[29]),"=r"((r)[30]),"=r"((r)[31])                   \
        : "r"(a))
#define STTM_X16(a, r)                                                              \
    asm volatile("tcgen05.st.sync.aligned.32x32b.x16.b32 [%0], "                    \
        "{%1,%2,%3,%4,%5,%6,%7,%8,%9,%10,%11,%12,%13,%14,%15,%16};"                 \
        :: "r"(a),                                                                  \
           "r"((r)[0]),"r"((r)[1]),"r"((r)[2]),"r"((r)[3]),                         \
           "r"((r)[4]),"r"((r)[5]),"r"((r)[6]),"r"((r)[7]),                         \
           "r"((r)[8]),"r"((r)[9]),"r"((r)[10]),"r"((r)[11]),                       \
           "r"((r)[12]),"r"((r)[13]),"r"((r)[14]),"r"((r)[15])                      \
        : "memory")

// SMEM descriptor: SW128, version=1(Blackwell), LBO=1, SBO=64 (K-major)
static __device__ __forceinline__ uint64_t smem_desc(uint32_t addr) {
    const uint64_t base = (uint64_t(2) << 61) | (uint64_t(1) << 46)
                        | (uint64_t(64) << 32) | (uint64_t(1) << 16);
    return base | ((uint64_t)(addr >> 4) & 0x3FFF);
}
#endif // USE_TC

// ---------------------------------------------------------------------------
__global__ void __launch_bounds__(256) zero_deg_kernel() {
    int i = blockIdx.x * 256 + threadIdx.x;
    if (i < NP) g_deg[i] = 0.0f;
}

// ---------------------------------------------------------------------------
// All three W matrices -> swizzled bf16 hi/lo W^T images, fully parallel.
__global__ void __launch_bounds__(256) wconv_kernel(
    const float* __restrict__ W0, const float* __restrict__ W1,
    const float* __restrict__ W2)
{
    int i = blockIdx.x * 256 + threadIdx.x;            // 0 .. 3*16384-1
    if (i >= 3 * DIM * DIM) return;
    int m = i >> 14, e = i & (DIM * DIM - 1);
    const float* W = (m == 0) ? W0 : (m == 1) ? W1 : W2;
    int k = e >> 7, n = e & 127;
    float x = W[e];                                     // W[k][n]
    __nv_bfloat16 h = __float2bfloat16(x);
    __nv_bfloat16 l = __float2bfloat16(x - __bfloat162float(h));
    uint32_t o = bf16_off(n, k) >> 1;
    g_WT[m][0][o] = h;
    g_WT[m][1][o] = l;
}

// ---------------------------------------------------------------------------
// Y[n_rows,128] = X[n_rows,128] @ W[128,128].
// TC path: TS-mode tcgen05. A (bf16 hi/lo) stored straight to TMEM from
// registers; SMEM holds only the pre-swizzled B images -> 2 CTAs/SM overlap.
// TMEM cols: D 0..127, A_hi 128..191, A_lo 192..255 (alloc 256).
#define SM_TMEM 0
#define SM_MBAR 8
#define SM_BHI  1024
#define SM_BLO  (SM_BHI + 32768)
#define SM_TOTAL (SM_BLO + 32768)   // 66560

#define TM_D    0
#define TM_AHI  128
#define TM_ALO  192

// idesc kind::f16: dtype=F32, atype=BF16, btype=BF16, (N/8)<<17, (M/16)<<24
#define IDESC_BF16_128 0x8200490u

__global__ void __launch_bounds__(256, 2) gemm_kernel(
    const float* __restrict__ X, const float* __restrict__ Wf,
    const __nv_bfloat16* __restrict__ Bhi_img,
    const __nv_bfloat16* __restrict__ Blo_img,
    float* __restrict__ Y, int n_rows)
{
    extern __shared__ char smem[];
    const int tid = threadIdx.x, w = tid >> 5, lane = tid & 31;
    const int row0 = blockIdx.x * 128;

#if USE_TC
    uint32_t sb = s2u(smem);

    if (w == 0) TC_ALLOC(sb + SM_TMEM, 256);
    if (tid == 0) MBAR_INIT(sb + SM_MBAR, 1);
    __syncthreads();

    uint32_t tmem;
    asm volatile("ld.shared.b32 %0, [%1];" : "=r"(tmem) : "r"(sb + SM_TMEM));

    // Stage B (pre-swizzled images): straight float4 copies
    for (int i = tid; i < 2048; i += 256) {
        ((float4*)(smem + SM_BHI))[i] = ((const float4*)Bhi_img)[i];
        ((float4*)(smem + SM_BLO))[i] = ((const float4*)Blo_img)[i];
    }

    // A -> TMEM directly. wg0 (warps 0-3) stores A_hi, wg1 stores A_lo.
    // Thread handles row (wg_tid); per quarter: 8 float4 -> 16 bf16x2 -> STTM.
    {
        int wg_tid = tid & 127;
        int hi_path = (tid < 128);
        int gr = row0 + wg_tid;
        const float4* xr = (const float4*)(X + (size_t)gr * DIM);
        uint32_t warp_off = (uint32_t)(wg_tid >> 5) << 21;
        uint32_t abase = tmem + (hi_path ? TM_AHI : TM_ALO) + warp_off;
        #pragma unroll
        for (int q = 0; q < 4; q++) {
            float4 vv[8];
            #pragma unroll
            for (int j = 0; j < 8; j++)
                vv[j] = (gr < n_rows) ? xr[q * 8 + j]
                                      : make_float4(0.f, 0.f, 0.f, 0.f);
            uint32_t rr[16];
            #pragma unroll
            for (int j = 0; j < 8; j++) {
                float a0 = vv[j].x, a1 = vv[j].y, a2 = vv[j].z, a3 = vv[j].w;
                __nv_bfloat16 h0 = __float2bfloat16(a0);
                __nv_bfloat16 h1 = __float2bfloat16(a1);
                __nv_bfloat16 h2 = __float2bfloat16(a2);
                __nv_bfloat16 h3 = __float2bfloat16(a3);
                __nv_bfloat16 o0 = h0, o1 = h1, o2 = h2, o3 = h3;
                if (!hi_path) {
                    o0 = __float2bfloat16(a0 - __bfloat162float(h0));
                    o1 = __float2bfloat16(a1 - __bfloat162float(h1));
                    o2 = __float2bfloat16(a2 - __bfloat162float(h2));
                    o3 = __float2bfloat16(a3 - __bfloat162float(h3));
                }
                __nv_bfloat162 p01 = __halves2bfloat162(o0, o1);
                __nv_bfloat162 p23 = __halves2bfloat162(o2, o3);
                rr[2 * j]     = *(uint32_t*)&p01;
                rr[2 * j + 1] = *(uint32_t*)&p23;
            }
            STTM_X16(abase + q * 16, rr);
        }
        TC_WAIT_ST();
    }

    TC_FENCE_BEFORE();
    asm volatile("fence.proxy.async.shared::cta;" ::: "memory");
    __syncthreads();

    // MMA: 3 passes (Ahi*Bhi, Ahi*Blo, Alo*Bhi), 8 K-steps, fp32 TMEM accum
    if (w == 0 && elect1()) {
        TC_FENCE_AFTER();
        uint64_t dBh = smem_desc(sb + SM_BHI), dBl = smem_desc(sb + SM_BLO);
        uint32_t aA[3] = {tmem + TM_AHI, tmem + TM_AHI, tmem + TM_ALO};
        uint64_t pb[3] = {dBh, dBl, dBh};
        const int koff[8] = {0, 2, 4, 6, 1024, 1026, 1028, 1030};
        uint32_t en = 0;
        for (int p = 0; p < 3; p++)
            for (int ks = 0; ks < 8; ks++) {
                mma_bf16_ts(tmem + TM_D, aA[p] + ks * 8, pb[p] + koff[ks],
                            IDESC_BF16_128, en);
                en = 1;
            }
        TC_COMMIT(sb + SM_MBAR);
    }

    __syncthreads();
    MBAR_WAIT(sb + SM_MBAR, 0);
    TC_FENCE_AFTER();

    // Epilogue: warps 0-3 -> cols 0..63, warps 4-7 -> cols 64..127.
    {
        uint32_t d[64];
        uint32_t c0 = (uint32_t)(w >> 2) * 64;
        LDTM_X32(d, tmem + TM_D + c0);
        LDTM_X32(d + 32, tmem + TM_D + c0 + 32);
        TC_WAIT_LD();
        int gr = row0 + (w & 3) * 32 + lane;
        if (gr < n_rows) {
            float4* yp = (float4*)(Y + (size_t)gr * DIM + c0);
            #pragma unroll
            for (int j = 0; j < 16; j++)
                yp[j] = make_float4(__uint_as_float(d[4 * j + 0]),
                                    __uint_as_float(d[4 * j + 1]),
                                    __uint_as_float(d[4 * j + 2]),
                                    __uint_as_float(d[4 * j + 3]));
        }
    }

    __syncthreads();
    if (tid == 0) MBAR_INVAL(sb + SM_MBAR);
    __syncthreads();
    if (w == 0) {
        TC_RELINQ();
        TC_DEALLOC(tmem, 256);
    }
#else
    // -------- SIMT fallback (non-'a' PTX target only; never runs on GB300) --
    float4* Ws4 = (float4*)smem;                    // 128 x 32 float4 = 64KB
    for (int i = tid; i < DIM * 32; i += 256)
        Ws4[i] = ((const float4*)Wf)[i];
    __syncthreads();

    float acc[16][4];
    #pragma unroll
    for (int i = 0; i < 16; i++)
        acc[i][0] = acc[i][1] = acc[i][2] = acc[i][3] = 0.f;

    for (int k4 = 0; k4 < 32; k4++) {
        float4 w0 = Ws4[(k4 * 4 + 0) * 32 + lane];
        float4 w1 = Ws4[(k4 * 4 + 1) * 32 + lane];
        float4 w2 = Ws4[(k4 * 4 + 2) * 32 + lane];
        float4 w3 = Ws4[(k4 * 4 + 3) * 32 + lane];
        for (int i = 0; i < 16; i++) {
            int gr = row0 + w + 8 * i;
            float4 xv = (gr < n_rows)
                ? __ldg((const float4*)(X + (size_t)gr * DIM) + k4)
                : make_float4(0.f, 0.f, 0.f, 0.f);
            acc[i][0] += xv.x * w0.x + xv.y * w1.x + xv.z * w2.x + xv.w * w3.x;
            acc[i][1] += xv.x * w0.y + xv.y * w1.y + xv.z * w2.y + xv.w * w3.y;
            acc[i][2] += xv.x * w0.z + xv.y * w1.z + xv.z * w2.z + xv.w * w3.z;
            acc[i][3] += xv.x * w0.w + xv.y * w1.w + xv.z * w2.w + xv.w * w3.w;
        }
    }

    #pragma unroll
    for (int i = 0; i < 16; i++) {
        int gr = row0 + w + 8 * i;
        if (gr < n_rows)
            ((float4*)(Y + (size_t)gr * DIM))[lane] =
                make_float4(acc[i][0], acc[i][1], acc[i][2], acc[i][3]);
    }
#endif
}

// ---------------------------------------------------------------------------
// One warp per edge: gather 512B row H[src]; one red.v4 per lane into out[dst].
__global__ void __launch_bounds__(256) scatter_kernel(
    const float* __restrict__ H, const int* __restrict__ src,
    const int* __restrict__ dst, float* __restrict__ out, int nE)
{
    int e    = (blockIdx.x * 256 + threadIdx.x) >> 5;
    int lane = threadIdx.x & 31;
    if (e >= nE) return;

    int s = __ldg(src + e);
    int d = __ldg(dst + e);

    float4 v = ((const float4*)(H + (size_t)s * DIM))[lane];
    float* op = out + (size_t)d * DIM + lane * 4;
    asm volatile("red.global.add.v4.f32 [%0], {%1, %2, %3, %4};"
                 :: "l"(op), "f"(v.x), "f"(v.y), "f"(v.z), "f"(v.w)
                 : "memory");

    if (lane == 0)
        asm volatile("red.global.add.f32 [%0], %1;"
                     :: "l"(&g_deg[d]), "f"(1.0f) : "memory");
}

// ---------------------------------------------------------------------------
__global__ void __launch_bounds__(256) finalize_kernel(
    float* __restrict__ out, const float* __restrict__ bias)
{
    int i = blockIdx.x * 256 + threadIdx.x;
    if (i >= NP * 32) return;
    int row = i >> 5;
    int c4  = i & 31;

    float inv = 1.0f / (g_deg[row] + 1.0f);
    float4 v = ((float4*)out)[i];
    float4 b = ((const float4*)bias)[c4];
    v.x = fmaxf(fmaf(v.x, inv, b.x), 0.f);
    v.y = fmaxf(fmaf(v.y, inv, b.y), 0.f);
    v.z = fmaxf(fmaf(v.z, inv, b.z), 0.f);
    v.w = fmaxf(fmaf(v.w, inv, b.w), 0.f);
    ((float4*)out)[i] = v;
}

// ---------------------------------------------------------------------------
extern "C" void kernel_launch(void* const* d_in, const int* in_sizes, int n_in,
                              void* d_out, int out_size)
{
    const float* x_paper    = (const float*)d_in[0];
    const float* x_author   = (const float*)d_in[1];
    const float* W_cites    = (const float*)d_in[2];
    const float* W_writes   = (const float*)d_in[3];
    const float* W_self     = (const float*)d_in[4];
    const float* bias       = (const float*)d_in[5];
    const int*   cites_src  = (const int*)d_in[6];
    const int*   cites_dst  = (const int*)d_in[7];
    const int*   writes_src = (const int*)d_in[8];
    const int*   writes_dst = (const int*)d_in[9];
    float*       out        = (float*)d_out;

    cudaFuncSetAttribute(gemm_kernel,
                         cudaFuncAttributeMaxDynamicSharedMemorySize, SM_TOTAL);

    void *pHc = nullptr, *pHw = nullptr, *pWT = nullptr;
    cudaGetSymbolAddress(&pHc, g_Hc);
    cudaGetSymbolAddress(&pHw, g_Hw);
    cudaGetSymbolAddress(&pWT, g_WT);
    __nv_bfloat16* WT = (__nv_bfloat16*)pWT;
    const int WSZ = DIM * DIM;
    __nv_bfloat16 *Wc_h = WT + 0 * WSZ, *Wc_l = WT + 1 * WSZ;
    __nv_bfloat16 *Ww_h = WT + 2 * WSZ, *Ww_l = WT + 3 * WSZ;
    __nv_bfloat16 *Ws_h = WT + 4 * WSZ, *Ws_l = WT + 5 * WSZ;

    // 1. degree accumulator -> 0; all W -> swizzled bf16 hi/lo images (parallel)
    zero_deg_kernel<<<(NP + 255) / 256, 256>>>();
    wconv_kernel<<<(3 * DIM * DIM + 255) / 256, 256>>>(W_cites, W_writes, W_self);

    // 2. GEMMs (self-transform writes d_out = accumulator init)
    gemm_kernel<<<(NP + 127) / 128, 256, SM_TOTAL>>>(x_paper,  W_self,   Ws_h, Ws_l, out,         NP);
    gemm_kernel<<<(NP + 127) / 128, 256, SM_TOTAL>>>(x_paper,  W_cites,  Wc_h, Wc_l, (float*)pHc, NP);
    gemm_kernel<<<(NA + 127) / 128, 256, SM_TOTAL>>>(x_author, W_writes, Ww_h, Ww_l, (float*)pHw, NA);

    // 3. edge scatter (vectorized L2 atomics) + fused degree counting
    scatter_kernel<<<EE / 8, 256>>>((const float*)pHc, cites_src,  cites_dst,  out, EE);
    scatter_kernel<<<EE / 8, 256>>>((const float*)pHw, writes_src, writes_dst, out, EE);

    // 4. mean + bias + relu
    finalize_kernel<<<(NP * 32 + 255) / 256, 256>>>(out, bias);
}

// round 6
// speedup vs baseline: 1.6494x; 1.1613x over previous
#include <cuda_runtime.h>
#include <cuda_bf16.h>
#include <cstdint>

#define NP 100000
#define NA 50000
#define DIM 128
#define EE  500000

#if defined(__CUDA_ARCH__) && defined(__CUDA_ARCH_FEAT_SM103_ALL)
#define USE_TC 1
#else
#define USE_TC 0
#endif

// ---------------------------------------------------------------------------
// Scratch (allocation-guard-safe __device__ globals)
__device__ float g_Hc[(size_t)NP * DIM];          // x_paper  @ W_cites
__device__ float g_Hw[(size_t)NA * DIM];          // x_author @ W_writes
__device__ float g_deg[NP];                       // deg_c + deg_w
// Pre-swizzled bf16 operand images of W^T: [matrix][hi|lo][128*128]
__device__ __nv_bfloat16 g_WT[3][2][DIM * DIM];

// ---------------------------------------------------------------------------
// Swizzled byte offset of element (r,k) in a 128x128 bf16 K-major blocked-atom
// tile: atom = 8 rows x 64 bf16 (1024B), 16 atom-rows x 2 atom-cols.
__device__ __forceinline__ uint32_t bf16_off(int r, int k) {
    uint32_t b = (uint32_t)(((r >> 3) + (k >> 6) * 16) * 1024
                            + (r & 7) * 128 + (k & 63) * 2);
    return b ^ ((b >> 3) & 0x70);
}

#if USE_TC
// ---------------------------------------------------------------------------
// PTX helpers (sm_103a tcgen05, cg1) — only on the 'a' target.
__device__ __forceinline__ uint32_t s2u(const void* p) {
    uint32_t a;
    asm("{ .reg .u64 t; cvta.to.shared.u64 t, %1; cvt.u32.u64 %0, t; }"
        : "=r"(a) : "l"(p));
    return a;
}
__device__ __forceinline__ bool elect1() {
    uint32_t p;
    asm volatile("{ .reg .pred p; elect.sync _|p, 0xFFFFFFFF; selp.b32 %0,1,0,p; }"
                 : "=r"(p));
    return p != 0;
}
// TS form: A in TMEM, B in SMEM
__device__ __forceinline__ void mma_bf16_ts(uint32_t d, uint32_t a, uint64_t b,
                                            uint32_t idesc, uint32_t en) {
    asm volatile(
        "{\n\t.reg .pred p;\n\tsetp.ne.u32 p, %4, 0;\n\t"
        "tcgen05.mma.cta_group::1.kind::f16 [%0], [%1], %2, %3, {%5,%5,%5,%5}, p;\n\t}"
        :: "r"(d), "r"(a), "l"(b), "r"(idesc), "r"(en), "r"(0u) : "memory");
}
#define TC_ALLOC(sa, n)  asm volatile("tcgen05.alloc.cta_group::1.sync.aligned.shared::cta.b32 [%0], %1;" :: "r"(sa), "r"(n) : "memory")
#define TC_DEALLOC(t, n) asm volatile("tcgen05.dealloc.cta_group::1.sync.aligned.b32 %0, %1;" :: "r"(t), "r"(n))
#define TC_RELINQ()      asm volatile("tcgen05.relinquish_alloc_permit.cta_group::1.sync.aligned;")
#define TC_COMMIT(mb)    asm volatile("tcgen05.commit.cta_group::1.mbarrier::arrive::one.shared::cluster.b64 [%0];" :: "r"(mb) : "memory")
#define TC_WAIT_LD()     asm volatile("tcgen05.wait::ld.sync.aligned;" ::: "memory")
#define TC_WAIT_ST()     asm volatile("tcgen05.wait::st.sync.aligned;" ::: "memory")
#define TC_FENCE_BEFORE() asm volatile("tcgen05.fence::before_thread_sync;" ::: "memory")
#define TC_FENCE_AFTER()  asm volatile("tcgen05.fence::after_thread_sync;" ::: "memory")
#define MBAR_INIT(mb, c) asm volatile("mbarrier.init.shared.b64 [%0], %1;" :: "r"(mb), "r"(c) : "memory")
#define MBAR_INVAL(mb)   asm volatile("mbarrier.inval.shared.b64 [%0];" :: "r"(mb) : "memory")
#define MBAR_WAIT(mb, ph) do {                                                      \
    uint32_t _m = (mb), _p = (ph), _d;                                              \
    asm volatile("{ .reg .pred p; mbarrier.try_wait.parity.acquire.cta.shared::cta.b64 p, [%1], %2; selp.b32 %0,1,0,p; }" \
                 : "=r"(_d) : "r"(_m), "r"(_p) : "memory");                         \
    if (!_d) {                                                                      \
        asm volatile("{ .reg .pred P1; WL_%=: mbarrier.try_wait.parity.acquire.cta.shared::cta.b64 P1, [%0], %1, 0x989680; @P1 bra.uni WD_%=; bra.uni WL_%=; WD_%=: }" \
                     :: "r"(_m), "r"(_p) : "memory");                               \
    }                                                                               \
} while (0)
#define LDTM_X32(r, a)                                                              \
    asm volatile("tcgen05.ld.sync.aligned.32x32b.x32.b32 "                          \
        "{%0,%1,%2,%3,%4,%5,%6,%7,%8,%9,%10,%11,%12,%13,%14,%15,"                   \
        "%16,%17,%18,%19,%20,%21,%22,%23,%24,%25,%26,%27,%28,%29,%30,%31}, [%32];"  \
        : "=r"((r)[0]),"=r"((r)[1]),"=r"((r)[2]),"=r"((r)[3]),                      \
          "=r"((r)[4]),"=r"((r)[5]),"=r"((r)[6]),"=r"((r)[7]),                      \
          "=r"((r)[8]),"=r"((r)[9]),"=r"((r)[10]),"=r"((r)[11]),                    \
          "=r"((r)[12]),"=r"((r)[13]),"=r"((r)[14]),"=r"((r)[15]),                  \
          "=r"((r)[16]),"=r"((r)[17]),"=r"((r)[18]),"=r"((r)[19]),                  \
          "=r"((r)[20]),"=r"((r)[21]),"=r"((r)[22]),"=r"((r)[23]),                  \
          "=r"((r)[24]),"=r"((r)[25]),"=r"((r)[26]),"=r"((r)[27]),                  \
          "=r"((r)[28]),"=r"((r)[29]),"=r"((r)[30]),"=r"((r)[31])                   \
        : "r"(a))
#define STTM_X16(a, r)                                                              \
    asm volatile("tcgen05.st.sync.aligned.32x32b.x16.b32 [%0], "                    \
        "{%1,%2,%3,%4,%5,%6,%7,%8,%9,%10,%11,%12,%13,%14,%15,%16};"                 \
        :: "r"(a),                                                                  \
           "r"((r)[0]),"r"((r)[1]),"r"((r)[2]),"r"((r)[3]),                         \
           "r"((r)[4]),"r"((r)[5]),"r"((r)[6]),"r"((r)[7]),                         \
           "r"((r)[8]),"r"((r)[9]),"r"((r)[10]),"r"((r)[11]),                       \
           "r"((r)[12]),"r"((r)[13]),"r"((r)[14]),"r"((r)[15])                      \
        : "memory")

// SMEM descriptor: SW128, version=1(Blackwell), LBO=1, SBO=64 (K-major)
static __device__ __forceinline__ uint64_t smem_desc(uint32_t addr) {
    const uint64_t base = (uint64_t(2) << 61) | (uint64_t(1) << 46)
                        | (uint64_t(64) << 32) | (uint64_t(1) << 16);
    return base | ((uint64_t)(addr >> 4) & 0x3FFF);
}

// Convert this thread's X row quarter-by-quarter into bf16 (hi or lo) and
// STTM into TMEM at abase. gr >= n_rows -> zeros.
__device__ __forceinline__ void store_a_row(
    const float* __restrict__ X, int gr, int n_rows, int hi_path,
    uint32_t abase)
{
    const float4* xr = (const float4*)(X + (size_t)gr * DIM);
    #pragma unroll
    for (int q = 0; q < 4; q++) {
        float4 vv[8];
        #pragma unroll
        for (int j = 0; j < 8; j++)
            vv[j] = (gr < n_rows) ? xr[q * 8 + j]
                                  : make_float4(0.f, 0.f, 0.f, 0.f);
        uint32_t rr[16];
        #pragma unroll
        for (int j = 0; j < 8; j++) {
            float a0 = vv[j].x, a1 = vv[j].y, a2 = vv[j].z, a3 = vv[j].w;
            __nv_bfloat16 h0 = __float2bfloat16(a0);
            __nv_bfloat16 h1 = __float2bfloat16(a1);
            __nv_bfloat16 h2 = __float2bfloat16(a2);
            __nv_bfloat16 h3 = __float2bfloat16(a3);
            __nv_bfloat16 o0 = h0, o1 = h1, o2 = h2, o3 = h3;
            if (!hi_path) {
                o0 = __float2bfloat16(a0 - __bfloat162float(h0));
                o1 = __float2bfloat16(a1 - __bfloat162float(h1));
                o2 = __float2bfloat16(a2 - __bfloat162float(h2));
                o3 = __float2bfloat16(a3 - __bfloat162float(h3));
            }
            __nv_bfloat162 p01 = __halves2bfloat162(o0, o1);
            __nv_bfloat162 p23 = __halves2bfloat162(o2, o3);
            rr[2 * j]     = *(uint32_t*)&p01;
            rr[2 * j + 1] = *(uint32_t*)&p23;
        }
        STTM_X16(abase + q * 16, rr);
    }
    TC_WAIT_ST();
}

// Issue the 3-pass bf16-split MMA chain for one (Bhi,Blo) pair into D.
__device__ __forceinline__ void issue_3pass(
    uint32_t d, uint32_t aHi, uint32_t aLo, uint64_t dBh, uint64_t dBl,
    uint32_t idesc)
{
    const int koff[8] = {0, 2, 4, 6, 1024, 1026, 1028, 1030};
    uint32_t aA[3] = {aHi, aHi, aLo};
    uint64_t pb[3] = {dBh, dBl, dBh};
    uint32_t en = 0;
    for (int p = 0; p < 3; p++)
        for (int ks = 0; ks < 8; ks++) {
            mma_bf16_ts(d, aA[p] + ks * 8, pb[p] + koff[ks], idesc, en);
            en = 1;
        }
}
#endif // USE_TC

// ---------------------------------------------------------------------------
__global__ void __launch_bounds__(256) zero_deg_kernel() {
    int i = blockIdx.x * 256 + threadIdx.x;
    if (i < NP) g_deg[i] = 0.0f;
}

// ---------------------------------------------------------------------------
// All three W matrices -> swizzled bf16 hi/lo W^T images, fully parallel.
__global__ void __launch_bounds__(256) wconv_kernel(
    const float* __restrict__ W0, const float* __restrict__ W1,
    const float* __restrict__ W2)
{
    int i = blockIdx.x * 256 + threadIdx.x;            // 0 .. 3*16384-1
    if (i >= 3 * DIM * DIM) return;
    int m = i >> 14, e = i & (DIM * DIM - 1);
    const float* W = (m == 0) ? W0 : (m == 1) ? W1 : W2;
    int k = e >> 7, n = e & 127;
    float x = W[e];                                     // W[k][n]
    __nv_bfloat16 h = __float2bfloat16(x);
    __nv_bfloat16 l = __float2bfloat16(x - __bfloat162float(h));
    uint32_t o = bf16_off(n, k) >> 1;
    g_WT[m][0][o] = h;
    g_WT[m][1][o] = l;
}

// ---------------------------------------------------------------------------
// idesc kind::f16: dtype=F32, atype=BF16, btype=BF16, (N/8)<<17, (M/16)<<24
#define IDESC_BF16_128 0x8200490u

// ===== DUAL GEMM: Y1 = X@W1, Y2 = X@W2 (shared A, one pass over X) =========
// TMEM: D1 0..127, D2 128..255, A_hi 256..319, A_lo 320..383 (alloc 512).
// SMEM: 4 pre-swizzled B images (self/cites hi/lo), 128KB.
#define D_TMEM 0
#define D_MBAR 8
#define D_B1H  1024
#define D_B1L  (D_B1H + 32768)
#define D_B2H  (D_B1L + 32768)
#define D_B2L  (D_B2H + 32768)
#define D_TOTAL (D_B2L + 32768)     // 132096

#define TM2_D1  0
#define TM2_D2  128
#define TM2_AHI 256
#define TM2_ALO 320

__global__ void __launch_bounds__(256, 1) gemm2_kernel(
    const float* __restrict__ X,
    const float* __restrict__ Wf1, const float* __restrict__ Wf2,
    const __nv_bfloat16* __restrict__ B1h, const __nv_bfloat16* __restrict__ B1l,
    const __nv_bfloat16* __restrict__ B2h, const __nv_bfloat16* __restrict__ B2l,
    float* __restrict__ Y1, float* __restrict__ Y2, int n_rows)
{
    extern __shared__ char smem[];
    const int tid = threadIdx.x, w = tid >> 5, lane = tid & 31;
    const int row0 = blockIdx.x * 128;

#if USE_TC
    uint32_t sb = s2u(smem);

    if (w == 0) TC_ALLOC(sb + D_TMEM, 512);
    if (tid == 0) MBAR_INIT(sb + D_MBAR, 1);
    __syncthreads();

    uint32_t tmem;
    asm volatile("ld.shared.b32 %0, [%1];" : "=r"(tmem) : "r"(sb + D_TMEM));

    // Stage 4 B images (pre-swizzled): straight float4 copies
    for (int i = tid; i < 2048; i += 256) {
        ((float4*)(smem + D_B1H))[i] = ((const float4*)B1h)[i];
        ((float4*)(smem + D_B1L))[i] = ((const float4*)B1l)[i];
        ((float4*)(smem + D_B2H))[i] = ((const float4*)B2h)[i];
        ((float4*)(smem + D_B2L))[i] = ((const float4*)B2l)[i];
    }

    // A -> TMEM: wg0 stores A_hi, wg1 stores A_lo
    {
        int wg_tid = tid & 127;
        int hi_path = (tid < 128);
        uint32_t warp_off = (uint32_t)(wg_tid >> 5) << 21;
        uint32_t abase = tmem + (hi_path ? TM2_AHI : TM2_ALO) + warp_off;
        store_a_row(X, row0 + wg_tid, n_rows, hi_path, abase);
    }

    TC_FENCE_BEFORE();
    asm volatile("fence.proxy.async.shared::cta;" ::: "memory");
    __syncthreads();

    if (w == 0 && elect1()) {
        TC_FENCE_AFTER();
        issue_3pass(tmem + TM2_D1, tmem + TM2_AHI, tmem + TM2_ALO,
                    smem_desc(sb + D_B1H), smem_desc(sb + D_B1L), IDESC_BF16_128);
        issue_3pass(tmem + TM2_D2, tmem + TM2_AHI, tmem + TM2_ALO,
                    smem_desc(sb + D_B2H), smem_desc(sb + D_B2L), IDESC_BF16_128);
        TC_COMMIT(sb + D_MBAR);
    }

    __syncthreads();
    MBAR_WAIT(sb + D_MBAR, 0);
    TC_FENCE_AFTER();

    // Epilogue: warp w covers cols c0..c0+63; rows (w&3)*32+lane.
    {
        uint32_t c0 = (uint32_t)(w >> 2) * 64;
        int gr = row0 + (w & 3) * 32 + lane;
        uint32_t d[64];

        LDTM_X32(d, tmem + TM2_D1 + c0);
        LDTM_X32(d + 32, tmem + TM2_D1 + c0 + 32);
        TC_WAIT_LD();
        if (gr < n_rows) {
            float4* yp = (float4*)(Y1 + (size_t)gr * DIM + c0);
            #pragma unroll
            for (int j = 0; j < 16; j++)
                yp[j] = make_float4(__uint_as_float(d[4 * j + 0]),
                                    __uint_as_float(d[4 * j + 1]),
                                    __uint_as_float(d[4 * j + 2]),
                                    __uint_as_float(d[4 * j + 3]));
        }

        LDTM_X32(d, tmem + TM2_D2 + c0);
        LDTM_X32(d + 32, tmem + TM2_D2 + c0 + 32);
        TC_WAIT_LD();
        if (gr < n_rows) {
            float4* yp = (float4*)(Y2 + (size_t)gr * DIM + c0);
            #pragma unroll
            for (int j = 0; j < 16; j++)
                yp[j] = make_float4(__uint_as_float(d[4 * j + 0]),
                                    __uint_as_float(d[4 * j + 1]),
                                    __uint_as_float(d[4 * j + 2]),
                                    __uint_as_float(d[4 * j + 3]));
        }
    }

    __syncthreads();
    if (tid == 0) MBAR_INVAL(sb + D_MBAR);
    __syncthreads();
    if (w == 0) {
        TC_RELINQ();
        TC_DEALLOC(tmem, 512);
    }
#else
    // -------- SIMT fallback (never runs on GB300) --------
    float4* Ws4 = (float4*)smem;
    for (int m = 0; m < 2; m++) {
        const float* Wf = m ? Wf2 : Wf1;
        float* Y = m ? Y2 : Y1;
        for (int i = tid; i < DIM * 32; i += 256)
            Ws4[i] = ((const float4*)Wf)[i];
        __syncthreads();
        float acc[16][4];
        #pragma unroll
        for (int i = 0; i < 16; i++)
            acc[i][0] = acc[i][1] = acc[i][2] = acc[i][3] = 0.f;
        for (int k4 = 0; k4 < 32; k4++) {
            float4 w0 = Ws4[(k4 * 4 + 0) * 32 + lane];
            float4 w1 = Ws4[(k4 * 4 + 1) * 32 + lane];
            float4 w2 = Ws4[(k4 * 4 + 2) * 32 + lane];
            float4 w3 = Ws4[(k4 * 4 + 3) * 32 + lane];
            for (int i = 0; i < 16; i++) {
                int gr = row0 + w + 8 * i;
                float4 xv = (gr < n_rows)
                    ? __ldg((const float4*)(X + (size_t)gr * DIM) + k4)
                    : make_float4(0.f, 0.f, 0.f, 0.f);
                acc[i][0] += xv.x * w0.x + xv.y * w1.x + xv.z * w2.x + xv.w * w3.x;
                acc[i][1] += xv.x * w0.y + xv.y * w1.y + xv.z * w2.y + xv.w * w3.y;
                acc[i][2] += xv.x * w0.z + xv.y * w1.z + xv.z * w2.z + xv.w * w3.z;
                acc[i][3] += xv.x * w0.w + xv.y * w1.w + xv.z * w2.w + xv.w * w3.w;
            }
        }
        #pragma unroll
        for (int i = 0; i < 16; i++) {
            int gr = row0 + w + 8 * i;
            if (gr < n_rows)
                ((float4*)(Y + (size_t)gr * DIM))[lane] =
                    make_float4(acc[i][0], acc[i][1], acc[i][2], acc[i][3]);
        }
        __syncthreads();
    }
#endif
}

// ===== SINGLE GEMM (author) =================================================
#define S_TMEM 0
#define S_MBAR 8
#define S_BHI  1024
#define S_BLO  (S_BHI + 32768)
#define S_TOTAL (S_BLO + 32768)     // 66560

#define TM1_D   0
#define TM1_AHI 128
#define TM1_ALO 192

__global__ void __launch_bounds__(256, 2) gemm1_kernel(
    const float* __restrict__ X, const float* __restrict__ Wf,
    const __nv_bfloat16* __restrict__ Bhi, const __nv_bfloat16* __restrict__ Blo,
    float* __restrict__ Y, int n_rows)
{
    extern __shared__ char smem[];
    const int tid = threadIdx.x, w = tid >> 5, lane = tid & 31;
    const int row0 = blockIdx.x * 128;

#if USE_TC
    uint32_t sb = s2u(smem);

    if (w == 0) TC_ALLOC(sb + S_TMEM, 256);
    if (tid == 0) MBAR_INIT(sb + S_MBAR, 1);
    __syncthreads();

    uint32_t tmem;
    asm volatile("ld.shared.b32 %0, [%1];" : "=r"(tmem) : "r"(sb + S_TMEM));

    for (int i = tid; i < 2048; i += 256) {
        ((float4*)(smem + S_BHI))[i] = ((const float4*)Bhi)[i];
        ((float4*)(smem + S_BLO))[i] = ((const float4*)Blo)[i];
    }

    {
        int wg_tid = tid & 127;
        int hi_path = (tid < 128);
        uint32_t warp_off = (uint32_t)(wg_tid >> 5) << 21;
        uint32_t abase = tmem + (hi_path ? TM1_AHI : TM1_ALO) + warp_off;
        store_a_row(X, row0 + wg_tid, n_rows, hi_path, abase);
    }

    TC_FENCE_BEFORE();
    asm volatile("fence.proxy.async.shared::cta;" ::: "memory");
    __syncthreads();

    if (w == 0 && elect1()) {
        TC_FENCE_AFTER();
        issue_3pass(tmem + TM1_D, tmem + TM1_AHI, tmem + TM1_ALO,
                    smem_desc(sb + S_BHI), smem_desc(sb + S_BLO), IDESC_BF16_128);
        TC_COMMIT(sb + S_MBAR);
    }

    __syncthreads();
    MBAR_WAIT(sb + S_MBAR, 0);
    TC_FENCE_AFTER();

    {
        uint32_t d[64];
        uint32_t c0 = (uint32_t)(w >> 2) * 64;
        LDTM_X32(d, tmem + TM1_D + c0);
        LDTM_X32(d + 32, tmem + TM1_D + c0 + 32);
        TC_WAIT_LD();
        int gr = row0 + (w & 3) * 32 + lane;
        if (gr < n_rows) {
            float4* yp = (float4*)(Y + (size_t)gr * DIM + c0);
            #pragma unroll
            for (int j = 0; j < 16; j++)
                yp[j] = make_float4(__uint_as_float(d[4 * j + 0]),
                                    __uint_as_float(d[4 * j + 1]),
                                    __uint_as_float(d[4 * j + 2]),
                                    __uint_as_float(d[4 * j + 3]));
        }
    }

    __syncthreads();
    if (tid == 0) MBAR_INVAL(sb + S_MBAR);
    __syncthreads();
    if (w == 0) {
        TC_RELINQ();
        TC_DEALLOC(tmem, 256);
    }
#else
    float4* Ws4 = (float4*)smem;
    for (int i = tid; i < DIM * 32; i += 256)
        Ws4[i] = ((const float4*)Wf)[i];
    __syncthreads();
    float acc[16][4];
    #pragma unroll
    for (int i = 0; i < 16; i++)
        acc[i][0] = acc[i][1] = acc[i][2] = acc[i][3] = 0.f;
    for (int k4 = 0; k4 < 32; k4++) {
        float4 w0 = Ws4[(k4 * 4 + 0) * 32 + lane];
        float4 w1 = Ws4[(k4 * 4 + 1) * 32 + lane];
        float4 w2 = Ws4[(k4 * 4 + 2) * 32 + lane];
        float4 w3 = Ws4[(k4 * 4 + 3) * 32 + lane];
        for (int i = 0; i < 16; i++) {
            int gr = row0 + w + 8 * i;
            float4 xv = (gr < n_rows)
                ? __ldg((const float4*)(X + (size_t)gr * DIM) + k4)
                : make_float4(0.f, 0.f, 0.f, 0.f);
            acc[i][0] += xv.x * w0.x + xv.y * w1.x + xv.z * w2.x + xv.w * w3.x;
            acc[i][1] += xv.x * w0.y + xv.y * w1.y + xv.z * w2.y + xv.w * w3.y;
            acc[i][2] += xv.x * w0.z + xv.y * w1.z + xv.z * w2.z + xv.w * w3.z;
            acc[i][3] += xv.x * w0.w + xv.y * w1.w + xv.z * w2.w + xv.w * w3.w;
        }
    }
    #pragma unroll
    for (int i = 0; i < 16; i++) {
        int gr = row0 + w + 8 * i;
        if (gr < n_rows)
            ((float4*)(Y + (size_t)gr * DIM))[lane] =
                make_float4(acc[i][0], acc[i][1], acc[i][2], acc[i][3]);
    }
#endif
}

// ---------------------------------------------------------------------------
// Combined edge scatter: block b < EE/8 handles cites edges, else writes.
// One warp per edge: gather 512B row H[src]; one red.v4 per lane into out[dst].
__global__ void __launch_bounds__(256) scatter_all_kernel(
    const float* __restrict__ Hc, const float* __restrict__ Hw,
    const int* __restrict__ c_src, const int* __restrict__ c_dst,
    const int* __restrict__ w_src, const int* __restrict__ w_dst,
    float* __restrict__ out)
{
    int g    = blockIdx.x * 256 + threadIdx.x;
    int e    = g >> 5;
    int lane = threadIdx.x & 31;

    const float* H;
    int s, d;
    if (e < EE) {
        H = Hc; s = __ldg(c_src + e);      d = __ldg(c_dst + e);
    } else {
        H = Hw; s = __ldg(w_src + e - EE); d = __ldg(w_dst + e - EE);
    }

    float4 v = ((const float4*)(H + (size_t)s * DIM))[lane];
    float* op = out + (size_t)d * DIM + lane * 4;
    asm volatile("red.global.add.v4.f32 [%0], {%1, %2, %3, %4};"
                 :: "l"(op), "f"(v.x), "f"(v.y), "f"(v.z), "f"(v.w)
                 : "memory");

    if (lane == 0)
        asm volatile("red.global.add.f32 [%0], %1;"
                     :: "l"(&g_deg[d]), "f"(1.0f) : "memory");
}

// ---------------------------------------------------------------------------
__global__ void __launch_bounds__(256) finalize_kernel(
    float* __restrict__ out, const float* __restrict__ bias)
{
    int i = blockIdx.x * 256 + threadIdx.x;
    if (i >= NP * 32) return;
    int row = i >> 5;
    int c4  = i & 31;

    float inv = 1.0f / (g_deg[row] + 1.0f);
    float4 v = ((float4*)out)[i];
    float4 b = ((const float4*)bias)[c4];
    v.x = fmaxf(fmaf(v.x, inv, b.x), 0.f);
    v.y = fmaxf(fmaf(v.y, inv, b.y), 0.f);
    v.z = fmaxf(fmaf(v.z, inv, b.z), 0.f);
    v.w = fmaxf(fmaf(v.w, inv, b.w), 0.f);
    ((float4*)out)[i] = v;
}

// ---------------------------------------------------------------------------
extern "C" void kernel_launch(void* const* d_in, const int* in_sizes, int n_in,
                              void* d_out, int out_size)
{
    const float* x_paper    = (const float*)d_in[0];
    const float* x_author   = (const float*)d_in[1];
    const float* W_cites    = (const float*)d_in[2];
    const float* W_writes   = (const float*)d_in[3];
    const float* W_self     = (const float*)d_in[4];
    const float* bias       = (const float*)d_in[5];
    const int*   cites_src  = (const int*)d_in[6];
    const int*   cites_dst  = (const int*)d_in[7];
    const int*   writes_src = (const int*)d_in[8];
    const int*   writes_dst = (const int*)d_in[9];
    float*       out        = (float*)d_out;

    cudaFuncSetAttribute(gemm2_kernel,
                         cudaFuncAttributeMaxDynamicSharedMemorySize, D_TOTAL);
    cudaFuncSetAttribute(gemm1_kernel,
                         cudaFuncAttributeMaxDynamicSharedMemorySize, S_TOTAL);

    void *pHc = nullptr, *pHw = nullptr, *pWT = nullptr;
    cudaGetSymbolAddress(&pHc, g_Hc);
    cudaGetSymbolAddress(&pHw, g_Hw);
    cudaGetSymbolAddress(&pWT, g_WT);
    __nv_bfloat16* WT = (__nv_bfloat16*)pWT;
    const int WSZ = DIM * DIM;
    __nv_bfloat16 *Wc_h = WT + 0 * WSZ, *Wc_l = WT + 1 * WSZ;
    __nv_bfloat16 *Ww_h = WT + 2 * WSZ, *Ww_l = WT + 3 * WSZ;
    __nv_bfloat16 *Ws_h = WT + 4 * WSZ, *Ws_l = WT + 5 * WSZ;

    // 1. degree accumulator -> 0; all W -> swizzled bf16 hi/lo images
    zero_deg_kernel<<<(NP + 255) / 256, 256>>>();
    wconv_kernel<<<(3 * DIM * DIM + 255) / 256, 256>>>(W_cites, W_writes, W_self);

    // 2. GEMMs: dual paper GEMM (self->out = accumulator init, cites->g_Hc),
    //    single author GEMM (writes->g_Hw)
    gemm2_kernel<<<(NP + 127) / 128, 256, D_TOTAL>>>(
        x_paper, W_self, W_cites, Ws_h, Ws_l, Wc_h, Wc_l,
        out, (float*)pHc, NP);
    gemm1_kernel<<<(NA + 127) / 128, 256, S_TOTAL>>>(
        x_author, W_writes, Ww_h, Ww_l, (float*)pHw, NA);

    // 3. combined edge scatter (vectorized L2 atomics) + degree counting
    scatter_all_kernel<<<2 * EE / 8, 256>>>(
        (const float*)pHc, (const float*)pHw,
        cites_src, cites_dst, writes_src, writes_dst, out);

    // 4. mean + bias + relu
    finalize_kernel<<<(NP * 32 + 255) / 256, 256>>>(out, bias);
}

// round 7
// speedup vs baseline: 1.9097x; 1.1578x over previous
#include <cuda_runtime.h>
#include <cuda_bf16.h>
#include <cstdint>

#define NP 100000
#define NA 50000
#define DIM 128
#define EE  500000

#define NT_P 782            // ceil(NP/128) paper tiles
#define NT_A 391            // ceil(NA/128) author tiles
#define NT   (NT_P + NT_A)  // 1173
#define GRID_PERS 152       // GB300 SM count

#if defined(__CUDA_ARCH__) && defined(__CUDA_ARCH_FEAT_SM103_ALL)
#define USE_TC 1
#else
#define USE_TC 0
#endif

// ---------------------------------------------------------------------------
// Scratch (allocation-guard-safe __device__ globals)
__device__ float g_Hc[(size_t)NP * DIM];          // x_paper  @ W_cites
__device__ float g_Hw[(size_t)NA * DIM];          // x_author @ W_writes
__device__ float g_deg[NP];                       // deg_c + deg_w
// Pre-swizzled bf16 operand images of W^T: [cites|writes|self][hi|lo][16384]
__device__ __nv_bfloat16 g_WT[3][2][DIM * DIM];

// ---------------------------------------------------------------------------
// Swizzled byte offset of element (r,k) in a 128x128 bf16 K-major blocked-atom
// tile: atom = 8 rows x 64 bf16 (1024B), 16 atom-rows x 2 atom-cols.
__device__ __forceinline__ uint32_t bf16_off(int r, int k) {
    uint32_t b = (uint32_t)(((r >> 3) + (k >> 6) * 16) * 1024
                            + (r & 7) * 128 + (k & 63) * 2);
    return b ^ ((b >> 3) & 0x70);
}

#if USE_TC
// ---------------------------------------------------------------------------
// PTX helpers (sm_103a tcgen05, cg1) — only on the 'a' target.
__device__ __forceinline__ uint32_t s2u(const void* p) {
    uint32_t a;
    asm("{ .reg .u64 t; cvta.to.shared.u64 t, %1; cvt.u32.u64 %0, t; }"
        : "=r"(a) : "l"(p));
    return a;
}
__device__ __forceinline__ bool elect1() {
    uint32_t p;
    asm volatile("{ .reg .pred p; elect.sync _|p, 0xFFFFFFFF; selp.b32 %0,1,0,p; }"
                 : "=r"(p));
    return p != 0;
}
// TS form: A in TMEM, B in SMEM
__device__ __forceinline__ void mma_bf16_ts(uint32_t d, uint32_t a, uint64_t b,
                                            uint32_t idesc, uint32_t en) {
    asm volatile(
        "{\n\t.reg .pred p;\n\tsetp.ne.u32 p, %4, 0;\n\t"
        "tcgen05.mma.cta_group::1.kind::f16 [%0], [%1], %2, %3, {%5,%5,%5,%5}, p;\n\t}"
        :: "r"(d), "r"(a), "l"(b), "r"(idesc), "r"(en), "r"(0u) : "memory");
}
#define TC_ALLOC(sa, n)  asm volatile("tcgen05.alloc.cta_group::1.sync.aligned.shared::cta.b32 [%0], %1;" :: "r"(sa), "r"(n) : "memory")
#define TC_DEALLOC(t, n) asm volatile("tcgen05.dealloc.cta_group::1.sync.aligned.b32 %0, %1;" :: "r"(t), "r"(n))
#define TC_RELINQ()      asm volatile("tcgen05.relinquish_alloc_permit.cta_group::1.sync.aligned;")
#define TC_COMMIT(mb)    asm volatile("tcgen05.commit.cta_group::1.mbarrier::arrive::one.shared::cluster.b64 [%0];" :: "r"(mb) : "memory")
#define TC_WAIT_LD()     asm volatile("tcgen05.wait::ld.sync.aligned;" ::: "memory")
#define TC_WAIT_ST()     asm volatile("tcgen05.wait::st.sync.aligned;" ::: "memory")
#define TC_FENCE_BEFORE() asm volatile("tcgen05.fence::before_thread_sync;" ::: "memory")
#define TC_FENCE_AFTER()  asm volatile("tcgen05.fence::after_thread_sync;" ::: "memory")
#define MBAR_INIT(mb, c) asm volatile("mbarrier.init.shared.b64 [%0], %1;" :: "r"(mb), "r"(c) : "memory")
#define MBAR_INVAL(mb)   asm volatile("mbarrier.inval.shared.b64 [%0];" :: "r"(mb) : "memory")
#define MBAR_WAIT(mb, ph) do {                                                      \
    uint32_t _m = (mb), _p = (ph), _d;                                              \
    asm volatile("{ .reg .pred p; mbarrier.try_wait.parity.acquire.cta.shared::cta.b64 p, [%1], %2; selp.b32 %0,1,0,p; }" \
                 : "=r"(_d) : "r"(_m), "r"(_p) : "memory");                         \
    if (!_d) {                                                                      \
        asm volatile("{ .reg .pred P1; WL_%=: mbarrier.try_wait.parity.acquire.cta.shared::cta.b64 P1, [%0], %1, 0x989680; @P1 bra.uni WD_%=; bra.uni WL_%=; WD_%=: }" \
                     :: "r"(_m), "r"(_p) : "memory");                               \
    }                                                                               \
} while (0)
#define LDTM_X32(r, a)                                                              \
    asm volatile("tcgen05.ld.sync.aligned.32x32b.x32.b32 "                          \
        "{%0,%1,%2,%3,%4,%5,%6,%7,%8,%9,%10,%11,%12,%13,%14,%15,"                   \
        "%16,%17,%18,%19,%20,%21,%22,%23,%24,%25,%26,%27,%28,%29,%30,%31}, [%32];"  \
        : "=r"((r)[0]),"=r"((r)[1]),"=r"((r)[2]),"=r"((r)[3]),                      \
          "=r"((r)[4]),"=r"((r)[5]),"=r"((r)[6]),"=r"((r)[7]),                      \
          "=r"((r)[8]),"=r"((r)[9]),"=r"((r)[10]),"=r"((r)[11]),                    \
          "=r"((r)[12]),"=r"((r)[13]),"=r"((r)[14]),"=r"((r)[15]),                  \
          "=r"((r)[16]),"=r"((r)[17]),"=r"((r)[18]),"=r"((r)[19]),                  \
          "=r"((r)[20]),"=r"((r)[21]),"=r"((r)[22]),"=r"((r)[23]),                  \
          "=r"((r)[24]),"=r"((r)[25]),"=r"((r)[26]),"=r"((r)[27]),                  \
          "=r"((r)[28]),"=r"((r)[29]),"=r"((r)[30]),"=r"((r)[31])                   \
        : "r"(a))
#define STTM_X16(a, r)                                                              \
    asm volatile("tcgen05.st.sync.aligned.32x32b.x16.b32 [%0], "                    \
        "{%1,%2,%3,%4,%5,%6,%7,%8,%9,%10,%11,%12,%13,%14,%15,%16};"                 \
        :: "r"(a),                                                                  \
           "r"((r)[0]),"r"((r)[1]),"r"((r)[2]),"r"((r)[3]),                         \
           "r"((r)[4]),"r"((r)[5]),"r"((r)[6]),"r"((r)[7]),                         \
           "r"((r)[8]),"r"((r)[9]),"r"((r)[10]),"r"((r)[11]),                       \
           "r"((r)[12]),"r"((r)[13]),"r"((r)[14]),"r"((r)[15])                      \
        : "memory")

// SMEM descriptor: SW128, version=1(Blackwell), LBO=1, SBO=64 (K-major)
static __device__ __forceinline__ uint64_t smem_desc(uint32_t addr) {
    const uint64_t base = (uint64_t(2) << 61) | (uint64_t(1) << 46)
                        | (uint64_t(64) << 32) | (uint64_t(1) << 16);
    return base | ((uint64_t)(addr >> 4) & 0x3FFF);
}

// Convert this thread's X row into bf16 (hi or lo) and STTM into abase.
__device__ __forceinline__ void store_a_row(
    const float* __restrict__ X, int gr, int n_rows, int hi_path,
    uint32_t abase)
{
    const float4* xr = (const float4*)(X + (size_t)gr * DIM);
    #pragma unroll
    for (int q = 0; q < 4; q++) {
        float4 vv[8];
        #pragma unroll
        for (int j = 0; j < 8; j++)
            vv[j] = (gr < n_rows) ? xr[q * 8 + j]
                                  : make_float4(0.f, 0.f, 0.f, 0.f);
        uint32_t rr[16];
        #pragma unroll
        for (int j = 0; j < 8; j++) {
            float a0 = vv[j].x, a1 = vv[j].y, a2 = vv[j].z, a3 = vv[j].w;
            __nv_bfloat16 h0 = __float2bfloat16(a0);
            __nv_bfloat16 h1 = __float2bfloat16(a1);
            __nv_bfloat16 h2 = __float2bfloat16(a2);
            __nv_bfloat16 h3 = __float2bfloat16(a3);
            __nv_bfloat16 o0 = h0, o1 = h1, o2 = h2, o3 = h3;
            if (!hi_path) {
                o0 = __float2bfloat16(a0 - __bfloat162float(h0));
                o1 = __float2bfloat16(a1 - __bfloat162float(h1));
                o2 = __float2bfloat16(a2 - __bfloat162float(h2));
                o3 = __float2bfloat16(a3 - __bfloat162float(h3));
            }
            __nv_bfloat162 p01 = __halves2bfloat162(o0, o1);
            __nv_bfloat162 p23 = __halves2bfloat162(o2, o3);
            rr[2 * j]     = *(uint32_t*)&p01;
            rr[2 * j + 1] = *(uint32_t*)&p23;
        }
        STTM_X16(abase + q * 16, rr);
    }
    TC_WAIT_ST();
    TC_FENCE_BEFORE();
}

// Issue the 3-pass bf16-split MMA chain for one (Bhi,Blo) pair into D.
__device__ __forceinline__ void issue_3pass(
    uint32_t d, uint32_t aHi, uint32_t aLo, uint64_t dBh, uint64_t dBl,
    uint32_t idesc)
{
    const int koff[8] = {0, 2, 4, 6, 1024, 1026, 1028, 1030};
    uint32_t aA[3] = {aHi, aHi, aLo};
    uint64_t pb[3] = {dBh, dBl, dBh};
    uint32_t en = 0;
    for (int p = 0; p < 3; p++)
        for (int ks = 0; ks < 8; ks++) {
            mma_bf16_ts(d, aA[p] + ks * 8, pb[p] + koff[ks], idesc, en);
            en = 1;
        }
}
#endif // USE_TC

// ---------------------------------------------------------------------------
__global__ void __launch_bounds__(256) zero_deg_kernel() {
    int i = blockIdx.x * 256 + threadIdx.x;
    if (i < NP) g_deg[i] = 0.0f;
}

// ---------------------------------------------------------------------------
// All three W matrices -> swizzled bf16 hi/lo W^T images, fully parallel.
__global__ void __launch_bounds__(256) wconv_kernel(
    const float* __restrict__ W0, const float* __restrict__ W1,
    const float* __restrict__ W2)
{
    int i = blockIdx.x * 256 + threadIdx.x;            // 0 .. 3*16384-1
    if (i >= 3 * DIM * DIM) return;
    int m = i >> 14, e = i & (DIM * DIM - 1);
    const float* W = (m == 0) ? W0 : (m == 1) ? W1 : W2;
    int k = e >> 7, n = e & 127;
    float x = W[e];                                     // W[k][n]
    __nv_bfloat16 h = __float2bfloat16(x);
    __nv_bfloat16 l = __float2bfloat16(x - __bfloat162float(h));
    uint32_t o = bf16_off(n, k) >> 1;
    g_WT[m][0][o] = h;
    g_WT[m][1][o] = l;
}

// ---------------------------------------------------------------------------
// idesc kind::f16: dtype=F32, atype=BF16, btype=BF16, (N/8)<<17, (M/16)<<24
#define IDESC_BF16_128 0x8200490u

// ===== Persistent mega GEMM =================================================
// Tiles 0..NT_P-1: paper rows t*128, dual (D1 = X@W_self -> out,
//                  D2 = X@W_cites -> g_Hc).
// Tiles NT_P..NT-1: author rows (t-NT_P)*128, single (D1 = X@W_writes -> g_Hw).
// SMEM: mbar + 6 pre-swizzled B images (self h/l, cites h/l, writes h/l).
// TMEM: D1 0-127, D2 128-255, A0 256-383, A1 384-511 (hi at +0, lo at +64).
#define M_TMEM 0
#define M_MBAR 8
#define M_B0   1024
#define SB_IMG(i) (M_B0 + (i) * 32768)
#define M_TOTAL (M_B0 + 6 * 32768)   // 197632

#define TM_D1 0
#define TM_D2 128
#define TM_A0 256
#define TM_A1 384

__global__ void __launch_bounds__(256, 1) gemm_mega_kernel(
    const float* __restrict__ xp, const float* __restrict__ xa,
    const float* __restrict__ Wc_f, const float* __restrict__ Ww_f,
    const float* __restrict__ Ws_f,
    float* __restrict__ out, float* __restrict__ Hc, float* __restrict__ Hw)
{
    extern __shared__ char smem[];
    const int tid = threadIdx.x, w = tid >> 5, lane = tid & 31;

#if USE_TC
    uint32_t sb = s2u(smem);

    if (w == 0) {
        TC_ALLOC(sb + M_TMEM, 512);
        TC_RELINQ();
    }
    if (tid == 0) MBAR_INIT(sb + M_MBAR, 1);

    // Stage 6 B images: smem order self_h, self_l, cites_h, cites_l,
    // writes_h, writes_l. g_WT order: [0]=cites, [1]=writes, [2]=self.
    {
        const __nv_bfloat16* srcs[6] = {
            g_WT[2][0], g_WT[2][1], g_WT[0][0], g_WT[0][1],
            g_WT[1][0], g_WT[1][1]
        };
        #pragma unroll
        for (int m = 0; m < 6; m++)
            for (int i = tid; i < 2048; i += 256)
                ((float4*)(smem + SB_IMG(m)))[i] = ((const float4*)srcs[m])[i];
    }
    asm volatile("fence.proxy.async.shared::cta;" ::: "memory");
    __syncthreads();

    uint32_t tmem;
    asm volatile("ld.shared.b32 %0, [%1];" : "=r"(tmem) : "r"(sb + M_TMEM));

    const uint64_t dSh = smem_desc(sb + SB_IMG(0)), dSl = smem_desc(sb + SB_IMG(1));
    const uint64_t dCh = smem_desc(sb + SB_IMG(2)), dCl = smem_desc(sb + SB_IMG(3));
    const uint64_t dWh = smem_desc(sb + SB_IMG(4)), dWl = smem_desc(sb + SB_IMG(5));

    const int wg_tid  = tid & 127;
    const int hi_path = (tid < 128);
    const uint32_t a_off = (hi_path ? 0u : 64u) + ((uint32_t)(wg_tid >> 5) << 21);

    // Prologue: load A for this CTA's first tile into buffer 0
    int t = blockIdx.x;
    if (t < NT) {
        int paper = (t < NT_P);
        const float* X = paper ? xp : xa;
        int nr   = paper ? NP : NA;
        int row0 = (paper ? t : t - NT_P) * 128;
        store_a_row(X, row0 + wg_tid, nr, hi_path, tmem + TM_A0 + a_off);
    }

    int i = 0;
    for (; t < NT; t += GRID_PERS, i++) {
        const int paper = (t < NT_P);
        const int row0  = (paper ? t : t - NT_P) * 128;
        const int nr    = paper ? NP : NA;
        const uint32_t abuf = (i & 1) ? TM_A1 : TM_A0;

        __syncthreads();   // A(t) stored by all warps; D free (epilogue t-1 done)

        if (w == 0 && elect1()) {
            TC_FENCE_AFTER();
            uint32_t ah = tmem + abuf, al = tmem + abuf + 64;
            if (paper) {
                issue_3pass(tmem + TM_D1, ah, al, dSh, dSl, IDESC_BF16_128);
                issue_3pass(tmem + TM_D2, ah, al, dCh, dCl, IDESC_BF16_128);
            } else {
                issue_3pass(tmem + TM_D1, ah, al, dWh, dWl, IDESC_BF16_128);
            }
            TC_COMMIT(sb + M_MBAR);
        }

        // Overlap: load A for next tile into the other buffer while MMA runs
        int tn = t + GRID_PERS;
        if (tn < NT) {
            int paper_n = (tn < NT_P);
            const float* Xn = paper_n ? xp : xa;
            int nrn   = paper_n ? NP : NA;
            int row0n = (paper_n ? tn : tn - NT_P) * 128;
            uint32_t abufn = (i & 1) ? TM_A0 : TM_A1;
            store_a_row(Xn, row0n + wg_tid, nrn, hi_path,
                        tmem + abufn + a_off);
        }

        MBAR_WAIT(sb + M_MBAR, i & 1);
        TC_FENCE_AFTER();

        // Epilogue: warp w covers cols c0..c0+63 of rows (w&3)*32+lane
        {
            const uint32_t c0 = (uint32_t)(w >> 2) * 64;
            const int gr = row0 + (w & 3) * 32 + lane;
            uint32_t d[64];

            LDTM_X32(d, tmem + TM_D1 + c0);
            LDTM_X32(d + 32, tmem + TM_D1 + c0 + 32);
            TC_WAIT_LD();
            if (gr < nr) {
                float* Y1 = paper ? out : Hw;
                float4* yp = (float4*)(Y1 + (size_t)gr * DIM + c0);
                #pragma unroll
                for (int j = 0; j < 16; j++)
                    yp[j] = make_float4(__uint_as_float(d[4 * j + 0]),
                                        __uint_as_float(d[4 * j + 1]),
                                        __uint_as_float(d[4 * j + 2]),
                                        __uint_as_float(d[4 * j + 3]));
            }

            if (paper) {
                LDTM_X32(d, tmem + TM_D2 + c0);
                LDTM_X32(d + 32, tmem + TM_D2 + c0 + 32);
                TC_WAIT_LD();
                if (gr < nr) {
                    float4* yp = (float4*)(Hc + (size_t)gr * DIM + c0);
                    #pragma unroll
                    for (int j = 0; j < 16; j++)
                        yp[j] = make_float4(__uint_as_float(d[4 * j + 0]),
                                            __uint_as_float(d[4 * j + 1]),
                                            __uint_as_float(d[4 * j + 2]),
                                            __uint_as_float(d[4 * j + 3]));
                }
            }
            TC_FENCE_BEFORE();
        }
    }

    __syncthreads();
    if (tid == 0) MBAR_INVAL(sb + M_MBAR);
    __syncthreads();
    if (w == 0) TC_DEALLOC(tmem, 512);
#else
    // -------- SIMT fallback (non-'a' PTX target only; never runs on GB300) --
    (void)smem;
    for (int t = blockIdx.x; t < NT; t += GRID_PERS) {
        const int paper = (t < NT_P);
        const int row0  = (paper ? t : t - NT_P) * 128;
        const int nr    = paper ? NP : NA;
        const float* X  = paper ? xp : xa;
        const int nw    = paper ? 2 : 1;
        for (int m = 0; m < nw; m++) {
            const float* Wf = paper ? (m ? Wc_f : Ws_f) : Ww_f;
            float* Y = paper ? (m ? g_Hc : out) : g_Hw;
            float acc[16][4];
            #pragma unroll
            for (int r = 0; r < 16; r++)
                acc[r][0] = acc[r][1] = acc[r][2] = acc[r][3] = 0.f;
            for (int k4 = 0; k4 < 32; k4++) {
                float4 w0 = __ldg((const float4*)(Wf + (k4 * 4 + 0) * DIM) + lane);
                float4 w1 = __ldg((const float4*)(Wf + (k4 * 4 + 1) * DIM) + lane);
                float4 w2 = __ldg((const float4*)(Wf + (k4 * 4 + 2) * DIM) + lane);
                float4 w3 = __ldg((const float4*)(Wf + (k4 * 4 + 3) * DIM) + lane);
                for (int r = 0; r < 16; r++) {
                    int gr = row0 + w + 8 * r;
                    float4 xv = (gr < nr)
                        ? __ldg((const float4*)(X + (size_t)gr * DIM) + k4)
                        : make_float4(0.f, 0.f, 0.f, 0.f);
                    acc[r][0] += xv.x * w0.x + xv.y * w1.x + xv.z * w2.x + xv.w * w3.x;
                    acc[r][1] += xv.x * w0.y + xv.y * w1.y + xv.z * w2.y + xv.w * w3.y;
                    acc[r][2] += xv.x * w0.z + xv.y * w1.z + xv.z * w2.z + xv.w * w3.z;
                    acc[r][3] += xv.x * w0.w + xv.y * w1.w + xv.z * w2.w + xv.w * w3.w;
                }
            }
            #pragma unroll
            for (int r = 0; r < 16; r++) {
                int gr = row0 + w + 8 * r;
                if (gr < nr)
                    ((float4*)(Y + (size_t)gr * DIM))[lane] =
                        make_float4(acc[r][0], acc[r][1], acc[r][2], acc[r][3]);
            }
        }
    }
#endif
}

// ---------------------------------------------------------------------------
// Combined edge scatter. One warp per edge: gather 512B row H[src];
// one red.v4 per lane into out[dst]; lane0 counts degree.
__global__ void __launch_bounds__(256) scatter_all_kernel(
    const float* __restrict__ Hc, const float* __restrict__ Hw,
    const int* __restrict__ c_src, const int* __restrict__ c_dst,
    const int* __restrict__ w_src, const int* __restrict__ w_dst,
    float* __restrict__ out)
{
    int g    = blockIdx.x * 256 + threadIdx.x;
    int e    = g >> 5;
    int lane = threadIdx.x & 31;

    const float* H;
    int s, d;
    if (e < EE) {
        H = Hc; s = __ldg(c_src + e);      d = __ldg(c_dst + e);
    } else {
        H = Hw; s = __ldg(w_src + e - EE); d = __ldg(w_dst + e - EE);
    }

    float4 v = ((const float4*)(H + (size_t)s * DIM))[lane];
    float* op = out + (size_t)d * DIM + lane * 4;
    asm volatile("red.global.add.v4.f32 [%0], {%1, %2, %3, %4};"
                 :: "l"(op), "f"(v.x), "f"(v.y), "f"(v.z), "f"(v.w)
                 : "memory");

    if (lane == 0)
        asm volatile("red.global.add.f32 [%0], %1;"
                     :: "l"(&g_deg[d]), "f"(1.0f) : "memory");
}

// ---------------------------------------------------------------------------
__global__ void __launch_bounds__(256) finalize_kernel(
    float* __restrict__ out, const float* __restrict__ bias)
{
    int i = blockIdx.x * 256 + threadIdx.x;
    if (i >= NP * 32) return;
    int row = i >> 5;
    int c4  = i & 31;

    float inv = 1.0f / (g_deg[row] + 1.0f);
    float4 v = ((float4*)out)[i];
    float4 b = ((const float4*)bias)[c4];
    v.x = fmaxf(fmaf(v.x, inv, b.x), 0.f);
    v.y = fmaxf(fmaf(v.y, inv, b.y), 0.f);
    v.z = fmaxf(fmaf(v.z, inv, b.z), 0.f);
    v.w = fmaxf(fmaf(v.w, inv, b.w), 0.f);
    ((float4*)out)[i] = v;
}

// ---------------------------------------------------------------------------
extern "C" void kernel_launch(void* const* d_in, const int* in_sizes, int n_in,
                              void* d_out, int out_size)
{
    const float* x_paper    = (const float*)d_in[0];
    const float* x_author   = (const float*)d_in[1];
    const float* W_cites    = (const float*)d_in[2];
    const float* W_writes   = (const float*)d_in[3];
    const float* W_self     = (const float*)d_in[4];
    const float* bias       = (const float*)d_in[5];
    const int*   cites_src  = (const int*)d_in[6];
    const int*   cites_dst  = (const int*)d_in[7];
    const int*   writes_src = (const int*)d_in[8];
    const int*   writes_dst = (const int*)d_in[9];
    float*       out        = (float*)d_out;

    cudaFuncSetAttribute(gemm_mega_kernel,
                         cudaFuncAttributeMaxDynamicSharedMemorySize, M_TOTAL);

    void *pHc = nullptr, *pHw = nullptr;
    cudaGetSymbolAddress(&pHc, g_Hc);
    cudaGetSymbolAddress(&pHw, g_Hw);

    // 1. degree accumulator -> 0; all W -> swizzled bf16 hi/lo images
    zero_deg_kernel<<<(NP + 255) / 256, 256>>>();
    wconv_kernel<<<(3 * DIM * DIM + 255) / 256, 256>>>(W_cites, W_writes, W_self);

    // 2. persistent pipelined GEMM (all three matmuls in one launch;
    //    self-transform writes d_out = accumulator init)
    gemm_mega_kernel<<<GRID_PERS, 256, M_TOTAL>>>(
        x_paper, x_author, W_cites, W_writes, W_self,
        out, (float*)pHc, (float*)pHw);

    // 3. combined edge scatter (vectorized L2 atomics) + degree counting
    scatter_all_kernel<<<2 * EE / 8, 256>>>(
        (const float*)pHc, (const float*)pHw,
        cites_src, cites_dst, writes_src, writes_dst, out);

    // 4. mean + bias + relu
    finalize_kernel<<<(NP * 32 + 255) / 256, 256>>>(out, bias);
}

// round 8
// speedup vs baseline: 2.4642x; 1.2904x over previous
#include <cuda_runtime.h>
#include <cuda_bf16.h>
#include <cstdint>

#define NP 100000
#define NA 50000
#define DIM 128
#define EE  500000
#define E2  (2 * EE)

#define NT_P 782            // ceil(NP/128) paper tiles
#define NT_A 391            // ceil(NA/128) author tiles
#define NT   (NT_P + NT_A)  // 1173
#define GRID_PERS 152       // GB300 SM count

#define NBLK 391            // ceil(NP/256) scan blocks

#if defined(__CUDA_ARCH__) && defined(__CUDA_ARCH_FEAT_SM103_ALL)
#define USE_TC 1
#else
#define USE_TC 0
#endif

// ---------------------------------------------------------------------------
// Scratch (allocation-guard-safe __device__ globals)
__device__ float g_Hc[(size_t)NP * DIM];          // x_paper  @ W_cites
__device__ float g_Hw[(size_t)NA * DIM];          // x_author @ W_writes
__device__ __nv_bfloat16 g_WT[3][2][DIM * DIM];   // pre-swizzled B images
// CSR-by-dst machinery
__device__ int g_cnt[NP];                         // in-degree per paper
__device__ int g_off[NP];                         // CSR offsets
__device__ int g_cur[NP];                         // fill cursors
__device__ int g_bsum[NBLK + 1];
__device__ int g_boff[NBLK + 1];
__device__ unsigned g_esrc[E2];                   // src | (rel<<31), grouped by dst

// ---------------------------------------------------------------------------
// Swizzled byte offset of element (r,k) in a 128x128 bf16 K-major blocked-atom
// tile: atom = 8 rows x 64 bf16 (1024B), 16 atom-rows x 2 atom-cols.
__device__ __forceinline__ uint32_t bf16_off(int r, int k) {
    uint32_t b = (uint32_t)(((r >> 3) + (k >> 6) * 16) * 1024
                            + (r & 7) * 128 + (k & 63) * 2);
    return b ^ ((b >> 3) & 0x70);
}

#if USE_TC
// ---------------------------------------------------------------------------
// PTX helpers (sm_103a tcgen05, cg1) — only on the 'a' target.
__device__ __forceinline__ uint32_t s2u(const void* p) {
    uint32_t a;
    asm("{ .reg .u64 t; cvta.to.shared.u64 t, %1; cvt.u32.u64 %0, t; }"
        : "=r"(a) : "l"(p));
    return a;
}
__device__ __forceinline__ bool elect1() {
    uint32_t p;
    asm volatile("{ .reg .pred p; elect.sync _|p, 0xFFFFFFFF; selp.b32 %0,1,0,p; }"
                 : "=r"(p));
    return p != 0;
}
// TS form: A in TMEM, B in SMEM
__device__ __forceinline__ void mma_bf16_ts(uint32_t d, uint32_t a, uint64_t b,
                                            uint32_t idesc, uint32_t en) {
    asm volatile(
        "{\n\t.reg .pred p;\n\tsetp.ne.u32 p, %4, 0;\n\t"
        "tcgen05.mma.cta_group::1.kind::f16 [%0], [%1], %2, %3, {%5,%5,%5,%5}, p;\n\t}"
        :: "r"(d), "r"(a), "l"(b), "r"(idesc), "r"(en), "r"(0u) : "memory");
}
#define TC_ALLOC(sa, n)  asm volatile("tcgen05.alloc.cta_group::1.sync.aligned.shared::cta.b32 [%0], %1;" :: "r"(sa), "r"(n) : "memory")
#define TC_DEALLOC(t, n) asm volatile("tcgen05.dealloc.cta_group::1.sync.aligned.b32 %0, %1;" :: "r"(t), "r"(n))
#define TC_RELINQ()      asm volatile("tcgen05.relinquish_alloc_permit.cta_group::1.sync.aligned;")
#define TC_COMMIT(mb)    asm volatile("tcgen05.commit.cta_group::1.mbarrier::arrive::one.shared::cluster.b64 [%0];" :: "r"(mb) : "memory")
#define TC_WAIT_LD()     asm volatile("tcgen05.wait::ld.sync.aligned;" ::: "memory")
#define TC_WAIT_ST()     asm volatile("tcgen05.wait::st.sync.aligned;" ::: "memory")
#define TC_FENCE_BEFORE() asm volatile("tcgen05.fence::before_thread_sync;" ::: "memory")
#define TC_FENCE_AFTER()  asm volatile("tcgen05.fence::after_thread_sync;" ::: "memory")
#define MBAR_INIT(mb, c) asm volatile("mbarrier.init.shared.b64 [%0], %1;" :: "r"(mb), "r"(c) : "memory")
#define MBAR_INVAL(mb)   asm volatile("mbarrier.inval.shared.b64 [%0];" :: "r"(mb) : "memory")
#define MBAR_WAIT(mb, ph) do {                                                      \
    uint32_t _m = (mb), _p = (ph), _d;                                              \
    asm volatile("{ .reg .pred p; mbarrier.try_wait.parity.acquire.cta.shared::cta.b64 p, [%1], %2; selp.b32 %0,1,0,p; }" \
                 : "=r"(_d) : "r"(_m), "r"(_p) : "memory");                         \
    if (!_d) {                                                                      \
        asm volatile("{ .reg .pred P1; WL_%=: mbarrier.try_wait.parity.acquire.cta.shared::cta.b64 P1, [%0], %1, 0x989680; @P1 bra.uni WD_%=; bra.uni WL_%=; WD_%=: }" \
                     :: "r"(_m), "r"(_p) : "memory");                               \
    }                                                                               \
} while (0)
#define LDTM_X32(r, a)                                                              \
    asm volatile("tcgen05.ld.sync.aligned.32x32b.x32.b32 "                          \
        "{%0,%1,%2,%3,%4,%5,%6,%7,%8,%9,%10,%11,%12,%13,%14,%15,"                   \
        "%16,%17,%18,%19,%20,%21,%22,%23,%24,%25,%26,%27,%28,%29,%30,%31}, [%32];"  \
        : "=r"((r)[0]),"=r"((r)[1]),"=r"((r)[2]),"=r"((r)[3]),                      \
          "=r"((r)[4]),"=r"((r)[5]),"=r"((r)[6]),"=r"((r)[7]),                      \
          "=r"((r)[8]),"=r"((r)[9]),"=r"((r)[10]),"=r"((r)[11]),                    \
          "=r"((r)[12]),"=r"((r)[13]),"=r"((r)[14]),"=r"((r)[15]),                  \
          "=r"((r)[16]),"=r"((r)[17]),"=r"((r)[18]),"=r"((r)[19]),                  \
          "=r"((r)[20]),"=r"((r)[21]),"=r"((r)[22]),"=r"((r)[23]),                  \
          "=r"((r)[24]),"=r"((r)[25]),"=r"((r)[26]),"=r"((r)[27]),                  \
          "=r"((r)[28]),"=r"((r)[29]),"=r"((r)[30]),"=r"((r)[31])                   \
        : "r"(a))
#define STTM_X16(a, r)                                                              \
    asm volatile("tcgen05.st.sync.aligned.32x32b.x16.b32 [%0], "                    \
        "{%1,%2,%3,%4,%5,%6,%7,%8,%9,%10,%11,%12,%13,%14,%15,%16};"                 \
        :: "r"(a),                                                                  \
           "r"((r)[0]),"r"((r)[1]),"r"((r)[2]),"r"((r)[3]),                         \
           "r"((r)[4]),"r"((r)[5]),"r"((r)[6]),"r"((r)[7]),                         \
           "r"((r)[8]),"r"((r)[9]),"r"((r)[10]),"r"((r)[11]),                       \
           "r"((r)[12]),"r"((r)[13]),"r"((r)[14]),"r"((r)[15])                      \
        : "memory")

// SMEM descriptor: SW128, version=1(Blackwell), LBO=1, SBO=64 (K-major)
static __device__ __forceinline__ uint64_t smem_desc(uint32_t addr) {
    const uint64_t base = (uint64_t(2) << 61) | (uint64_t(1) << 46)
                        | (uint64_t(64) << 32) | (uint64_t(1) << 16);
    return base | ((uint64_t)(addr >> 4) & 0x3FFF);
}

// Convert this thread's X row into bf16 (hi or lo) and STTM into abase.
__device__ __forceinline__ void store_a_row(
    const float* __restrict__ X, int gr, int n_rows, int hi_path,
    uint32_t abase)
{
    const float4* xr = (const float4*)(X + (size_t)gr * DIM);
    #pragma unroll
    for (int q = 0; q < 4; q++) {
        float4 vv[8];
        #pragma unroll
        for (int j = 0; j < 8; j++)
            vv[j] = (gr < n_rows) ? xr[q * 8 + j]
                                  : make_float4(0.f, 0.f, 0.f, 0.f);
        uint32_t rr[16];
        #pragma unroll
        for (int j = 0; j < 8; j++) {
            float a0 = vv[j].x, a1 = vv[j].y, a2 = vv[j].z, a3 = vv[j].w;
            __nv_bfloat16 h0 = __float2bfloat16(a0);
            __nv_bfloat16 h1 = __float2bfloat16(a1);
            __nv_bfloat16 h2 = __float2bfloat16(a2);
            __nv_bfloat16 h3 = __float2bfloat16(a3);
            __nv_bfloat16 o0 = h0, o1 = h1, o2 = h2, o3 = h3;
            if (!hi_path) {
                o0 = __float2bfloat16(a0 - __bfloat162float(h0));
                o1 = __float2bfloat16(a1 - __bfloat162float(h1));
                o2 = __float2bfloat16(a2 - __bfloat162float(h2));
                o3 = __float2bfloat16(a3 - __bfloat162float(h3));
            }
            __nv_bfloat162 p01 = __halves2bfloat162(o0, o1);
            __nv_bfloat162 p23 = __halves2bfloat162(o2, o3);
            rr[2 * j]     = *(uint32_t*)&p01;
            rr[2 * j + 1] = *(uint32_t*)&p23;
        }
        STTM_X16(abase + q * 16, rr);
    }
    TC_WAIT_ST();
    TC_FENCE_BEFORE();
}

// Issue the 3-pass bf16-split MMA chain for one (Bhi,Blo) pair into D.
__device__ __forceinline__ void issue_3pass(
    uint32_t d, uint32_t aHi, uint32_t aLo, uint64_t dBh, uint64_t dBl,
    uint32_t idesc)
{
    const int koff[8] = {0, 2, 4, 6, 1024, 1026, 1028, 1030};
    uint32_t aA[3] = {aHi, aHi, aLo};
    uint64_t pb[3] = {dBh, dBl, dBh};
    uint32_t en = 0;
    for (int p = 0; p < 3; p++)
        for (int ks = 0; ks < 8; ks++) {
            mma_bf16_ts(d, aA[p] + ks * 8, pb[p] + koff[ks], idesc, en);
            en = 1;
        }
}
#endif // USE_TC

// ---------------------------------------------------------------------------
__global__ void __launch_bounds__(256) zero_cnt_kernel() {
    int i = blockIdx.x * 256 + threadIdx.x;
    if (i < NP) g_cnt[i] = 0;
}

// ---------------------------------------------------------------------------
// All three W matrices -> swizzled bf16 hi/lo W^T images, fully parallel.
__global__ void __launch_bounds__(256) wconv_kernel(
    const float* __restrict__ W0, const float* __restrict__ W1,
    const float* __restrict__ W2)
{
    int i = blockIdx.x * 256 + threadIdx.x;
    if (i >= 3 * DIM * DIM) return;
    int m = i >> 14, e = i & (DIM * DIM - 1);
    const float* W = (m == 0) ? W0 : (m == 1) ? W1 : W2;
    int k = e >> 7, n = e & 127;
    float x = W[e];                                     // W[k][n]
    __nv_bfloat16 h = __float2bfloat16(x);
    __nv_bfloat16 l = __float2bfloat16(x - __bfloat162float(h));
    uint32_t o = bf16_off(n, k) >> 1;
    g_WT[m][0][o] = h;
    g_WT[m][1][o] = l;
}

// ---------------------------------------------------------------------------
// CSR build: histogram, 3-step scan, fill.
__global__ void __launch_bounds__(256) hist_kernel(
    const int* __restrict__ c_dst, const int* __restrict__ w_dst)
{
    int e = blockIdx.x * 256 + threadIdx.x;
    if (e >= E2) return;
    int d = (e < EE) ? __ldg(c_dst + e) : __ldg(w_dst + e - EE);
    atomicAdd(&g_cnt[d], 1);
}

__global__ void __launch_bounds__(256) scan_a_kernel() {
    __shared__ int sm[256];
    int b = blockIdx.x, t = threadIdx.x;
    int i = b * 256 + t;
    int v = (i < NP) ? g_cnt[i] : 0;
    sm[t] = v;
    __syncthreads();
    int acc = v;
    #pragma unroll
    for (int s = 1; s < 256; s <<= 1) {
        int add = (t >= s) ? sm[t - s] : 0;
        __syncthreads();
        acc += add;
        sm[t] = acc;
        __syncthreads();
    }
    if (i < NP) g_off[i] = acc - v;          // exclusive within block
    if (t == 255) g_bsum[b] = acc;           // block total
}

__global__ void __launch_bounds__(512) scan_b_kernel() {
    __shared__ int sm[512];
    int t = threadIdx.x;
    int v = (t < NBLK) ? g_bsum[t] : 0;
    sm[t] = v;
    __syncthreads();
    int acc = v;
    #pragma unroll
    for (int s = 1; s < 512; s <<= 1) {
        int add = (t >= s) ? sm[t - s] : 0;
        __syncthreads();
        acc += add;
        sm[t] = acc;
        __syncthreads();
    }
    if (t < NBLK) g_boff[t] = acc - v;       // exclusive block offset
}

__global__ void __launch_bounds__(256) scan_c_kernel() {
    int b = blockIdx.x, t = threadIdx.x;
    int i = b * 256 + t;
    if (i < NP) {
        int o = g_off[i] + g_boff[b];
        g_off[i] = o;
        g_cur[i] = o;
    }
}

__global__ void __launch_bounds__(256) fill_kernel(
    const int* __restrict__ c_src, const int* __restrict__ c_dst,
    const int* __restrict__ w_src, const int* __restrict__ w_dst)
{
    int e = blockIdx.x * 256 + threadIdx.x;
    if (e >= E2) return;
    int d;
    unsigned sv;
    if (e < EE) {
        d = __ldg(c_dst + e);
        sv = (unsigned)__ldg(c_src + e);
    } else {
        d = __ldg(w_dst + e - EE);
        sv = (unsigned)__ldg(w_src + e - EE) | 0x80000000u;
    }
    int pos = atomicAdd(&g_cur[d], 1);
    g_esrc[pos] = sv;
}

// ---------------------------------------------------------------------------
// Pull aggregation + fused finalize. One warp per paper node:
// acc = sum over in-edges of H[src]; out = relu((self + acc)/(deg+1) + bias).
__global__ void __launch_bounds__(256) aggregate_kernel(
    float* __restrict__ out, const float* __restrict__ bias)
{
    int d    = (blockIdx.x * 256 + threadIdx.x) >> 5;
    int lane = threadIdx.x & 31;
    if (d >= NP) return;

    const int n    = g_cnt[d];
    const int base = g_off[d];

    float4 acc = make_float4(0.f, 0.f, 0.f, 0.f);
    int j = 0;
    for (; j + 2 <= n; j += 2) {
        unsigned s0 = __ldg(&g_esrc[base + j]);
        unsigned s1 = __ldg(&g_esrc[base + j + 1]);
        const float* H0 = (s0 & 0x80000000u) ? g_Hw : g_Hc;
        const float* H1 = (s1 & 0x80000000u) ? g_Hw : g_Hc;
        float4 v0 = ((const float4*)(H0 + (size_t)(s0 & 0x7FFFFFFFu) * DIM))[lane];
        float4 v1 = ((const float4*)(H1 + (size_t)(s1 & 0x7FFFFFFFu) * DIM))[lane];
        acc.x += v0.x + v1.x;
        acc.y += v0.y + v1.y;
        acc.z += v0.z + v1.z;
        acc.w += v0.w + v1.w;
    }
    if (j < n) {
        unsigned s0 = __ldg(&g_esrc[base + j]);
        const float* H0 = (s0 & 0x80000000u) ? g_Hw : g_Hc;
        float4 v0 = ((const float4*)(H0 + (size_t)(s0 & 0x7FFFFFFFu) * DIM))[lane];
        acc.x += v0.x; acc.y += v0.y; acc.z += v0.z; acc.w += v0.w;
    }

    const float inv = 1.0f / (float)(n + 1);
    float4* op = (float4*)(out + (size_t)d * DIM) + lane;
    float4 self = *op;
    float4 b = ((const float4*)bias)[lane];
    float4 r;
    r.x = fmaxf(fmaf((self.x + acc.x), inv, b.x), 0.f);
    r.y = fmaxf(fmaf((self.y + acc.y), inv, b.y), 0.f);
    r.z = fmaxf(fmaf((self.z + acc.z), inv, b.z), 0.f);
    r.w = fmaxf(fmaf((self.w + acc.w), inv, b.w), 0.f);
    *op = r;
}

// ---------------------------------------------------------------------------
// idesc kind::f16: dtype=F32, atype=BF16, btype=BF16, (N/8)<<17, (M/16)<<24
#define IDESC_BF16_128 0x8200490u

// ===== Persistent mega GEMM (unchanged from R7) =============================
#define M_TMEM 0
#define M_MBAR 8
#define M_B0   1024
#define SB_IMG(i) (M_B0 + (i) * 32768)
#define M_TOTAL (M_B0 + 6 * 32768)   // 197632

#define TM_D1 0
#define TM_D2 128
#define TM_A0 256
#define TM_A1 384

__global__ void __launch_bounds__(256, 1) gemm_mega_kernel(
    const float* __restrict__ xp, const float* __restrict__ xa,
    const float* __restrict__ Wc_f, const float* __restrict__ Ww_f,
    const float* __restrict__ Ws_f,
    float* __restrict__ out, float* __restrict__ Hc, float* __restrict__ Hw)
{
    extern __shared__ char smem[];
    const int tid = threadIdx.x, w = tid >> 5, lane = tid & 31;

#if USE_TC
    uint32_t sb = s2u(smem);

    if (w == 0) {
        TC_ALLOC(sb + M_TMEM, 512);
        TC_RELINQ();
    }
    if (tid == 0) MBAR_INIT(sb + M_MBAR, 1);

    {
        const __nv_bfloat16* srcs[6] = {
            g_WT[2][0], g_WT[2][1], g_WT[0][0], g_WT[0][1],
            g_WT[1][0], g_WT[1][1]
        };
        #pragma unroll
        for (int m = 0; m < 6; m++)
            for (int i = tid; i < 2048; i += 256)
                ((float4*)(smem + SB_IMG(m)))[i] = ((const float4*)srcs[m])[i];
    }
    asm volatile("fence.proxy.async.shared::cta;" ::: "memory");
    __syncthreads();

    uint32_t tmem;
    asm volatile("ld.shared.b32 %0, [%1];" : "=r"(tmem) : "r"(sb + M_TMEM));

    const uint64_t dSh = smem_desc(sb + SB_IMG(0)), dSl = smem_desc(sb + SB_IMG(1));
    const uint64_t dCh = smem_desc(sb + SB_IMG(2)), dCl = smem_desc(sb + SB_IMG(3));
    const uint64_t dWh = smem_desc(sb + SB_IMG(4)), dWl = smem_desc(sb + SB_IMG(5));

    const int wg_tid  = tid & 127;
    const int hi_path = (tid < 128);
    const uint32_t a_off = (hi_path ? 0u : 64u) + ((uint32_t)(wg_tid >> 5) << 21);

    int t = blockIdx.x;
    if (t < NT) {
        int paper = (t < NT_P);
        const float* X = paper ? xp : xa;
        int nr   = paper ? NP : NA;
        int row0 = (paper ? t : t - NT_P) * 128;
        store_a_row(X, row0 + wg_tid, nr, hi_path, tmem + TM_A0 + a_off);
    }

    int i = 0;
    for (; t < NT; t += GRID_PERS, i++) {
        const int paper = (t < NT_P);
        const int row0  = (paper ? t : t - NT_P) * 128;
        const int nr    = paper ? NP : NA;
        const uint32_t abuf = (i & 1) ? TM_A1 : TM_A0;

        __syncthreads();

        if (w == 0 && elect1()) {
            TC_FENCE_AFTER();
            uint32_t ah = tmem + abuf, al = tmem + abuf + 64;
            if (paper) {
                issue_3pass(tmem + TM_D1, ah, al, dSh, dSl, IDESC_BF16_128);
                issue_3pass(tmem + TM_D2, ah, al, dCh, dCl, IDESC_BF16_128);
            } else {
                issue_3pass(tmem + TM_D1, ah, al, dWh, dWl, IDESC_BF16_128);
            }
            TC_COMMIT(sb + M_MBAR);
        }

        int tn = t + GRID_PERS;
        if (tn < NT) {
            int paper_n = (tn < NT_P);
            const float* Xn = paper_n ? xp : xa;
            int nrn   = paper_n ? NP : NA;
            int row0n = (paper_n ? tn : tn - NT_P) * 128;
            uint32_t abufn = (i & 1) ? TM_A0 : TM_A1;
            store_a_row(Xn, row0n + wg_tid, nrn, hi_path,
                        tmem + abufn + a_off);
        }

        MBAR_WAIT(sb + M_MBAR, i & 1);
        TC_FENCE_AFTER();

        {
            const uint32_t c0 = (uint32_t)(w >> 2) * 64;
            const int gr = row0 + (w & 3) * 32 + lane;
            uint32_t d[64];

            LDTM_X32(d, tmem + TM_D1 + c0);
            LDTM_X32(d + 32, tmem + TM_D1 + c0 + 32);
            TC_WAIT_LD();
            if (gr < nr) {
                float* Y1 = paper ? out : Hw;
                float4* yp = (float4*)(Y1 + (size_t)gr * DIM + c0);
                #pragma unroll
                for (int j = 0; j < 16; j++)
                    yp[j] = make_float4(__uint_as_float(d[4 * j + 0]),
                                        __uint_as_float(d[4 * j + 1]),
                                        __uint_as_float(d[4 * j + 2]),
                                        __uint_as_float(d[4 * j + 3]));
            }

            if (paper) {
                LDTM_X32(d, tmem + TM_D2 + c0);
                LDTM_X32(d + 32, tmem + TM_D2 + c0 + 32);
                TC_WAIT_LD();
                if (gr < nr) {
                    float4* yp = (float4*)(Hc + (size_t)gr * DIM + c0);
                    #pragma unroll
                    for (int j = 0; j < 16; j++)
                        yp[j] = make_float4(__uint_as_float(d[4 * j + 0]),
                                            __uint_as_float(d[4 * j + 1]),
                                            __uint_as_float(d[4 * j + 2]),
                                            __uint_as_float(d[4 * j + 3]));
                }
            }
            TC_FENCE_BEFORE();
        }
    }

    __syncthreads();
    if (tid == 0) MBAR_INVAL(sb + M_MBAR);
    __syncthreads();
    if (w == 0) TC_DEALLOC(tmem, 512);
#else
    // -------- SIMT fallback (non-'a' PTX target only; never runs on GB300) --
    (void)smem;
    for (int t = blockIdx.x; t < NT; t += GRID_PERS) {
        const int paper = (t < NT_P);
        const int row0  = (paper ? t : t - NT_P) * 128;
        const int nr    = paper ? NP : NA;
        const float* X  = paper ? xp : xa;
        const int nw    = paper ? 2 : 1;
        for (int m = 0; m < nw; m++) {
            const float* Wf = paper ? (m ? Wc_f : Ws_f) : Ww_f;
            float* Y = paper ? (m ? g_Hc : out) : g_Hw;
            float acc[16][4];
            #pragma unroll
            for (int r = 0; r < 16; r++)
                acc[r][0] = acc[r][1] = acc[r][2] = acc[r][3] = 0.f;
            for (int k4 = 0; k4 < 32; k4++) {
                float4 w0 = __ldg((const float4*)(Wf + (k4 * 4 + 0) * DIM) + lane);
                float4 w1 = __ldg((const float4*)(Wf + (k4 * 4 + 1) * DIM) + lane);
                float4 w2 = __ldg((const float4*)(Wf + (k4 * 4 + 2) * DIM) + lane);
                float4 w3 = __ldg((const float4*)(Wf + (k4 * 4 + 3) * DIM) + lane);
                for (int r = 0; r < 16; r++) {
                    int gr = row0 + w + 8 * r;
                    float4 xv = (gr < nr)
                        ? __ldg((const float4*)(X + (size_t)gr * DIM) + k4)
                        : make_float4(0.f, 0.f, 0.f, 0.f);
                    acc[r][0] += xv.x * w0.x + xv.y * w1.x + xv.z * w2.x + xv.w * w3.x;
                    acc[r][1] += xv.x * w0.y + xv.y * w1.y + xv.z * w2.y + xv.w * w3.y;
                    acc[r][2] += xv.x * w0.z + xv.y * w1.z + xv.z * w2.z + xv.w * w3.z;
                    acc[r][3] += xv.x * w0.w + xv.y * w1.w + xv.z * w2.w + xv.w * w3.w;
                }
            }
            #pragma unroll
            for (int r = 0; r < 16; r++) {
                int gr = row0 + w + 8 * r;
                if (gr < nr)
                    ((float4*)(Y + (size_t)gr * DIM))[lane] =
                        make_float4(acc[r][0], acc[r][1], acc[r][2], acc[r][3]);
            }
        }
    }
#endif
}

// ---------------------------------------------------------------------------
extern "C" void kernel_launch(void* const* d_in, const int* in_sizes, int n_in,
                              void* d_out, int out_size)
{
    const float* x_paper    = (const float*)d_in[0];
    const float* x_author   = (const float*)d_in[1];
    const float* W_cites    = (const float*)d_in[2];
    const float* W_writes   = (const float*)d_in[3];
    const float* W_self     = (const float*)d_in[4];
    const float* bias       = (const float*)d_in[5];
    const int*   cites_src  = (const int*)d_in[6];
    const int*   cites_dst  = (const int*)d_in[7];
    const int*   writes_src = (const int*)d_in[8];
    const int*   writes_dst = (const int*)d_in[9];
    float*       out        = (float*)d_out;

    cudaFuncSetAttribute(gemm_mega_kernel,
                         cudaFuncAttributeMaxDynamicSharedMemorySize, M_TOTAL);

    void *pHc = nullptr, *pHw = nullptr;
    cudaGetSymbolAddress(&pHc, g_Hc);
    cudaGetSymbolAddress(&pHw, g_Hw);

    // 1. prologue: zero degree counts; W -> swizzled bf16 hi/lo images
    zero_cnt_kernel<<<NBLK, 256>>>();
    wconv_kernel<<<(3 * DIM * DIM + 255) / 256, 256>>>(W_cites, W_writes, W_self);

    // 2. CSR build (independent of GEMM): histogram -> scan -> fill
    hist_kernel<<<(E2 + 255) / 256, 256>>>(cites_dst, writes_dst);
    scan_a_kernel<<<NBLK, 256>>>();
    scan_b_kernel<<<1, 512>>>();
    scan_c_kernel<<<NBLK, 256>>>();
    fill_kernel<<<(E2 + 255) / 256, 256>>>(cites_src, cites_dst,
                                           writes_src, writes_dst);

    // 3. persistent pipelined GEMM (self -> out, cites -> g_Hc, writes -> g_Hw)
    gemm_mega_kernel<<<GRID_PERS, 256, M_TOTAL>>>(
        x_paper, x_author, W_cites, W_writes, W_self,
        out, (float*)pHc, (float*)pHw);

    // 4. pull aggregation + fused mean/bias/relu (no f32 atomics)
    aggregate_kernel<<<(NP * 32 + 255) / 256, 256>>>(out, bias);
}

// round 9
// speedup vs baseline: 2.6130x; 1.0604x over previous
#include <cuda_runtime.h>
#include <cuda_bf16.h>
#include <cstdint>

#define NP 100000
#define NA 50000
#define DIM 128
#define EE  500000
#define E2  (2 * EE)

#define NT_P 782            // ceil(NP/128) paper tiles
#define NT_A 391            // ceil(NA/128) author tiles
#define NT   (NT_P + NT_A)  // 1173
#define GRID_PERS 152       // GB300 SM count

#define NBLK 391            // ceil(NP/256) scan blocks

#if defined(__CUDA_ARCH__) && defined(__CUDA_ARCH_FEAT_SM103_ALL)
#define USE_TC 1
#else
#define USE_TC 0
#endif

// ---------------------------------------------------------------------------
// Scratch (allocation-guard-safe __device__ globals)
__device__ float g_Hc[(size_t)NP * DIM];          // x_paper  @ W_cites
__device__ float g_Hw[(size_t)NA * DIM];          // x_author @ W_writes
__device__ __nv_bfloat16 g_WT[3][2][DIM * DIM];   // pre-swizzled B images
// CSR-by-dst machinery
__device__ int g_cnt[NP];                         // in-degree per paper
__device__ int g_off[NP];                         // CSR offsets
__device__ int g_cur[NP];                         // fill cursors
__device__ int g_bsum[NBLK + 1];
__device__ int g_boff[NBLK + 1];
__device__ unsigned g_esrc[E2];                   // src | (rel<<31), grouped by dst

// ---------------------------------------------------------------------------
// Swizzled byte offset of element (r,k) in a 128x128 bf16 K-major blocked-atom
// tile: atom = 8 rows x 64 bf16 (1024B), 16 atom-rows x 2 atom-cols.
__device__ __forceinline__ uint32_t bf16_off(int r, int k) {
    uint32_t b = (uint32_t)(((r >> 3) + (k >> 6) * 16) * 1024
                            + (r & 7) * 128 + (k & 63) * 2);
    return b ^ ((b >> 3) & 0x70);
}

#if USE_TC
// ---------------------------------------------------------------------------
// PTX helpers (sm_103a tcgen05, cg1) — only on the 'a' target.
__device__ __forceinline__ uint32_t s2u(const void* p) {
    uint32_t a;
    asm("{ .reg .u64 t; cvta.to.shared.u64 t, %1; cvt.u32.u64 %0, t; }"
        : "=r"(a) : "l"(p));
    return a;
}
__device__ __forceinline__ bool elect1() {
    uint32_t p;
    asm volatile("{ .reg .pred p; elect.sync _|p, 0xFFFFFFFF; selp.b32 %0,1,0,p; }"
                 : "=r"(p));
    return p != 0;
}
// TS form: A in TMEM, B in SMEM
__device__ __forceinline__ void mma_bf16_ts(uint32_t d, uint32_t a, uint64_t b,
                                            uint32_t idesc, uint32_t en) {
    asm volatile(
        "{\n\t.reg .pred p;\n\tsetp.ne.u32 p, %4, 0;\n\t"
        "tcgen05.mma.cta_group::1.kind::f16 [%0], [%1], %2, %3, {%5,%5,%5,%5}, p;\n\t}"
        :: "r"(d), "r"(a), "l"(b), "r"(idesc), "r"(en), "r"(0u) : "memory");
}
#define TC_ALLOC(sa, n)  asm volatile("tcgen05.alloc.cta_group::1.sync.aligned.shared::cta.b32 [%0], %1;" :: "r"(sa), "r"(n) : "memory")
#define TC_DEALLOC(t, n) asm volatile("tcgen05.dealloc.cta_group::1.sync.aligned.b32 %0, %1;" :: "r"(t), "r"(n))
#define TC_RELINQ()      asm volatile("tcgen05.relinquish_alloc_permit.cta_group::1.sync.aligned;")
#define TC_COMMIT(mb)    asm volatile("tcgen05.commit.cta_group::1.mbarrier::arrive::one.shared::cluster.b64 [%0];" :: "r"(mb) : "memory")
#define TC_WAIT_LD()     asm volatile("tcgen05.wait::ld.sync.aligned;" ::: "memory")
#define TC_WAIT_ST()     asm volatile("tcgen05.wait::st.sync.aligned;" ::: "memory")
#define TC_FENCE_BEFORE() asm volatile("tcgen05.fence::before_thread_sync;" ::: "memory")
#define TC_FENCE_AFTER()  asm volatile("tcgen05.fence::after_thread_sync;" ::: "memory")
#define MBAR_INIT(mb, c) asm volatile("mbarrier.init.shared.b64 [%0], %1;" :: "r"(mb), "r"(c) : "memory")
#define MBAR_INVAL(mb)   asm volatile("mbarrier.inval.shared.b64 [%0];" :: "r"(mb) : "memory")
#define MBAR_WAIT(mb, ph) do {                                                      \
    uint32_t _m = (mb), _p = (ph), _d;                                              \
    asm volatile("{ .reg .pred p; mbarrier.try_wait.parity.acquire.cta.shared::cta.b64 p, [%1], %2; selp.b32 %0,1,0,p; }" \
                 : "=r"(_d) : "r"(_m), "r"(_p) : "memory");                         \
    if (!_d) {                                                                      \
        asm volatile("{ .reg .pred P1; WL_%=: mbarrier.try_wait.parity.acquire.cta.shared::cta.b64 P1, [%0], %1, 0x989680; @P1 bra.uni WD_%=; bra.uni WL_%=; WD_%=: }" \
                     :: "r"(_m), "r"(_p) : "memory");                               \
    }                                                                               \
} while (0)
#define LDTM_X32(r, a)                                                              \
    asm volatile("tcgen05.ld.sync.aligned.32x32b.x32.b32 "                          \
        "{%0,%1,%2,%3,%4,%5,%6,%7,%8,%9,%10,%11,%12,%13,%14,%15,"                   \
        "%16,%17,%18,%19,%20,%21,%22,%23,%24,%25,%26,%27,%28,%29,%30,%31}, [%32];"  \
        : "=r"((r)[0]),"=r"((r)[1]),"=r"((r)[2]),"=r"((r)[3]),                      \
          "=r"((r)[4]),"=r"((r)[5]),"=r"((r)[6]),"=r"((r)[7]),                      \
          "=r"((r)[8]),"=r"((r)[9]),"=r"((r)[10]),"=r"((r)[11]),                    \
          "=r"((r)[12]),"=r"((r)[13]),"=r"((r)[14]),"=r"((r)[15]),                  \
          "=r"((r)[16]),"=r"((r)[17]),"=r"((r)[18]),"=r"((r)[19]),                  \
          "=r"((r)[20]),"=r"((r)[21]),"=r"((r)[22]),"=r"((r)[23]),                  \
          "=r"((r)[24]),"=r"((r)[25]),"=r"((r)[26]),"=r"((r)[27]),                  \
          "=r"((r)[28]),"=r"((r)[29]),"=r"((r)[30]),"=r"((r)[31])                   \
        : "r"(a))
#define STTM_X16(a, r)                                                              \
    asm volatile("tcgen05.st.sync.aligned.32x32b.x16.b32 [%0], "                    \
        "{%1,%2,%3,%4,%5,%6,%7,%8,%9,%10,%11,%12,%13,%14,%15,%16};"                 \
        :: "r"(a),                                                                  \
           "r"((r)[0]),"r"((r)[1]),"r"((r)[2]),"r"((r)[3]),                         \
           "r"((r)[4]),"r"((r)[5]),"r"((r)[6]),"r"((r)[7]),                         \
           "r"((r)[8]),"r"((r)[9]),"r"((r)[10]),"r"((r)[11]),                       \
           "r"((r)[12]),"r"((r)[13]),"r"((r)[14]),"r"((r)[15])                      \
        : "memory")

// SMEM descriptor: SW128, version=1(Blackwell), LBO=1, SBO=64 (K-major)
static __device__ __forceinline__ uint64_t smem_desc(uint32_t addr) {
    const uint64_t base = (uint64_t(2) << 61) | (uint64_t(1) << 46)
                        | (uint64_t(64) << 32) | (uint64_t(1) << 16);
    return base | ((uint64_t)(addr >> 4) & 0x3FFF);
}

// Convert this thread's X row into bf16 (hi or lo) and STTM into abase.
__device__ __forceinline__ void store_a_row(
    const float* __restrict__ X, int gr, int n_rows, int hi_path,
    uint32_t abase)
{
    const float4* xr = (const float4*)(X + (size_t)gr * DIM);
    #pragma unroll
    for (int q = 0; q < 4; q++) {
        float4 vv[8];
        #pragma unroll
        for (int j = 0; j < 8; j++)
            vv[j] = (gr < n_rows) ? xr[q * 8 + j]
                                  : make_float4(0.f, 0.f, 0.f, 0.f);
        uint32_t rr[16];
        #pragma unroll
        for (int j = 0; j < 8; j++) {
            float a0 = vv[j].x, a1 = vv[j].y, a2 = vv[j].z, a3 = vv[j].w;
            __nv_bfloat16 h0 = __float2bfloat16(a0);
            __nv_bfloat16 h1 = __float2bfloat16(a1);
            __nv_bfloat16 h2 = __float2bfloat16(a2);
            __nv_bfloat16 h3 = __float2bfloat16(a3);
            __nv_bfloat16 o0 = h0, o1 = h1, o2 = h2, o3 = h3;
            if (!hi_path) {
                o0 = __float2bfloat16(a0 - __bfloat162float(h0));
                o1 = __float2bfloat16(a1 - __bfloat162float(h1));
                o2 = __float2bfloat16(a2 - __bfloat162float(h2));
                o3 = __float2bfloat16(a3 - __bfloat162float(h3));
            }
            __nv_bfloat162 p01 = __halves2bfloat162(o0, o1);
            __nv_bfloat162 p23 = __halves2bfloat162(o2, o3);
            rr[2 * j]     = *(uint32_t*)&p01;
            rr[2 * j + 1] = *(uint32_t*)&p23;
        }
        STTM_X16(abase + q * 16, rr);
    }
    TC_WAIT_ST();
    TC_FENCE_BEFORE();
}

// Issue the 3-pass bf16-split MMA chain for one (Bhi,Blo) pair into D.
__device__ __forceinline__ void issue_3pass(
    uint32_t d, uint32_t aHi, uint32_t aLo, uint64_t dBh, uint64_t dBl,
    uint32_t idesc)
{
    const int koff[8] = {0, 2, 4, 6, 1024, 1026, 1028, 1030};
    uint32_t aA[3] = {aHi, aHi, aLo};
    uint64_t pb[3] = {dBh, dBl, dBh};
    uint32_t en = 0;
    for (int p = 0; p < 3; p++)
        for (int ks = 0; ks < 8; ks++) {
            mma_bf16_ts(d, aA[p] + ks * 8, pb[p] + koff[ks], idesc, en);
            en = 1;
        }
}
#endif // USE_TC

// ---------------------------------------------------------------------------
__global__ void __launch_bounds__(256) zero_cnt_kernel() {
    int i = blockIdx.x * 256 + threadIdx.x;
    if (i < NP) g_cnt[i] = 0;
}

// ---------------------------------------------------------------------------
// All three W matrices -> swizzled bf16 hi/lo W^T images, fully parallel.
__global__ void __launch_bounds__(256) wconv_kernel(
    const float* __restrict__ W0, const float* __restrict__ W1,
    const float* __restrict__ W2)
{
    int i = blockIdx.x * 256 + threadIdx.x;
    if (i >= 3 * DIM * DIM) return;
    int m = i >> 14, e = i & (DIM * DIM - 1);
    const float* W = (m == 0) ? W0 : (m == 1) ? W1 : W2;
    int k = e >> 7, n = e & 127;
    float x = W[e];                                     // W[k][n]
    __nv_bfloat16 h = __float2bfloat16(x);
    __nv_bfloat16 l = __float2bfloat16(x - __bfloat162float(h));
    uint32_t o = bf16_off(n, k) >> 1;
    g_WT[m][0][o] = h;
    g_WT[m][1][o] = l;
}

// ---------------------------------------------------------------------------
// CSR build: histogram, 3-step scan, fill.
__global__ void __launch_bounds__(256) hist_kernel(
    const int* __restrict__ c_dst, const int* __restrict__ w_dst)
{
    int e = blockIdx.x * 256 + threadIdx.x;
    if (e >= E2) return;
    int d = (e < EE) ? __ldg(c_dst + e) : __ldg(w_dst + e - EE);
    atomicAdd(&g_cnt[d], 1);
}

__global__ void __launch_bounds__(256) scan_a_kernel() {
    __shared__ int sm[256];
    int b = blockIdx.x, t = threadIdx.x;
    int i = b * 256 + t;
    int v = (i < NP) ? g_cnt[i] : 0;
    sm[t] = v;
    __syncthreads();
    int acc = v;
    #pragma unroll
    for (int s = 1; s < 256; s <<= 1) {
        int add = (t >= s) ? sm[t - s] : 0;
        __syncthreads();
        acc += add;
        sm[t] = acc;
        __syncthreads();
    }
    if (i < NP) g_off[i] = acc - v;          // exclusive within block
    if (t == 255) g_bsum[b] = acc;           // block total
}

__global__ void __launch_bounds__(512) scan_b_kernel() {
    __shared__ int sm[512];
    int t = threadIdx.x;
    int v = (t < NBLK) ? g_bsum[t] : 0;
    sm[t] = v;
    __syncthreads();
    int acc = v;
    #pragma unroll
    for (int s = 1; s < 512; s <<= 1) {
        int add = (t >= s) ? sm[t - s] : 0;
        __syncthreads();
        acc += add;
        sm[t] = acc;
        __syncthreads();
    }
    if (t < NBLK) g_boff[t] = acc - v;       // exclusive block offset
}

__global__ void __launch_bounds__(256) scan_c_kernel() {
    int b = blockIdx.x, t = threadIdx.x;
    int i = b * 256 + t;
    if (i < NP) {
        int o = g_off[i] + g_boff[b];
        g_off[i] = o;
        g_cur[i] = o;
    }
}

__global__ void __launch_bounds__(256) fill_kernel(
    const int* __restrict__ c_src, const int* __restrict__ c_dst,
    const int* __restrict__ w_src, const int* __restrict__ w_dst)
{
    int e = blockIdx.x * 256 + threadIdx.x;
    if (e >= E2) return;
    int d;
    unsigned sv;
    if (e < EE) {
        d = __ldg(c_dst + e);
        sv = (unsigned)__ldg(c_src + e);
    } else {
        d = __ldg(w_dst + e - EE);
        sv = (unsigned)__ldg(w_src + e - EE) | 0x80000000u;
    }
    int pos = atomicAdd(&g_cur[d], 1);
    g_esrc[pos] = sv;
}

// ---------------------------------------------------------------------------
// Pull aggregation + fused finalize. One warp per paper node:
// acc = sum over in-edges of H[src]; out = relu((self + acc)/(deg+1) + bias).
__global__ void __launch_bounds__(256) aggregate_kernel(
    float* __restrict__ out, const float* __restrict__ bias)
{
    int d    = (blockIdx.x * 256 + threadIdx.x) >> 5;
    int lane = threadIdx.x & 31;
    if (d >= NP) return;

    const int n    = g_cnt[d];
    const int base = g_off[d];

    float4 acc = make_float4(0.f, 0.f, 0.f, 0.f);
    int j = 0;
    for (; j + 2 <= n; j += 2) {
        unsigned s0 = __ldg(&g_esrc[base + j]);
        unsigned s1 = __ldg(&g_esrc[base + j + 1]);
        const float* H0 = (s0 & 0x80000000u) ? g_Hw : g_Hc;
        const float* H1 = (s1 & 0x80000000u) ? g_Hw : g_Hc;
        float4 v0 = ((const float4*)(H0 + (size_t)(s0 & 0x7FFFFFFFu) * DIM))[lane];
        float4 v1 = ((const float4*)(H1 + (size_t)(s1 & 0x7FFFFFFFu) * DIM))[lane];
        acc.x += v0.x + v1.x;
        acc.y += v0.y + v1.y;
        acc.z += v0.z + v1.z;
        acc.w += v0.w + v1.w;
    }
    if (j < n) {
        unsigned s0 = __ldg(&g_esrc[base + j]);
        const float* H0 = (s0 & 0x80000000u) ? g_Hw : g_Hc;
        float4 v0 = ((const float4*)(H0 + (size_t)(s0 & 0x7FFFFFFFu) * DIM))[lane];
        acc.x += v0.x; acc.y += v0.y; acc.z += v0.z; acc.w += v0.w;
    }

    const float inv = 1.0f / (float)(n + 1);
    float4* op = (float4*)(out + (size_t)d * DIM) + lane;
    float4 self = *op;
    float4 b = ((const float4*)bias)[lane];
    float4 r;
    r.x = fmaxf(fmaf((self.x + acc.x), inv, b.x), 0.f);
    r.y = fmaxf(fmaf((self.y + acc.y), inv, b.y), 0.f);
    r.z = fmaxf(fmaf((self.z + acc.z), inv, b.z), 0.f);
    r.w = fmaxf(fmaf((self.w + acc.w), inv, b.w), 0.f);
    *op = r;
}

// ---------------------------------------------------------------------------
// idesc kind::f16: dtype=F32, atype=BF16, btype=BF16, (N/8)<<17, (M/16)<<24
#define IDESC_BF16_128 0x8200490u

// ===== Persistent mega GEMM (unchanged from R8) =============================
#define M_TMEM 0
#define M_MBAR 8
#define M_B0   1024
#define SB_IMG(i) (M_B0 + (i) * 32768)
#define M_TOTAL (M_B0 + 6 * 32768)   // 197632

#define TM_D1 0
#define TM_D2 128
#define TM_A0 256
#define TM_A1 384

__global__ void __launch_bounds__(256, 1) gemm_mega_kernel(
    const float* __restrict__ xp, const float* __restrict__ xa,
    const float* __restrict__ Wc_f, const float* __restrict__ Ww_f,
    const float* __restrict__ Ws_f,
    float* __restrict__ out, float* __restrict__ Hc, float* __restrict__ Hw)
{
    extern __shared__ char smem[];
    const int tid = threadIdx.x, w = tid >> 5, lane = tid & 31;

#if USE_TC
    uint32_t sb = s2u(smem);

    if (w == 0) {
        TC_ALLOC(sb + M_TMEM, 512);
        TC_RELINQ();
    }
    if (tid == 0) MBAR_INIT(sb + M_MBAR, 1);

    {
        const __nv_bfloat16* srcs[6] = {
            g_WT[2][0], g_WT[2][1], g_WT[0][0], g_WT[0][1],
            g_WT[1][0], g_WT[1][1]
        };
        #pragma unroll
        for (int m = 0; m < 6; m++)
            for (int i = tid; i < 2048; i += 256)
                ((float4*)(smem + SB_IMG(m)))[i] = ((const float4*)srcs[m])[i];
    }
    asm volatile("fence.proxy.async.shared::cta;" ::: "memory");
    __syncthreads();

    uint32_t tmem;
    asm volatile("ld.shared.b32 %0, [%1];" : "=r"(tmem) : "r"(sb + M_TMEM));

    const uint64_t dSh = smem_desc(sb + SB_IMG(0)), dSl = smem_desc(sb + SB_IMG(1));
    const uint64_t dCh = smem_desc(sb + SB_IMG(2)), dCl = smem_desc(sb + SB_IMG(3));
    const uint64_t dWh = smem_desc(sb + SB_IMG(4)), dWl = smem_desc(sb + SB_IMG(5));

    const int wg_tid  = tid & 127;
    const int hi_path = (tid < 128);
    const uint32_t a_off = (hi_path ? 0u : 64u) + ((uint32_t)(wg_tid >> 5) << 21);

    int t = blockIdx.x;
    if (t < NT) {
        int paper = (t < NT_P);
        const float* X = paper ? xp : xa;
        int nr   = paper ? NP : NA;
        int row0 = (paper ? t : t - NT_P) * 128;
        store_a_row(X, row0 + wg_tid, nr, hi_path, tmem + TM_A0 + a_off);
    }

    int i = 0;
    for (; t < NT; t += GRID_PERS, i++) {
        const int paper = (t < NT_P);
        const int row0  = (paper ? t : t - NT_P) * 128;
        const int nr    = paper ? NP : NA;
        const uint32_t abuf = (i & 1) ? TM_A1 : TM_A0;

        __syncthreads();

        if (w == 0 && elect1()) {
            TC_FENCE_AFTER();
            uint32_t ah = tmem + abuf, al = tmem + abuf + 64;
            if (paper) {
                issue_3pass(tmem + TM_D1, ah, al, dSh, dSl, IDESC_BF16_128);
                issue_3pass(tmem + TM_D2, ah, al, dCh, dCl, IDESC_BF16_128);
            } else {
                issue_3pass(tmem + TM_D1, ah, al, dWh, dWl, IDESC_BF16_128);
            }
            TC_COMMIT(sb + M_MBAR);
        }

        int tn = t + GRID_PERS;
        if (tn < NT) {
            int paper_n = (tn < NT_P);
            const float* Xn = paper_n ? xp : xa;
            int nrn   = paper_n ? NP : NA;
            int row0n = (paper_n ? tn : tn - NT_P) * 128;
            uint32_t abufn = (i & 1) ? TM_A0 : TM_A1;
            store_a_row(Xn, row0n + wg_tid, nrn, hi_path,
                        tmem + abufn + a_off);
        }

        MBAR_WAIT(sb + M_MBAR, i & 1);
        TC_FENCE_AFTER();

        {
            const uint32_t c0 = (uint32_t)(w >> 2) * 64;
            const int gr = row0 + (w & 3) * 32 + lane;
            uint32_t d[64];

            LDTM_X32(d, tmem + TM_D1 + c0);
            LDTM_X32(d + 32, tmem + TM_D1 + c0 + 32);
            TC_WAIT_LD();
            if (gr < nr) {
                float* Y1 = paper ? out : Hw;
                float4* yp = (float4*)(Y1 + (size_t)gr * DIM + c0);
                #pragma unroll
                for (int j = 0; j < 16; j++)
                    yp[j] = make_float4(__uint_as_float(d[4 * j + 0]),
                                        __uint_as_float(d[4 * j + 1]),
                                        __uint_as_float(d[4 * j + 2]),
                                        __uint_as_float(d[4 * j + 3]));
            }

            if (paper) {
                LDTM_X32(d, tmem + TM_D2 + c0);
                LDTM_X32(d + 32, tmem + TM_D2 + c0 + 32);
                TC_WAIT_LD();
                if (gr < nr) {
                    float4* yp = (float4*)(Hc + (size_t)gr * DIM + c0);
                    #pragma unroll
                    for (int j = 0; j < 16; j++)
                        yp[j] = make_float4(__uint_as_float(d[4 * j + 0]),
                                            __uint_as_float(d[4 * j + 1]),
                                            __uint_as_float(d[4 * j + 2]),
                                            __uint_as_float(d[4 * j + 3]));
                }
            }
            TC_FENCE_BEFORE();
        }
    }

    __syncthreads();
    if (tid == 0) MBAR_INVAL(sb + M_MBAR);
    __syncthreads();
    if (w == 0) TC_DEALLOC(tmem, 512);
#else
    // -------- SIMT fallback (non-'a' PTX target only; never runs on GB300) --
    (void)smem;
    for (int t = blockIdx.x; t < NT; t += GRID_PERS) {
        const int paper = (t < NT_P);
        const int row0  = (paper ? t : t - NT_P) * 128;
        const int nr    = paper ? NP : NA;
        const float* X  = paper ? xp : xa;
        const int nw    = paper ? 2 : 1;
        for (int m = 0; m < nw; m++) {
            const float* Wf = paper ? (m ? Wc_f : Ws_f) : Ww_f;
            float* Y = paper ? (m ? g_Hc : out) : g_Hw;
            float acc[16][4];
            #pragma unroll
            for (int r = 0; r < 16; r++)
                acc[r][0] = acc[r][1] = acc[r][2] = acc[r][3] = 0.f;
            for (int k4 = 0; k4 < 32; k4++) {
                float4 w0 = __ldg((const float4*)(Wf + (k4 * 4 + 0) * DIM) + lane);
                float4 w1 = __ldg((const float4*)(Wf + (k4 * 4 + 1) * DIM) + lane);
                float4 w2 = __ldg((const float4*)(Wf + (k4 * 4 + 2) * DIM) + lane);
                float4 w3 = __ldg((const float4*)(Wf + (k4 * 4 + 3) * DIM) + lane);
                for (int r = 0; r < 16; r++) {
                    int gr = row0 + w + 8 * r;
                    float4 xv = (gr < nr)
                        ? __ldg((const float4*)(X + (size_t)gr * DIM) + k4)
                        : make_float4(0.f, 0.f, 0.f, 0.f);
                    acc[r][0] += xv.x * w0.x + xv.y * w1.x + xv.z * w2.x + xv.w * w3.x;
                    acc[r][1] += xv.x * w0.y + xv.y * w1.y + xv.z * w2.y + xv.w * w3.y;
                    acc[r][2] += xv.x * w0.z + xv.y * w1.z + xv.z * w2.z + xv.w * w3.z;
                    acc[r][3] += xv.x * w0.w + xv.y * w1.w + xv.z * w2.w + xv.w * w3.w;
                }
            }
            #pragma unroll
            for (int r = 0; r < 16; r++) {
                int gr = row0 + w + 8 * r;
                if (gr < nr)
                    ((float4*)(Y + (size_t)gr * DIM))[lane] =
                        make_float4(acc[r][0], acc[r][1], acc[r][2], acc[r][3]);
            }
        }
    }
#endif
}

// ---------------------------------------------------------------------------
extern "C" void kernel_launch(void* const* d_in, const int* in_sizes, int n_in,
                              void* d_out, int out_size)
{
    const float* x_paper    = (const float*)d_in[0];
    const float* x_author   = (const float*)d_in[1];
    const float* W_cites    = (const float*)d_in[2];
    const float* W_writes   = (const float*)d_in[3];
    const float* W_self     = (const float*)d_in[4];
    const float* bias       = (const float*)d_in[5];
    const int*   cites_src  = (const int*)d_in[6];
    const int*   cites_dst  = (const int*)d_in[7];
    const int*   writes_src = (const int*)d_in[8];
    const int*   writes_dst = (const int*)d_in[9];
    float*       out        = (float*)d_out;

    cudaFuncSetAttribute(gemm_mega_kernel,
                         cudaFuncAttributeMaxDynamicSharedMemorySize, M_TOTAL);

    void *pHc = nullptr, *pHw = nullptr;
    cudaGetSymbolAddress(&pHc, g_Hc);
    cudaGetSymbolAddress(&pHw, g_Hw);

    // Fork a side stream for the CSR chain (graph-capture-legal fork/join).
    cudaStream_t s2;
    cudaStreamCreateWithFlags(&s2, cudaStreamNonBlocking);
    cudaEvent_t ev_fork, ev_join;
    cudaEventCreateWithFlags(&ev_fork, cudaEventDisableTiming);
    cudaEventCreateWithFlags(&ev_join, cudaEventDisableTiming);

    cudaEventRecord(ev_fork, 0);
    cudaStreamWaitEvent(s2, ev_fork, 0);

    // --- side stream: CSR build (independent of GEMM) ---
    zero_cnt_kernel<<<NBLK, 256, 0, s2>>>();
    hist_kernel<<<(E2 + 255) / 256, 256, 0, s2>>>(cites_dst, writes_dst);
    scan_a_kernel<<<NBLK, 256, 0, s2>>>();
    scan_b_kernel<<<1, 512, 0, s2>>>();
    scan_c_kernel<<<NBLK, 256, 0, s2>>>();
    fill_kernel<<<(E2 + 255) / 256, 256, 0, s2>>>(cites_src, cites_dst,
                                                  writes_src, writes_dst);
    cudaEventRecord(ev_join, s2);

    // --- main stream: W images + persistent pipelined GEMM ---
    wconv_kernel<<<(3 * DIM * DIM + 255) / 256, 256>>>(W_cites, W_writes, W_self);
    gemm_mega_kernel<<<GRID_PERS, 256, M_TOTAL>>>(
        x_paper, x_author, W_cites, W_writes, W_self,
        out, (float*)pHc, (float*)pHw);

    // join: aggregate needs both chains
    cudaStreamWaitEvent(0, ev_join, 0);
    aggregate_kernel<<<(NP * 32 + 255) / 256, 256>>>(out, bias);

    cudaEventDestroy(ev_fork);
    cudaEventDestroy(ev_join);
    cudaStreamDestroy(s2);
}

// round 10
// speedup vs baseline: 2.8083x; 1.0747x over previous
#include <cuda_runtime.h>
#include <cuda_bf16.h>
#include <cstdint>

#define NP 100000
#define NA 50000
#define DIM 128
#define EE  500000
#define E2  (2 * EE)

#define NT_P 782            // ceil(NP/128) paper tiles
#define NT_A 391            // ceil(NA/128) author tiles
#define NT   (NT_P + NT_A)  // 1173
#define GRID_PERS 152       // GB300 SM count

#define NBLK 391            // ceil(NP/256) scan blocks

#if defined(__CUDA_ARCH__) && defined(__CUDA_ARCH_FEAT_SM103_ALL)
#define USE_TC 1
#else
#define USE_TC 0
#endif

// ---------------------------------------------------------------------------
// Scratch (allocation-guard-safe __device__ globals)
__device__ float g_Hc[(size_t)NP * DIM];          // x_paper  @ W_cites
__device__ float g_Hw[(size_t)NA * DIM];          // x_author @ W_writes
__device__ __nv_bfloat16 g_WT[3][2][DIM * DIM];   // pre-swizzled B images
// CSR-by-dst machinery
__device__ int g_cnt[NP];
__device__ int g_off[NP];
__device__ int g_cur[NP];
__device__ int g_bsum[NBLK + 1];
__device__ int g_boff[NBLK + 1];
__device__ unsigned g_esrc[E2];                   // src | (rel<<31), grouped by dst

// ---------------------------------------------------------------------------
// Swizzled byte offset of element (r,k) in a 128x128 bf16 K-major blocked-atom
// tile (for B operand images).
__device__ __forceinline__ uint32_t bf16_off(int r, int k) {
    uint32_t b = (uint32_t)(((r >> 3) + (k >> 6) * 16) * 1024
                            + (r & 7) * 128 + (k & 63) * 2);
    return b ^ ((b >> 3) & 0x70);
}

#if USE_TC
// ---------------------------------------------------------------------------
// PTX helpers (sm_103a tcgen05, cg1) — only on the 'a' target.
__device__ __forceinline__ uint32_t s2u(const void* p) {
    uint32_t a;
    asm("{ .reg .u64 t; cvta.to.shared.u64 t, %1; cvt.u32.u64 %0, t; }"
        : "=r"(a) : "l"(p));
    return a;
}
__device__ __forceinline__ bool elect1() {
    uint32_t p;
    asm volatile("{ .reg .pred p; elect.sync _|p, 0xFFFFFFFF; selp.b32 %0,1,0,p; }"
                 : "=r"(p));
    return p != 0;
}
// TS form: A in TMEM, B in SMEM
__device__ __forceinline__ void mma_bf16_ts(uint32_t d, uint32_t a, uint64_t b,
                                            uint32_t idesc, uint32_t en) {
    asm volatile(
        "{\n\t.reg .pred p;\n\tsetp.ne.u32 p, %4, 0;\n\t"
        "tcgen05.mma.cta_group::1.kind::f16 [%0], [%1], %2, %3, {%5,%5,%5,%5}, p;\n\t}"
        :: "r"(d), "r"(a), "l"(b), "r"(idesc), "r"(en), "r"(0u) : "memory");
}
#define TC_ALLOC(sa, n)  asm volatile("tcgen05.alloc.cta_group::1.sync.aligned.shared::cta.b32 [%0], %1;" :: "r"(sa), "r"(n) : "memory")
#define TC_DEALLOC(t, n) asm volatile("tcgen05.dealloc.cta_group::1.sync.aligned.b32 %0, %1;" :: "r"(t), "r"(n))
#define TC_RELINQ()      asm volatile("tcgen05.relinquish_alloc_permit.cta_group::1.sync.aligned;")
#define TC_COMMIT(mb)    asm volatile("tcgen05.commit.cta_group::1.mbarrier::arrive::one.shared::cluster.b64 [%0];" :: "r"(mb) : "memory")
#define TC_WAIT_LD()     asm volatile("tcgen05.wait::ld.sync.aligned;" ::: "memory")
#define TC_WAIT_ST()     asm volatile("tcgen05.wait::st.sync.aligned;" ::: "memory")
#define TC_FENCE_BEFORE() asm volatile("tcgen05.fence::before_thread_sync;" ::: "memory")
#define TC_FENCE_AFTER()  asm volatile("tcgen05.fence::after_thread_sync;" ::: "memory")
#define MBAR_INIT(mb, c) asm volatile("mbarrier.init.shared.b64 [%0], %1;" :: "r"(mb), "r"(c) : "memory")
#define MBAR_INVAL(mb)   asm volatile("mbarrier.inval.shared.b64 [%0];" :: "r"(mb) : "memory")
#define MBAR_WAIT(mb, ph) do {                                                      \
    uint32_t _m = (mb), _p = (ph), _d;                                              \
    asm volatile("{ .reg .pred p; mbarrier.try_wait.parity.acquire.cta.shared::cta.b64 p, [%1], %2; selp.b32 %0,1,0,p; }" \
                 : "=r"(_d) : "r"(_m), "r"(_p) : "memory");                         \
    if (!_d) {                                                                      \
        asm volatile("{ .reg .pred P1; WL_%=: mbarrier.try_wait.parity.acquire.cta.shared::cta.b64 P1, [%0], %1, 0x989680; @P1 bra.uni WD_%=; bra.uni WL_%=; WD_%=: }" \
                     :: "r"(_m), "r"(_p) : "memory");                               \
    }                                                                               \
} while (0)
#define LDTM_X32(r, a)                                                              \
    asm volatile("tcgen05.ld.sync.aligned.32x32b.x32.b32 "                          \
        "{%0,%1,%2,%3,%4,%5,%6,%7,%8,%9,%10,%11,%12,%13,%14,%15,"                   \
        "%16,%17,%18,%19,%20,%21,%22,%23,%24,%25,%26,%27,%28,%29,%30,%31}, [%32];"  \
        : "=r"((r)[0]),"=r"((r)[1]),"=r"((r)[2]),"=r"((r)[3]),                      \
          "=r"((r)[4]),"=r"((r)[5]),"=r"((r)[6]),"=r"((r)[7]),                      \
          "=r"((r)[8]),"=r"((r)[9]),"=r"((r)[10]),"=r"((r)[11]),                    \
          "=r"((r)[12]),"=r"((r)[13]),"=r"((r)[14]),"=r"((r)[15]),                  \
          "=r"((r)[16]),"=r"((r)[17]),"=r"((r)[18]),"=r"((r)[19]),                  \
          "=r"((r)[20]),"=r"((r)[21]),"=r"((r)[22]),"=r"((r)[23]),                  \
          "=r"((r)[24]),"=r"((r)[25]),"=r"((r)[26]),"=r"((r)[27]),                  \
          "=r"((r)[28]),"=r"((r)[29]),"=r"((r)[30]),"=r"((r)[31])                   \
        : "r"(a))
#define STTM_X16(a, r)                                                              \
    asm volatile("tcgen05.st.sync.aligned.32x32b.x16.b32 [%0], "                    \
        "{%1,%2,%3,%4,%5,%6,%7,%8,%9,%10,%11,%12,%13,%14,%15,%16};"                 \
        :: "r"(a),                                                                  \
           "r"((r)[0]),"r"((r)[1]),"r"((r)[2]),"r"((r)[3]),                         \
           "r"((r)[4]),"r"((r)[5]),"r"((r)[6]),"r"((r)[7]),                         \
           "r"((r)[8]),"r"((r)[9]),"r"((r)[10]),"r"((r)[11]),                       \
           "r"((r)[12]),"r"((r)[13]),"r"((r)[14]),"r"((r)[15])                      \
        : "memory")

// SMEM descriptor: SW128, version=1(Blackwell), LBO=1, SBO=64 (K-major)
static __device__ __forceinline__ uint64_t smem_desc(uint32_t addr) {
    const uint64_t base = (uint64_t(2) << 61) | (uint64_t(1) << 46)
                        | (uint64_t(64) << 32) | (uint64_t(1) << 16);
    return base | ((uint64_t)(addr >> 4) & 0x3FFF);
}

__device__ __forceinline__ uint32_t cvt_pair(float a0, float a1, int hi_path) {
    __nv_bfloat16 h0 = __float2bfloat16(a0);
    __nv_bfloat16 h1 = __float2bfloat16(a1);
    if (!hi_path) {
        h0 = __float2bfloat16(a0 - __bfloat162float(h0));
        h1 = __float2bfloat16(a1 - __bfloat162float(h1));
    }
    __nv_bfloat162 p = __halves2bfloat162(h0, h1);
    return *(uint32_t*)&p;
}

// Staged A load: coalesced LDG -> swizzled STS(f32) -> per-row LDS ->
// bf16 hi/lo convert -> STTM. Two 64-row chunks through sbuf (32KB).
// sbuf layout: row r (0..63) at r*512, float4 j at group g = j ^ (r&31).
__device__ __forceinline__ void load_a_staged(
    const float* __restrict__ X, int row0, int n_rows, uint32_t abase_tm,
    char* sbuf, int tid, int w, int lane)
{
    #pragma unroll
    for (int c = 0; c < 2; c++) {
        // coalesced global -> swizzled smem (f32)
        #pragma unroll
        for (int k = 0; k < 8; k++) {
            int i = tid + k * 256;               // 0..2047 float4
            int r = i >> 5, j = i & 31;
            int gr = row0 + c * 64 + r;
            float4 v = (gr < n_rows)
                ? __ldg((const float4*)(X + (size_t)gr * DIM) + j)
                : make_float4(0.f, 0.f, 0.f, 0.f);
            int g = j ^ (r & 31);
            *(float4*)(sbuf + r * 512 + g * 16) = v;
        }
        __syncthreads();

        // convert + STTM: active warps have (w&3)>>1 == c
        int sub = w & 3;
        if ((sub >> 1) == c) {
            int lrow = (sub & 1) * 32 + lane;    // buffer-local row 0..63
            int hi_path = (w < 4);
            uint32_t abase = abase_tm + (hi_path ? 0u : 64u)
                           + ((uint32_t)sub << 21);
            #pragma unroll
            for (int q = 0; q < 4; q++) {
                uint32_t rr[16];
                #pragma unroll
                for (int j = 0; j < 8; j++) {
                    int col4 = q * 8 + j;
                    int g = col4 ^ (lrow & 31);
                    float4 v = *(const float4*)(sbuf + lrow * 512 + g * 16);
                    rr[2 * j]     = cvt_pair(v.x, v.y, hi_path);
                    rr[2 * j + 1] = cvt_pair(v.z, v.w, hi_path);
                }
                STTM_X16(abase + q * 16, rr);
            }
        }
        TC_WAIT_ST();
        TC_FENCE_BEFORE();
        __syncthreads();                          // buffer reuse / visibility
    }
}

// Staged D store: LDTM -> swizzled STS -> coalesced STG. Two 64-row chunks.
__device__ __forceinline__ void store_d_staged(
    float* __restrict__ Y, int row0, int n_rows, uint32_t dtm,
    char* sbuf, int tid, int w, int lane)
{
    #pragma unroll
    for (int c = 0; c < 2; c++) {
        int sub = w & 3;
        if ((sub >> 1) == c) {
            uint32_t c0 = (uint32_t)(w >> 2) * 64;
            uint32_t d[64];
            LDTM_X32(d, dtm + c0);
            LDTM_X32(d + 32, dtm + c0 + 32);
            TC_WAIT_LD();
            int lrow = (sub & 1) * 32 + lane;
            #pragma unroll
            for (int j = 0; j < 16; j++) {
                int col4 = (int)(c0 >> 2) + j;
                int g = col4 ^ (lrow & 31);
                *(float4*)(sbuf + lrow * 512 + g * 16) =
                    make_float4(__uint_as_float(d[4 * j + 0]),
                                __uint_as_float(d[4 * j + 1]),
                                __uint_as_float(d[4 * j + 2]),
                                __uint_as_float(d[4 * j + 3]));
            }
        }
        __syncthreads();

        // coalesced smem -> global
        #pragma unroll
        for (int k = 0; k < 8; k++) {
            int i = tid + k * 256;
            int r = i >> 5, j = i & 31;
            int gr = row0 + c * 64 + r;
            if (gr < n_rows) {
                int g = j ^ (r & 31);
                float4 v = *(const float4*)(sbuf + r * 512 + g * 16);
                ((float4*)(Y + (size_t)gr * DIM))[j] = v;
            }
        }
        __syncthreads();
    }
}

// Issue the 3-pass bf16-split MMA chain for one (Bhi,Blo) pair into D.
__device__ __forceinline__ void issue_3pass(
    uint32_t d, uint32_t aHi, uint32_t aLo, uint64_t dBh, uint64_t dBl,
    uint32_t idesc)
{
    const int koff[8] = {0, 2, 4, 6, 1024, 1026, 1028, 1030};
    uint32_t aA[3] = {aHi, aHi, aLo};
    uint64_t pb[3] = {dBh, dBl, dBh};
    uint32_t en = 0;
    for (int p = 0; p < 3; p++)
        for (int ks = 0; ks < 8; ks++) {
            mma_bf16_ts(d, aA[p] + ks * 8, pb[p] + koff[ks], idesc, en);
            en = 1;
        }
}
#endif // USE_TC

// ---------------------------------------------------------------------------
__global__ void __launch_bounds__(256) zero_cnt_kernel() {
    int i = blockIdx.x * 256 + threadIdx.x;
    if (i < NP) g_cnt[i] = 0;
}

// ---------------------------------------------------------------------------
__global__ void __launch_bounds__(256) wconv_kernel(
    const float* __restrict__ W0, const float* __restrict__ W1,
    const float* __restrict__ W2)
{
    int i = blockIdx.x * 256 + threadIdx.x;
    if (i >= 3 * DIM * DIM) return;
    int m = i >> 14, e = i & (DIM * DIM - 1);
    const float* W = (m == 0) ? W0 : (m == 1) ? W1 : W2;
    int k = e >> 7, n = e & 127;
    float x = W[e];                                     // W[k][n]
    __nv_bfloat16 h = __float2bfloat16(x);
    __nv_bfloat16 l = __float2bfloat16(x - __bfloat162float(h));
    uint32_t o = bf16_off(n, k) >> 1;
    g_WT[m][0][o] = h;
    g_WT[m][1][o] = l;
}

// ---------------------------------------------------------------------------
// CSR build: histogram, 3-step scan, fill.
__global__ void __launch_bounds__(256) hist_kernel(
    const int* __restrict__ c_dst, const int* __restrict__ w_dst)
{
    int e = blockIdx.x * 256 + threadIdx.x;
    if (e >= E2) return;
    int d = (e < EE) ? __ldg(c_dst + e) : __ldg(w_dst + e - EE);
    atomicAdd(&g_cnt[d], 1);
}

__global__ void __launch_bounds__(256) scan_a_kernel() {
    __shared__ int sm[256];
    int b = blockIdx.x, t = threadIdx.x;
    int i = b * 256 + t;
    int v = (i < NP) ? g_cnt[i] : 0;
    sm[t] = v;
    __syncthreads();
    int acc = v;
    #pragma unroll
    for (int s = 1; s < 256; s <<= 1) {
        int add = (t >= s) ? sm[t - s] : 0;
        __syncthreads();
        acc += add;
        sm[t] = acc;
        __syncthreads();
    }
    if (i < NP) g_off[i] = acc - v;
    if (t == 255) g_bsum[b] = acc;
}

__global__ void __launch_bounds__(512) scan_b_kernel() {
    __shared__ int sm[512];
    int t = threadIdx.x;
    int v = (t < NBLK) ? g_bsum[t] : 0;
    sm[t] = v;
    __syncthreads();
    int acc = v;
    #pragma unroll
    for (int s = 1; s < 512; s <<= 1) {
        int add = (t >= s) ? sm[t - s] : 0;
        __syncthreads();
        acc += add;
        sm[t] = acc;
        __syncthreads();
    }
    if (t < NBLK) g_boff[t] = acc - v;
}

__global__ void __launch_bounds__(256) scan_c_kernel() {
    int b = blockIdx.x, t = threadIdx.x;
    int i = b * 256 + t;
    if (i < NP) {
        int o = g_off[i] + g_boff[b];
        g_off[i] = o;
        g_cur[i] = o;
    }
}

__global__ void __launch_bounds__(256) fill_kernel(
    const int* __restrict__ c_src, const int* __restrict__ c_dst,
    const int* __restrict__ w_src, const int* __restrict__ w_dst)
{
    int e = blockIdx.x * 256 + threadIdx.x;
    if (e >= E2) return;
    int d;
    unsigned sv;
    if (e < EE) {
        d = __ldg(c_dst + e);
        sv = (unsigned)__ldg(c_src + e);
    } else {
        d = __ldg(w_dst + e - EE);
        sv = (unsigned)__ldg(w_src + e - EE) | 0x80000000u;
    }
    int pos = atomicAdd(&g_cur[d], 1);
    g_esrc[pos] = sv;
}

// ---------------------------------------------------------------------------
// Pull aggregation + fused finalize. One warp per paper node.
__global__ void __launch_bounds__(256) aggregate_kernel(
    float* __restrict__ out, const float* __restrict__ bias)
{
    int d    = (blockIdx.x * 256 + threadIdx.x) >> 5;
    int lane = threadIdx.x & 31;
    if (d >= NP) return;

    const int n    = g_cnt[d];
    const int base = g_off[d];

    float4 acc = make_float4(0.f, 0.f, 0.f, 0.f);
    int j = 0;
    for (; j + 2 <= n; j += 2) {
        unsigned s0 = __ldg(&g_esrc[base + j]);
        unsigned s1 = __ldg(&g_esrc[base + j + 1]);
        const float* H0 = (s0 & 0x80000000u) ? g_Hw : g_Hc;
        const float* H1 = (s1 & 0x80000000u) ? g_Hw : g_Hc;
        float4 v0 = ((const float4*)(H0 + (size_t)(s0 & 0x7FFFFFFFu) * DIM))[lane];
        float4 v1 = ((const float4*)(H1 + (size_t)(s1 & 0x7FFFFFFFu) * DIM))[lane];
        acc.x += v0.x + v1.x;
        acc.y += v0.y + v1.y;
        acc.z += v0.z + v1.z;
        acc.w += v0.w + v1.w;
    }
    if (j < n) {
        unsigned s0 = __ldg(&g_esrc[base + j]);
        const float* H0 = (s0 & 0x80000000u) ? g_Hw : g_Hc;
        float4 v0 = ((const float4*)(H0 + (size_t)(s0 & 0x7FFFFFFFu) * DIM))[lane];
        acc.x += v0.x; acc.y += v0.y; acc.z += v0.z; acc.w += v0.w;
    }

    const float inv = 1.0f / (float)(n + 1);
    float4* op = (float4*)(out + (size_t)d * DIM) + lane;
    float4 self = *op;
    float4 b = ((const float4*)bias)[lane];
    float4 r;
    r.x = fmaxf(fmaf((self.x + acc.x), inv, b.x), 0.f);
    r.y = fmaxf(fmaf((self.y + acc.y), inv, b.y), 0.f);
    r.z = fmaxf(fmaf((self.z + acc.z), inv, b.z), 0.f);
    r.w = fmaxf(fmaf((self.w + acc.w), inv, b.w), 0.f);
    *op = r;
}

// ---------------------------------------------------------------------------
// idesc kind::f16: dtype=F32, atype=BF16, btype=BF16, (N/8)<<17, (M/16)<<24
#define IDESC_BF16_128 0x8200490u

// ===== Persistent mega GEMM with staged (coalesced) A-load and epilogue =====
#define M_TMEM 0
#define M_MBAR 8
#define M_B0   1024
#define SB_IMG(i) (M_B0 + (i) * 32768)
#define M_STG  (M_B0 + 6 * 32768)      // 32KB staging buffer
#define M_TOTAL (M_STG + 32768)        // 230400 <= 232448

#define TM_D1 0
#define TM_D2 128
#define TM_A0 256
#define TM_A1 384

__global__ void __launch_bounds__(256, 1) gemm_mega_kernel(
    const float* __restrict__ xp, const float* __restrict__ xa,
    const float* __restrict__ Wc_f, const float* __restrict__ Ww_f,
    const float* __restrict__ Ws_f,
    float* __restrict__ out, float* __restrict__ Hc, float* __restrict__ Hw)
{
    extern __shared__ char smem[];
    const int tid = threadIdx.x, w = tid >> 5, lane = tid & 31;

#if USE_TC
    uint32_t sb = s2u(smem);
    char* sbuf = smem + M_STG;

    if (w == 0) {
        TC_ALLOC(sb + M_TMEM, 512);
        TC_RELINQ();
    }
    if (tid == 0) MBAR_INIT(sb + M_MBAR, 1);

    // Stage 6 B images: self_h, self_l, cites_h, cites_l, writes_h, writes_l
    {
        const __nv_bfloat16* srcs[6] = {
            g_WT[2][0], g_WT[2][1], g_WT[0][0], g_WT[0][1],
            g_WT[1][0], g_WT[1][1]
        };
        #pragma unroll
        for (int m = 0; m < 6; m++)
            for (int i = tid; i < 2048; i += 256)
                ((float4*)(smem + SB_IMG(m)))[i] = ((const float4*)srcs[m])[i];
    }
    asm volatile("fence.proxy.async.shared::cta;" ::: "memory");
    __syncthreads();

    uint32_t tmem;
    asm volatile("ld.shared.b32 %0, [%1];" : "=r"(tmem) : "r"(sb + M_TMEM));

    const uint64_t dSh = smem_desc(sb + SB_IMG(0)), dSl = smem_desc(sb + SB_IMG(1));
    const uint64_t dCh = smem_desc(sb + SB_IMG(2)), dCl = smem_desc(sb + SB_IMG(3));
    const uint64_t dWh = smem_desc(sb + SB_IMG(4)), dWl = smem_desc(sb + SB_IMG(5));

    // Prologue: load A for this CTA's first tile into buffer 0
    int t = blockIdx.x;
    if (t < NT) {
        int paper = (t < NT_P);
        const float* X = paper ? xp : xa;
        int nr   = paper ? NP : NA;
        int row0 = (paper ? t : t - NT_P) * 128;
        load_a_staged(X, row0, nr, tmem + TM_A0, sbuf, tid, w, lane);
    }

    int i = 0;
    for (; t < NT; t += GRID_PERS, i++) {
        const int paper = (t < NT_P);
        const int row0  = (paper ? t : t - NT_P) * 128;
        const int nr    = paper ? NP : NA;
        const uint32_t abuf = (i & 1) ? TM_A1 : TM_A0;

        __syncthreads();   // A(t) visible; D free (epilogue t-1 done)

        if (w == 0 && elect1()) {
            TC_FENCE_AFTER();
            uint32_t ah = tmem + abuf, al = tmem + abuf + 64;
            if (paper) {
                issue_3pass(tmem + TM_D1, ah, al, dSh, dSl, IDESC_BF16_128);
                issue_3pass(tmem + TM_D2, ah, al, dCh, dCl, IDESC_BF16_128);
            } else {
                issue_3pass(tmem + TM_D1, ah, al, dWh, dWl, IDESC_BF16_128);
            }
            TC_COMMIT(sb + M_MBAR);
        }

        // Overlap: staged load of A(t+1) into the other buffer while MMA runs
        int tn = t + GRID_PERS;
        if (tn < NT) {
            int paper_n = (tn < NT_P);
            const float* Xn = paper_n ? xp : xa;
            int nrn   = paper_n ? NP : NA;
            int row0n = (paper_n ? tn : tn - NT_P) * 128;
            uint32_t abufn = (i & 1) ? TM_A0 : TM_A1;
            load_a_staged(Xn, row0n, nrn, tmem + abufn, sbuf, tid, w, lane);
        }

        MBAR_WAIT(sb + M_MBAR, i & 1);
        TC_FENCE_AFTER();

        // Staged epilogue(s)
        store_d_staged(paper ? out : Hw, row0, nr, tmem + TM_D1,
                       sbuf, tid, w, lane);
        if (paper)
            store_d_staged(Hc, row0, nr, tmem + TM_D2, sbuf, tid, w, lane);
        TC_FENCE_BEFORE();
    }

    __syncthreads();
    if (tid == 0) MBAR_INVAL(sb + M_MBAR);
    __syncthreads();
    if (w == 0) TC_DEALLOC(tmem, 512);
#else
    // -------- SIMT fallback (non-'a' PTX target only; never runs on GB300) --
    (void)smem;
    for (int t = blockIdx.x; t < NT; t += GRID_PERS) {
        const int paper = (t < NT_P);
        const int row0  = (paper ? t : t - NT_P) * 128;
        const int nr    = paper ? NP : NA;
        const float* X  = paper ? xp : xa;
        const int nw    = paper ? 2 : 1;
        for (int m = 0; m < nw; m++) {
            const float* Wf = paper ? (m ? Wc_f : Ws_f) : Ww_f;
            float* Y = paper ? (m ? g_Hc : out) : g_Hw;
            float acc[16][4];
            #pragma unroll
            for (int r = 0; r < 16; r++)
                acc[r][0] = acc[r][1] = acc[r][2] = acc[r][3] = 0.f;
            for (int k4 = 0; k4 < 32; k4++) {
                float4 w0 = __ldg((const float4*)(Wf + (k4 * 4 + 0) * DIM) + lane);
                float4 w1 = __ldg((const float4*)(Wf + (k4 * 4 + 1) * DIM) + lane);
                float4 w2 = __ldg((const float4*)(Wf + (k4 * 4 + 2) * DIM) + lane);
                float4 w3 = __ldg((const float4*)(Wf + (k4 * 4 + 3) * DIM) + lane);
                for (int r = 0; r < 16; r++) {
                    int gr = row0 + w + 8 * r;
                    float4 xv = (gr < nr)
                        ? __ldg((const float4*)(X + (size_t)gr * DIM) + k4)
                        : make_float4(0.f, 0.f, 0.f, 0.f);
                    acc[r][0] += xv.x * w0.x + xv.y * w1.x + xv.z * w2.x + xv.w * w3.x;
                    acc[r][1] += xv.x * w0.y + xv.y * w1.y + xv.z * w2.y + xv.w * w3.y;
                    acc[r][2] += xv.x * w0.z + xv.y * w1.z + xv.z * w2.z + xv.w * w3.z;
                    acc[r][3] += xv.x * w0.w + xv.y * w1.w + xv.z * w2.w + xv.w * w3.w;
                }
            }
            #pragma unroll
            for (int r = 0; r < 16; r++) {
                int gr = row0 + w + 8 * r;
                if (gr < nr)
                    ((float4*)(Y + (size_t)gr * DIM))[lane] =
                        make_float4(acc[r][0], acc[r][1], acc[r][2], acc[r][3]);
            }
        }
    }
#endif
}

// ---------------------------------------------------------------------------
extern "C" void kernel_launch(void* const* d_in, const int* in_sizes, int n_in,
                              void* d_out, int out_size)
{
    const float* x_paper    = (const float*)d_in[0];
    const float* x_author   = (const float*)d_in[1];
    const float* W_cites    = (const float*)d_in[2];
    const float* W_writes   = (const float*)d_in[3];
    const float* W_self     = (const float*)d_in[4];
    const float* bias       = (const float*)d_in[5];
    const int*   cites_src  = (const int*)d_in[6];
    const int*   cites_dst  = (const int*)d_in[7];
    const int*   writes_src = (const int*)d_in[8];
    const int*   writes_dst = (const int*)d_in[9];
    float*       out        = (float*)d_out;

    cudaFuncSetAttribute(gemm_mega_kernel,
                         cudaFuncAttributeMaxDynamicSharedMemorySize, M_TOTAL);

    void *pHc = nullptr, *pHw = nullptr;
    cudaGetSymbolAddress(&pHc, g_Hc);
    cudaGetSymbolAddress(&pHw, g_Hw);

    // Fork a side stream for the CSR chain (graph-capture-legal fork/join).
    cudaStream_t s2;
    cudaStreamCreateWithFlags(&s2, cudaStreamNonBlocking);
    cudaEvent_t ev_fork, ev_join;
    cudaEventCreateWithFlags(&ev_fork, cudaEventDisableTiming);
    cudaEventCreateWithFlags(&ev_join, cudaEventDisableTiming);

    cudaEventRecord(ev_fork, 0);
    cudaStreamWaitEvent(s2, ev_fork, 0);

    // --- side stream: CSR build ---
    zero_cnt_kernel<<<NBLK, 256, 0, s2>>>();
    hist_kernel<<<(E2 + 255) / 256, 256, 0, s2>>>(cites_dst, writes_dst);
    scan_a_kernel<<<NBLK, 256, 0, s2>>>();
    scan_b_kernel<<<1, 512, 0, s2>>>();
    scan_c_kernel<<<NBLK, 256, 0, s2>>>();
    fill_kernel<<<(E2 + 255) / 256, 256, 0, s2>>>(cites_src, cites_dst,
                                                  writes_src, writes_dst);
    cudaEventRecord(ev_join, s2);

    // --- main stream: W images + persistent pipelined GEMM ---
    wconv_kernel<<<(3 * DIM * DIM + 255) / 256, 256>>>(W_cites, W_writes, W_self);
    gemm_mega_kernel<<<GRID_PERS, 256, M_TOTAL>>>(
        x_paper, x_author, W_cites, W_writes, W_self,
        out, (float*)pHc, (float*)pHw);

    // join: aggregate needs both chains
    cudaStreamWaitEvent(0, ev_join, 0);
    aggregate_kernel<<<(NP * 32 + 255) / 256, 256>>>(out, bias);

    cudaEventDestroy(ev_fork);
    cudaEventDestroy(ev_join);
    cudaStreamDestroy(s2);
}

// round 11
// speedup vs baseline: 3.0834x; 1.0979x over previous
#include <cuda_runtime.h>
#include <cuda_bf16.h>
#include <cstdint>

#define NP 100000
#define NA 50000
#define DIM 128
#define EE  500000
#define E2  (2 * EE)

#define NT_P 782            // ceil(NP/128) paper tiles
#define NT_A 391            // ceil(NA/128) author tiles
#define NT   (NT_P + NT_A)
#define NCTA_P 117          // paper CTAs
#define NCTA_A 35           // author CTAs
#define GRID_PERS (NCTA_P + NCTA_A)   // 152 = GB300 SM count

#define NBLK 391            // ceil(NP/256) scan blocks

#if defined(__CUDA_ARCH__) && defined(__CUDA_ARCH_FEAT_SM103_ALL)
#define USE_TC 1
#else
#define USE_TC 0
#endif

// ---------------------------------------------------------------------------
// Scratch (allocation-guard-safe __device__ globals)
__device__ float g_Hc[(size_t)NP * DIM];          // x_paper  @ W_cites
__device__ float g_Hw[(size_t)NA * DIM];          // x_author @ W_writes
__device__ float g_Wf[3][DIM * DIM];              // swizzled f32 W^T images:
                                                  // [0]=cites [1]=writes [2]=self
// CSR-by-dst machinery
__device__ int g_cnt[NP];
__device__ int g_off[NP];
__device__ int g_cur[NP];
__device__ int g_bsum[NBLK + 1];
__device__ int g_boff[NBLK + 1];
__device__ unsigned g_esrc[E2];                   // src | (rel<<31), grouped by dst

// ---------------------------------------------------------------------------
// Swizzled byte offset of f32 element (r,k) in a 128x128 f32 K-major
// blocked-atom tile: atom = 8 rows x 32 f32 (1024B), 16 atom-rows x 4
// atom-cols, atom_offset = atom_row + atom_col*16. SW128 swizzle on top.
__device__ __forceinline__ uint32_t f32_off(int r, int k) {
    uint32_t b = (uint32_t)(((r >> 3) + (k >> 5) * 16) * 1024
                            + (r & 7) * 128 + (k & 31) * 4);
    return b ^ ((b >> 3) & 0x70);
}

#if USE_TC
// ---------------------------------------------------------------------------
// PTX helpers (sm_103a tcgen05, cg1) — only on the 'a' target.
__device__ __forceinline__ uint32_t s2u(const void* p) {
    uint32_t a;
    asm("{ .reg .u64 t; cvta.to.shared.u64 t, %1; cvt.u32.u64 %0, t; }"
        : "=r"(a) : "l"(p));
    return a;
}
__device__ __forceinline__ bool elect1() {
    uint32_t p;
    asm volatile("{ .reg .pred p; elect.sync _|p, 0xFFFFFFFF; selp.b32 %0,1,0,p; }"
                 : "=r"(p));
    return p != 0;
}
// idesc kind::tf32: dtype=F32(1<<4), atype=TF32(2<<7), btype=TF32(2<<10),
// (N/8)<<17, (M/16)<<24  -> M=128, N=128
#define IDESC_TF32_128 0x8200910u

// SS form, kind::tf32
__device__ __forceinline__ void mma_tf32_ss(uint32_t d, uint64_t a, uint64_t b,
                                            uint32_t en) {
    asm volatile(
        "{\n\t.reg .pred p;\n\tsetp.ne.u32 p, %4, 0;\n\t"
        "tcgen05.mma.cta_group::1.kind::tf32 [%0], %1, %2, %3, {%5,%5,%5,%5}, p;\n\t}"
        :: "r"(d), "l"(a), "l"(b), "r"(IDESC_TF32_128), "r"(en), "r"(0u)
        : "memory");
}
#define TC_ALLOC(sa, n)  asm volatile("tcgen05.alloc.cta_group::1.sync.aligned.shared::cta.b32 [%0], %1;" :: "r"(sa), "r"(n) : "memory")
#define TC_DEALLOC(t, n) asm volatile("tcgen05.dealloc.cta_group::1.sync.aligned.b32 %0, %1;" :: "r"(t), "r"(n))
#define TC_RELINQ()      asm volatile("tcgen05.relinquish_alloc_permit.cta_group::1.sync.aligned;")
#define TC_COMMIT(mb)    asm volatile("tcgen05.commit.cta_group::1.mbarrier::arrive::one.shared::cluster.b64 [%0];" :: "r"(mb) : "memory")
#define TC_WAIT_LD()     asm volatile("tcgen05.wait::ld.sync.aligned;" ::: "memory")
#define TC_FENCE_BEFORE() asm volatile("tcgen05.fence::before_thread_sync;" ::: "memory")
#define TC_FENCE_AFTER()  asm volatile("tcgen05.fence::after_thread_sync;" ::: "memory")
#define MBAR_INIT(mb, c) asm volatile("mbarrier.init.shared.b64 [%0], %1;" :: "r"(mb), "r"(c) : "memory")
#define MBAR_INVAL(mb)   asm volatile("mbarrier.inval.shared.b64 [%0];" :: "r"(mb) : "memory")
#define MBAR_WAIT(mb, ph) do {                                                      \
    uint32_t _m = (mb), _p = (ph), _d;                                              \
    asm volatile("{ .reg .pred p; mbarrier.try_wait.parity.acquire.cta.shared::cta.b64 p, [%1], %2; selp.b32 %0,1,0,p; }" \
                 : "=r"(_d) : "r"(_m), "r"(_p) : "memory");                         \
    if (!_d) {                                                                      \
        asm volatile("{ .reg .pred P1; WL_%=: mbarrier.try_wait.parity.acquire.cta.shared::cta.b64 P1, [%0], %1, 0x989680; @P1 bra.uni WD_%=; bra.uni WL_%=; WD_%=: }" \
                     :: "r"(_m), "r"(_p) : "memory");                               \
    }                                                                               \
} while (0)
#define LDTM_X32(r, a)                                                              \
    asm volatile("tcgen05.ld.sync.aligned.32x32b.x32.b32 "                          \
        "{%0,%1,%2,%3,%4,%5,%6,%7,%8,%9,%10,%11,%12,%13,%14,%15,"                   \
        "%16,%17,%18,%19,%20,%21,%22,%23,%24,%25,%26,%27,%28,%29,%30,%31}, [%32];"  \
        : "=r"((r)[0]),"=r"((r)[1]),"=r"((r)[2]),"=r"((r)[3]),                      \
          "=r"((r)[4]),"=r"((r)[5]),"=r"((r)[6]),"=r"((r)[7]),                      \
          "=r"((r)[8]),"=r"((r)[9]),"=r"((r)[10]),"=r"((r)[11]),                    \
          "=r"((r)[12]),"=r"((r)[13]),"=r"((r)[14]),"=r"((r)[15]),                  \
          "=r"((r)[16]),"=r"((r)[17]),"=r"((r)[18]),"=r"((r)[19]),                  \
          "=r"((r)[20]),"=r"((r)[21]),"=r"((r)[22]),"=r"((r)[23]),                  \
          "=r"((r)[24]),"=r"((r)[25]),"=r"((r)[26]),"=r"((r)[27]),                  \
          "=r"((r)[28]),"=r"((r)[29]),"=r"((r)[30]),"=r"((r)[31])                   \
        : "r"(a))

// SMEM descriptor: SW128, version=1(Blackwell), LBO=1, SBO=64 (K-major)
static __device__ __forceinline__ uint64_t smem_desc(uint32_t addr) {
    const uint64_t base = (uint64_t(2) << 61) | (uint64_t(1) << 46)
                        | (uint64_t(64) << 32) | (uint64_t(1) << 16);
    return base | ((uint64_t)(addr >> 4) & 0x3FFF);
}

// Full 128x128 K=128 tf32 gemm into D: 16 K-steps of K=8.
// Desc offset per step = 32B = 2 units; per atom-col (4 steps) jump 1024 units.
__device__ __forceinline__ void issue_tf32(uint32_t d, uint64_t da, uint64_t db) {
    uint32_t en = 0;
    #pragma unroll
    for (int g = 0; g < 4; g++)
        #pragma unroll
        for (int s = 0; s < 4; s++) {
            uint64_t off = (uint64_t)(g * 1024 + s * 2);
            mma_tf32_ss(d, da + off, db + off, en);
            en = 1;
        }
}

// Coalesced LDG -> swizzled STS of one 128x128 f32 X tile into SMEM A.
__device__ __forceinline__ void copy_a(
    const float* __restrict__ X, int row0, int n_rows, char* sA, int tid)
{
    #pragma unroll
    for (int kk = 0; kk < 16; kk++) {
        int i = tid + kk * 256;              // 0..4095 float4
        int r = i >> 5, j = i & 31;
        int gr = row0 + r;
        float4 v = (gr < n_rows)
            ? __ldg((const float4*)(X + (size_t)gr * DIM) + j)
            : make_float4(0.f, 0.f, 0.f, 0.f);
        *(float4*)(sA + f32_off(r, j * 4)) = v;
    }
}

// Staged D store: LDTM -> swizzled STS -> coalesced STG. Two 64-row chunks.
// sbuf: row r at r*512, float4 j at group g = j ^ (r&31).
__device__ __forceinline__ void store_d_staged(
    float* __restrict__ Y, int row0, int n_rows, uint32_t dtm,
    char* sbuf, int tid, int w, int lane)
{
    #pragma unroll
    for (int c = 0; c < 2; c++) {
        int sub = w & 3;
        if ((sub >> 1) == c) {
            uint32_t c0 = (uint32_t)(w >> 2) * 64;
            uint32_t d[64];
            LDTM_X32(d, dtm + c0);
            LDTM_X32(d + 32, dtm + c0 + 32);
            TC_WAIT_LD();
            int lrow = (sub & 1) * 32 + lane;
            #pragma unroll
            for (int j = 0; j < 16; j++) {
                int col4 = (int)(c0 >> 2) + j;
                int g = col4 ^ (lrow & 31);
                *(float4*)(sbuf + lrow * 512 + g * 16) =
                    make_float4(__uint_as_float(d[4 * j + 0]),
                                __uint_as_float(d[4 * j + 1]),
                                __uint_as_float(d[4 * j + 2]),
                                __uint_as_float(d[4 * j + 3]));
            }
        }
        __syncthreads();

        #pragma unroll
        for (int k = 0; k < 8; k++) {
            int i = tid + k * 256;
            int r = i >> 5, j = i & 31;
            int gr = row0 + c * 64 + r;
            if (gr < n_rows) {
                int g = j ^ (r & 31);
                float4 v = *(const float4*)(sbuf + r * 512 + g * 16);
                ((float4*)(Y + (size_t)gr * DIM))[j] = v;
            }
        }
        __syncthreads();
    }
}
#endif // USE_TC

// ---------------------------------------------------------------------------
__global__ void __launch_bounds__(256) zero_cnt_kernel() {
    int i = blockIdx.x * 256 + threadIdx.x;
    if (i < NP) g_cnt[i] = 0;
}

// ---------------------------------------------------------------------------
// All three W matrices -> swizzled f32 W^T images, pre-rounded to tf32 (rna).
__global__ void __launch_bounds__(256) wconv_kernel(
    const float* __restrict__ W0, const float* __restrict__ W1,
    const float* __restrict__ W2)
{
    int i = blockIdx.x * 256 + threadIdx.x;
    if (i >= 3 * DIM * DIM) return;
    int m = i >> 14, e = i & (DIM * DIM - 1);
    const float* W = (m == 0) ? W0 : (m == 1) ? W1 : W2;
    int k = e >> 7, n = e & 127;
    float x = W[e];                                     // W[k][n]
    uint32_t xb;
#if USE_TC
    asm("cvt.rna.tf32.f32 %0, %1;" : "=r"(xb) : "f"(x));
#else
    xb = __float_as_uint(x);
#endif
    g_Wf[m][f32_off(n, k) >> 2] = __uint_as_float(xb);
}

// ---------------------------------------------------------------------------
// CSR build: histogram, 3-step scan, fill.
__global__ void __launch_bounds__(256) hist_kernel(
    const int* __restrict__ c_dst, const int* __restrict__ w_dst)
{
    int e = blockIdx.x * 256 + threadIdx.x;
    if (e >= E2) return;
    int d = (e < EE) ? __ldg(c_dst + e) : __ldg(w_dst + e - EE);
    atomicAdd(&g_cnt[d], 1);
}

__global__ void __launch_bounds__(256) scan_a_kernel() {
    __shared__ int sm[256];
    int b = blockIdx.x, t = threadIdx.x;
    int i = b * 256 + t;
    int v = (i < NP) ? g_cnt[i] : 0;
    sm[t] = v;
    __syncthreads();
    int acc = v;
    #pragma unroll
    for (int s = 1; s < 256; s <<= 1) {
        int add = (t >= s) ? sm[t - s] : 0;
        __syncthreads();
        acc += add;
        sm[t] = acc;
        __syncthreads();
    }
    if (i < NP) g_off[i] = acc - v;
    if (t == 255) g_bsum[b] = acc;
}

__global__ void __launch_bounds__(512) scan_b_kernel() {
    __shared__ int sm[512];
    int t = threadIdx.x;
    int v = (t < NBLK) ? g_bsum[t] : 0;
    sm[t] = v;
    __syncthreads();
    int acc = v;
    #pragma unroll
    for (int s = 1; s < 512; s <<= 1) {
        int add = (t >= s) ? sm[t - s] : 0;
        __syncthreads();
        acc += add;
        sm[t] = acc;
        __syncthreads();
    }
    if (t < NBLK) g_boff[t] = acc - v;
}

__global__ void __launch_bounds__(256) scan_c_kernel() {
    int b = blockIdx.x, t = threadIdx.x;
    int i = b * 256 + t;
    if (i < NP) {
        int o = g_off[i] + g_boff[b];
        g_off[i] = o;
        g_cur[i] = o;
    }
}

__global__ void __launch_bounds__(256) fill_kernel(
    const int* __restrict__ c_src, const int* __restrict__ c_dst,
    const int* __restrict__ w_src, const int* __restrict__ w_dst)
{
    int e = blockIdx.x * 256 + threadIdx.x;
    if (e >= E2) return;
    int d;
    unsigned sv;
    if (e < EE) {
        d = __ldg(c_dst + e);
        sv = (unsigned)__ldg(c_src + e);
    } else {
        d = __ldg(w_dst + e - EE);
        sv = (unsigned)__ldg(w_src + e - EE) | 0x80000000u;
    }
    int pos = atomicAdd(&g_cur[d], 1);
    g_esrc[pos] = sv;
}

// ---------------------------------------------------------------------------
// Pull aggregation + fused finalize. One warp per paper node.
__global__ void __launch_bounds__(256) aggregate_kernel(
    float* __restrict__ out, const float* __restrict__ bias)
{
    int d    = (blockIdx.x * 256 + threadIdx.x) >> 5;
    int lane = threadIdx.x & 31;
    if (d >= NP) return;

    const int n    = g_cnt[d];
    const int base = g_off[d];

    float4 acc = make_float4(0.f, 0.f, 0.f, 0.f);
    int j = 0;
    for (; j + 2 <= n; j += 2) {
        unsigned s0 = __ldg(&g_esrc[base + j]);
        unsigned s1 = __ldg(&g_esrc[base + j + 1]);
        const float* H0 = (s0 & 0x80000000u) ? g_Hw : g_Hc;
        const float* H1 = (s1 & 0x80000000u) ? g_Hw : g_Hc;
        float4 v0 = ((const float4*)(H0 + (size_t)(s0 & 0x7FFFFFFFu) * DIM))[lane];
        float4 v1 = ((const float4*)(H1 + (size_t)(s1 & 0x7FFFFFFFu) * DIM))[lane];
        acc.x += v0.x + v1.x;
        acc.y += v0.y + v1.y;
        acc.z += v0.z + v1.z;
        acc.w += v0.w + v1.w;
    }
    if (j < n) {
        unsigned s0 = __ldg(&g_esrc[base + j]);
        const float* H0 = (s0 & 0x80000000u) ? g_Hw : g_Hc;
        float4 v0 = ((const float4*)(H0 + (size_t)(s0 & 0x7FFFFFFFu) * DIM))[lane];
        acc.x += v0.x; acc.y += v0.y; acc.z += v0.z; acc.w += v0.w;
    }

    const float inv = 1.0f / (float)(n + 1);
    float4* op = (float4*)(out + (size_t)d * DIM) + lane;
    float4 self = *op;
    float4 b = ((const float4*)bias)[lane];
    float4 r;
    r.x = fmaxf(fmaf((self.x + acc.x), inv, b.x), 0.f);
    r.y = fmaxf(fmaf((self.y + acc.y), inv, b.y), 0.f);
    r.z = fmaxf(fmaf((self.z + acc.z), inv, b.z), 0.f);
    r.w = fmaxf(fmaf((self.w + acc.w), inv, b.w), 0.f);
    *op = r;
}

// ---------------------------------------------------------------------------
// ===== Persistent CTA-specialized tf32 GEMM, D double-buffered ==============
// Paper CTAs (bid < NCTA_P): B_self + B_cites resident; per tile two gemms
//   (D_self -> out, D_cites -> g_Hc). Author CTAs: B_writes; one gemm -> g_Hw.
// TMEM: slot s in {0,1}: D1 = s*256, D2 = s*256+128 (alloc 512).
// SMEM: hdr 1KB | B0 64KB | B1 64KB | A 64KB | sbuf 32KB = 230400.
#define G_MB0  8
#define G_MB1  16
#define G_B0   1024
#define G_B1   (G_B0 + 65536)
#define G_A    (G_B1 + 65536)
#define G_SB   (G_A + 65536)
#define G_TOTAL (G_SB + 32768)      // 230400 <= 232448

__global__ void __launch_bounds__(256, 1) gemm_mega_kernel(
    const float* __restrict__ xp, const float* __restrict__ xa,
    const float* __restrict__ Wc_f, const float* __restrict__ Ww_f,
    const float* __restrict__ Ws_f,
    float* __restrict__ out, float* __restrict__ Hc, float* __restrict__ Hw)
{
    extern __shared__ char smem[];
    const int tid = threadIdx.x, w = tid >> 5, lane = tid & 31;

#if USE_TC
    uint32_t sb = s2u(smem);
    char* sA   = smem + G_A;
    char* sbuf = smem + G_SB;

    if (w == 0) {
        TC_ALLOC(sb, 512);
        TC_RELINQ();
    }
    if (tid == 0) {
        MBAR_INIT(sb + G_MB0, 1);
        MBAR_INIT(sb + G_MB1, 1);
    }

    // CTA role
    const int paper = (blockIdx.x < NCTA_P);
    const float* X;
    float *Y1, *Y2;
    int t0, stride, tend, nr;
    if (paper) {
        X = xp; t0 = blockIdx.x;          stride = NCTA_P; tend = NT_P; nr = NP;
        Y1 = out; Y2 = Hc;
    } else {
        X = xa; t0 = blockIdx.x - NCTA_P; stride = NCTA_A; tend = NT_A; nr = NA;
        Y1 = Hw; Y2 = nullptr;
    }

    // Stage B images (pre-swizzled f32): paper = self(B0)+cites(B1); author = writes(B0)
    {
        const float* B0s = paper ? g_Wf[2] : g_Wf[1];
        for (int i = tid; i < 4096; i += 256)
            ((float4*)(smem + G_B0))[i] = ((const float4*)B0s)[i];
        if (paper)
            for (int i = tid; i < 4096; i += 256)
                ((float4*)(smem + G_B1))[i] = ((const float4*)g_Wf[0])[i];
    }
    asm volatile("fence.proxy.async.shared::cta;" ::: "memory");
    __syncthreads();

    uint32_t tmem;
    asm volatile("ld.shared.b32 %0, [%1];" : "=r"(tmem) : "r"(sb));

    const uint64_t dB0 = smem_desc(sb + G_B0);
    const uint64_t dB1 = smem_desc(sb + G_B1);
    const uint64_t dA  = smem_desc(sb + G_A);

    // Prologue: A(t0) + MMA into slot 0
    int t = t0;
    copy_a(X, t * 128, nr, sA, tid);
    asm volatile("fence.proxy.async.shared::cta;" ::: "memory");
    __syncthreads();
    if (w == 0 && elect1()) {
        issue_tf32(tmem + 0, dA, dB0);
        if (paper) issue_tf32(tmem + 128, dA, dB1);
        TC_COMMIT(sb + G_MB0);
    }

    int i = 0;
    for (; t < tend; t += stride, i++) {
        const int s  = i & 1;
        const int ph = (i >> 1) & 1;
        const int row0 = t * 128;

        MBAR_WAIT(sb + (s ? G_MB1 : G_MB0), ph);   // MMA(t) done: A free, D[s] full
        TC_FENCE_AFTER();

        int tn = t + stride;
        if (tn < tend) {
            copy_a(X, tn * 128, nr, sA, tid);
            asm volatile("fence.proxy.async.shared::cta;" ::: "memory");
            __syncthreads();
            if (w == 0 && elect1()) {
                uint32_t ds = (uint32_t)(s ^ 1) * 256;
                issue_tf32(tmem + ds, dA, dB0);
                if (paper) issue_tf32(tmem + ds + 128, dA, dB1);
                TC_COMMIT(sb + ((s ^ 1) ? G_MB1 : G_MB0));
            }
        }

        // Epilogue slot s (overlaps MMA(t+1))
        store_d_staged(Y1, row0, nr, tmem + (uint32_t)s * 256,
                       sbuf, tid, w, lane);
        if (paper)
            store_d_staged(Y2, row0, nr, tmem + (uint32_t)s * 256 + 128,
                           sbuf, tid, w, lane);
        TC_FENCE_BEFORE();
    }

    __syncthreads();
    if (tid == 0) {
        MBAR_INVAL(sb + G_MB0);
        MBAR_INVAL(sb + G_MB1);
    }
    __syncthreads();
    if (w == 0) TC_DEALLOC(tmem, 512);
#else
    // -------- SIMT fallback (non-'a' PTX target only; never runs on GB300) --
    (void)smem;
    for (int t = blockIdx.x; t < NT; t += GRID_PERS) {
        const int paper = (t < NT_P);
        const int row0  = (paper ? t : t - NT_P) * 128;
        const int nr    = paper ? NP : NA;
        const float* X  = paper ? xp : xa;
        const int nw    = paper ? 2 : 1;
        for (int m = 0; m < nw; m++) {
            const float* Wf = paper ? (m ? Wc_f : Ws_f) : Ww_f;
            float* Y = paper ? (m ? g_Hc : out) : g_Hw;
            float acc[16][4];
            #pragma unroll
            for (int r = 0; r < 16; r++)
                acc[r][0] = acc[r][1] = acc[r][2] = acc[r][3] = 0.f;
            for (int k4 = 0; k4 < 32; k4++) {
                float4 w0 = __ldg((const float4*)(Wf + (k4 * 4 + 0) * DIM) + lane);
                float4 w1 = __ldg((const float4*)(Wf + (k4 * 4 + 1) * DIM) + lane);
                float4 w2 = __ldg((const float4*)(Wf + (k4 * 4 + 2) * DIM) + lane);
                float4 w3 = __ldg((const float4*)(Wf + (k4 * 4 + 3) * DIM) + lane);
                for (int r = 0; r < 16; r++) {
                    int gr = row0 + w + 8 * r;
                    float4 xv = (gr < nr)
                        ? __ldg((const float4*)(X + (size_t)gr * DIM) + k4)
                        : make_float4(0.f, 0.f, 0.f, 0.f);
                    acc[r][0] += xv.x * w0.x + xv.y * w1.x + xv.z * w2.x + xv.w * w3.x;
                    acc[r][1] += xv.x * w0.y + xv.y * w1.y + xv.z * w2.y + xv.w * w3.y;
                    acc[r][2] += xv.x * w0.z + xv.y * w1.z + xv.z * w2.z + xv.w * w3.z;
                    acc[r][3] += xv.x * w0.w + xv.y * w1.w + xv.z * w2.w + xv.w * w3.w;
                }
            }
            #pragma unroll
            for (int r = 0; r < 16; r++) {
                int gr = row0 + w + 8 * r;
                if (gr < nr)
                    ((float4*)(Y + (size_t)gr * DIM))[lane] =
                        make_float4(acc[r][0], acc[r][1], acc[r][2], acc[r][3]);
            }
        }
    }
#endif
}

// ---------------------------------------------------------------------------
extern "C" void kernel_launch(void* const* d_in, const int* in_sizes, int n_in,
                              void* d_out, int out_size)
{
    const float* x_paper    = (const float*)d_in[0];
    const float* x_author   = (const float*)d_in[1];
    const float* W_cites    = (const float*)d_in[2];
    const float* W_writes   = (const float*)d_in[3];
    const float* W_self     = (const float*)d_in[4];
    const float* bias       = (const float*)d_in[5];
    const int*   cites_src  = (const int*)d_in[6];
    const int*   cites_dst  = (const int*)d_in[7];
    const int*   writes_src = (const int*)d_in[8];
    const int*   writes_dst = (const int*)d_in[9];
    float*       out        = (float*)d_out;

    cudaFuncSetAttribute(gemm_mega_kernel,
                         cudaFuncAttributeMaxDynamicSharedMemorySize, G_TOTAL);

    void *pHc = nullptr, *pHw = nullptr;
    cudaGetSymbolAddress(&pHc, g_Hc);
    cudaGetSymbolAddress(&pHw, g_Hw);

    // Fork a side stream for the CSR chain (graph-capture-legal fork/join).
    cudaStream_t s2;
    cudaStreamCreateWithFlags(&s2, cudaStreamNonBlocking);
    cudaEvent_t ev_fork, ev_join;
    cudaEventCreateWithFlags(&ev_fork, cudaEventDisableTiming);
    cudaEventCreateWithFlags(&ev_join, cudaEventDisableTiming);

    cudaEventRecord(ev_fork, 0);
    cudaStreamWaitEvent(s2, ev_fork, 0);

    // --- side stream: CSR build ---
    zero_cnt_kernel<<<NBLK, 256, 0, s2>>>();
    hist_kernel<<<(E2 + 255) / 256, 256, 0, s2>>>(cites_dst, writes_dst);
    scan_a_kernel<<<NBLK, 256, 0, s2>>>();
    scan_b_kernel<<<1, 512, 0, s2>>>();
    scan_c_kernel<<<NBLK, 256, 0, s2>>>();
    fill_kernel<<<(E2 + 255) / 256, 256, 0, s2>>>(cites_src, cites_dst,
                                                  writes_src, writes_dst);
    cudaEventRecord(ev_join, s2);

    // --- main stream: W images + persistent pipelined GEMM ---
    wconv_kernel<<<(3 * DIM * DIM + 255) / 256, 256>>>(W_cites, W_writes, W_self);
    gemm_mega_kernel<<<GRID_PERS, 256, G_TOTAL>>>(
        x_paper, x_author, W_cites, W_writes, W_self,
        out, (float*)pHc, (float*)pHw);

    // join: aggregate needs both chains
    cudaStreamWaitEvent(0, ev_join, 0);
    aggregate_kernel<<<(NP * 32 + 255) / 256, 256>>>(out, bias);

    cudaEventDestroy(ev_fork);
    cudaEventDestroy(ev_join);
    cudaStreamDestroy(s2);
}

// round 12
// speedup vs baseline: 3.4367x; 1.1146x over previous
#include <cuda_runtime.h>
#include <cuda_bf16.h>
#include <cstdint>

#define NP 100000
#define NA 50000
#define DIM 128
#define EE  500000
#define E2  (2 * EE)

#define NT_P 782            // ceil(NP/128) paper tiles
#define NT_A 391            // ceil(NA/128) author tiles
#define NT   (NT_P + NT_A)
#define NCTA_P 122          // paper CTAs (rebalanced: 12.8 work units/CTA)
#define NCTA_A 30           // author CTAs (13.0 units/CTA)
#define GRID_PERS (NCTA_P + NCTA_A)   // 152 = GB300 SM count

#define NBLK 391            // ceil(NP/256) scan blocks

#if defined(__CUDA_ARCH__) && defined(__CUDA_ARCH_FEAT_SM103_ALL)
#define USE_TC 1
#else
#define USE_TC 0
#endif

// ---------------------------------------------------------------------------
// Scratch (allocation-guard-safe __device__ globals)
__device__ float g_Hc[(size_t)NP * DIM];          // x_paper  @ W_cites
__device__ float g_Hw[(size_t)NA * DIM];          // x_author @ W_writes
__device__ float g_Wf[3][DIM * DIM];              // swizzled f32 W^T images:
                                                  // [0]=cites [1]=writes [2]=self
// CSR-by-dst machinery
__device__ int g_cnt[NP];
__device__ int g_off[NP];
__device__ int g_cur[NP];
__device__ int g_bsum[NBLK + 1];
__device__ int g_boff[NBLK + 1];
__device__ unsigned g_esrc[E2];                   // src | (rel<<31), grouped by dst

// ---------------------------------------------------------------------------
// Swizzled byte offset of f32 element (r,k) in a 128x128 f32 K-major
// blocked-atom tile: atom = 8 rows x 32 f32 (1024B), 16 atom-rows x 4
// atom-cols. SW128 swizzle on top.
__device__ __forceinline__ uint32_t f32_off(int r, int k) {
    uint32_t b = (uint32_t)(((r >> 3) + (k >> 5) * 16) * 1024
                            + (r & 7) * 128 + (k & 31) * 4);
    return b ^ ((b >> 3) & 0x70);
}

#if USE_TC
// ---------------------------------------------------------------------------
// PTX helpers (sm_103a tcgen05, cg1) — only on the 'a' target.
__device__ __forceinline__ uint32_t s2u(const void* p) {
    uint32_t a;
    asm("{ .reg .u64 t; cvta.to.shared.u64 t, %1; cvt.u32.u64 %0, t; }"
        : "=r"(a) : "l"(p));
    return a;
}
__device__ __forceinline__ bool elect1() {
    uint32_t p;
    asm volatile("{ .reg .pred p; elect.sync _|p, 0xFFFFFFFF; selp.b32 %0,1,0,p; }"
                 : "=r"(p));
    return p != 0;
}
// idesc kind::tf32: dtype=F32(1<<4), atype=TF32(2<<7), btype=TF32(2<<10),
// (N/8)<<17, (M/16)<<24  -> M=128, N=128
#define IDESC_TF32_128 0x8200910u

__device__ __forceinline__ void mma_tf32_ss(uint32_t d, uint64_t a, uint64_t b,
                                            uint32_t en) {
    asm volatile(
        "{\n\t.reg .pred p;\n\tsetp.ne.u32 p, %4, 0;\n\t"
        "tcgen05.mma.cta_group::1.kind::tf32 [%0], %1, %2, %3, {%5,%5,%5,%5}, p;\n\t}"
        :: "r"(d), "l"(a), "l"(b), "r"(IDESC_TF32_128), "r"(en), "r"(0u)
        : "memory");
}
#define TC_ALLOC(sa, n)  asm volatile("tcgen05.alloc.cta_group::1.sync.aligned.shared::cta.b32 [%0], %1;" :: "r"(sa), "r"(n) : "memory")
#define TC_DEALLOC(t, n) asm volatile("tcgen05.dealloc.cta_group::1.sync.aligned.b32 %0, %1;" :: "r"(t), "r"(n))
#define TC_RELINQ()      asm volatile("tcgen05.relinquish_alloc_permit.cta_group::1.sync.aligned;")
#define TC_COMMIT(mb)    asm volatile("tcgen05.commit.cta_group::1.mbarrier::arrive::one.shared::cluster.b64 [%0];" :: "r"(mb) : "memory")
#define TC_WAIT_LD()     asm volatile("tcgen05.wait::ld.sync.aligned;" ::: "memory")
#define TC_FENCE_BEFORE() asm volatile("tcgen05.fence::before_thread_sync;" ::: "memory")
#define TC_FENCE_AFTER()  asm volatile("tcgen05.fence::after_thread_sync;" ::: "memory")
#define MBAR_INIT(mb, c) asm volatile("mbarrier.init.shared.b64 [%0], %1;" :: "r"(mb), "r"(c) : "memory")
#define MBAR_INVAL(mb)   asm volatile("mbarrier.inval.shared.b64 [%0];" :: "r"(mb) : "memory")
#define MBAR_WAIT(mb, ph) do {                                                      \
    uint32_t _m = (mb), _p = (ph), _d;                                              \
    asm volatile("{ .reg .pred p; mbarrier.try_wait.parity.acquire.cta.shared::cta.b64 p, [%1], %2; selp.b32 %0,1,0,p; }" \
                 : "=r"(_d) : "r"(_m), "r"(_p) : "memory");                         \
    if (!_d) {                                                                      \
        asm volatile("{ .reg .pred P1; WL_%=: mbarrier.try_wait.parity.acquire.cta.shared::cta.b64 P1, [%0], %1, 0x989680; @P1 bra.uni WD_%=; bra.uni WL_%=; WD_%=: }" \
                     :: "r"(_m), "r"(_p) : "memory");                               \
    }                                                                               \
} while (0)
#define LDTM_X32(r, a)                                                              \
    asm volatile("tcgen05.ld.sync.aligned.32x32b.x32.b32 "                          \
        "{%0,%1,%2,%3,%4,%5,%6,%7,%8,%9,%10,%11,%12,%13,%14,%15,"                   \
        "%16,%17,%18,%19,%20,%21,%22,%23,%24,%25,%26,%27,%28,%29,%30,%31}, [%32];"  \
        : "=r"((r)[0]),"=r"((r)[1]),"=r"((r)[2]),"=r"((r)[3]),                      \
          "=r"((r)[4]),"=r"((r)[5]),"=r"((r)[6]),"=r"((r)[7]),                      \
          "=r"((r)[8]),"=r"((r)[9]),"=r"((r)[10]),"=r"((r)[11]),                    \
          "=r"((r)[12]),"=r"((r)[13]),"=r"((r)[14]),"=r"((r)[15]),                  \
          "=r"((r)[16]),"=r"((r)[17]),"=r"((r)[18]),"=r"((r)[19]),                  \
          "=r"((r)[20]),"=r"((r)[21]),"=r"((r)[22]),"=r"((r)[23]),                  \
          "=r"((r)[24]),"=r"((r)[25]),"=r"((r)[26]),"=r"((r)[27]),                  \
          "=r"((r)[28]),"=r"((r)[29]),"=r"((r)[30]),"=r"((r)[31])                   \
        : "r"(a))

// SMEM descriptor: SW128, version=1(Blackwell), LBO=1, SBO=64 (K-major)
static __device__ __forceinline__ uint64_t smem_desc(uint32_t addr) {
    const uint64_t base = (uint64_t(2) << 61) | (uint64_t(1) << 46)
                        | (uint64_t(64) << 32) | (uint64_t(1) << 16);
    return base | ((uint64_t)(addr >> 4) & 0x3FFF);
}

// Full 128x128 K=128 tf32 gemm into D: 16 K-steps of K=8.
__device__ __forceinline__ void issue_tf32(uint32_t d, uint64_t da, uint64_t db) {
    uint32_t en = 0;
    #pragma unroll
    for (int g = 0; g < 4; g++)
        #pragma unroll
        for (int s = 0; s < 4; s++) {
            uint64_t off = (uint64_t)(g * 1024 + s * 2);
            mma_tf32_ss(d, da + off, db + off, en);
            en = 1;
        }
}

// Non-blocking cp.async of one 128x128 f32 X tile into swizzled SMEM A.
// Boundary rows zero-filled via src-size = 0.
__device__ __forceinline__ void copy_a_async(
    const float* __restrict__ X, int row0, int n_rows, uint32_t sA_u, int tid)
{
    #pragma unroll
    for (int kk = 0; kk < 16; kk++) {
        int i = tid + kk * 256;              // 0..4095 float4
        int r = i >> 5, j = i & 31;
        int gr = row0 + r;
        uint32_t dst = sA_u + f32_off(r, j * 4);
        const float* src = X + (size_t)gr * DIM + j * 4;
        int sz = (gr < n_rows) ? 16 : 0;
        asm volatile("cp.async.cg.shared.global [%0], [%1], 16, %2;"
                     :: "r"(dst), "l"(src), "r"(sz) : "memory");
    }
    asm volatile("cp.async.commit_group;" ::: "memory");
}
#define CP_WAIT_ALL() asm volatile("cp.async.wait_group 0;" ::: "memory")

// Staged D store: LDTM -> swizzled STS -> coalesced STG. Two 64-row chunks.
__device__ __forceinline__ void store_d_staged(
    float* __restrict__ Y, int row0, int n_rows, uint32_t dtm,
    char* sbuf, int tid, int w, int lane)
{
    #pragma unroll
    for (int c = 0; c < 2; c++) {
        int sub = w & 3;
        if ((sub >> 1) == c) {
            uint32_t c0 = (uint32_t)(w >> 2) * 64;
            uint32_t d[64];
            LDTM_X32(d, dtm + c0);
            LDTM_X32(d + 32, dtm + c0 + 32);
            TC_WAIT_LD();
            int lrow = (sub & 1) * 32 + lane;
            #pragma unroll
            for (int j = 0; j < 16; j++) {
                int col4 = (int)(c0 >> 2) + j;
                int g = col4 ^ (lrow & 31);
                *(float4*)(sbuf + lrow * 512 + g * 16) =
                    make_float4(__uint_as_float(d[4 * j + 0]),
                                __uint_as_float(d[4 * j + 1]),
                                __uint_as_float(d[4 * j + 2]),
                                __uint_as_float(d[4 * j + 3]));
            }
        }
        __syncthreads();

        #pragma unroll
        for (int k = 0; k < 8; k++) {
            int i = tid + k * 256;
            int r = i >> 5, j = i & 31;
            int gr = row0 + c * 64 + r;
            if (gr < n_rows) {
                int g = j ^ (r & 31);
                float4 v = *(const float4*)(sbuf + r * 512 + g * 16);
                ((float4*)(Y + (size_t)gr * DIM))[j] = v;
            }
        }
        __syncthreads();
    }
}
#endif // USE_TC

// ---------------------------------------------------------------------------
__global__ void __launch_bounds__(256) zero_cnt_kernel() {
    int i = blockIdx.x * 256 + threadIdx.x;
    if (i < NP) g_cnt[i] = 0;
}

// ---------------------------------------------------------------------------
// All three W matrices -> swizzled f32 W^T images, pre-rounded to tf32 (rna).
__global__ void __launch_bounds__(256) wconv_kernel(
    const float* __restrict__ W0, const float* __restrict__ W1,
    const float* __restrict__ W2)
{
    int i = blockIdx.x * 256 + threadIdx.x;
    if (i >= 3 * DIM * DIM) return;
    int m = i >> 14, e = i & (DIM * DIM - 1);
    const float* W = (m == 0) ? W0 : (m == 1) ? W1 : W2;
    int k = e >> 7, n = e & 127;
    float x = W[e];                                     // W[k][n]
    uint32_t xb;
#if USE_TC
    asm("cvt.rna.tf32.f32 %0, %1;" : "=r"(xb) : "f"(x));
#else
    xb = __float_as_uint(x);
#endif
    g_Wf[m][f32_off(n, k) >> 2] = __uint_as_float(xb);
}

// ---------------------------------------------------------------------------
// CSR build: histogram, 3-step scan, fill.
__global__ void __launch_bounds__(256) hist_kernel(
    const int* __restrict__ c_dst, const int* __restrict__ w_dst)
{
    int e = blockIdx.x * 256 + threadIdx.x;
    if (e >= E2) return;
    int d = (e < EE) ? __ldg(c_dst + e) : __ldg(w_dst + e - EE);
    atomicAdd(&g_cnt[d], 1);
}

__global__ void __launch_bounds__(256) scan_a_kernel() {
    __shared__ int sm[256];
    int b = blockIdx.x, t = threadIdx.x;
    int i = b * 256 + t;
    int v = (i < NP) ? g_cnt[i] : 0;
    sm[t] = v;
    __syncthreads();
    int acc = v;
    #pragma unroll
    for (int s = 1; s < 256; s <<= 1) {
        int add = (t >= s) ? sm[t - s] : 0;
        __syncthreads();
        acc += add;
        sm[t] = acc;
        __syncthreads();
    }
    if (i < NP) g_off[i] = acc - v;
    if (t == 255) g_bsum[b] = acc;
}

__global__ void __launch_bounds__(512) scan_b_kernel() {
    __shared__ int sm[512];
    int t = threadIdx.x;
    int v = (t < NBLK) ? g_bsum[t] : 0;
    sm[t] = v;
    __syncthreads();
    int acc = v;
    #pragma unroll
    for (int s = 1; s < 512; s <<= 1) {
        int add = (t >= s) ? sm[t - s] : 0;
        __syncthreads();
        acc += add;
        sm[t] = acc;
        __syncthreads();
    }
    if (t < NBLK) g_boff[t] = acc - v;
}

__global__ void __launch_bounds__(256) scan_c_kernel() {
    int b = blockIdx.x, t = threadIdx.x;
    int i = b * 256 + t;
    if (i < NP) {
        int o = g_off[i] + g_boff[b];
        g_off[i] = o;
        g_cur[i] = o;
    }
}

__global__ void __launch_bounds__(256) fill_kernel(
    const int* __restrict__ c_src, const int* __restrict__ c_dst,
    const int* __restrict__ w_src, const int* __restrict__ w_dst)
{
    int e = blockIdx.x * 256 + threadIdx.x;
    if (e >= E2) return;
    int d;
    unsigned sv;
    if (e < EE) {
        d = __ldg(c_dst + e);
        sv = (unsigned)__ldg(c_src + e);
    } else {
        d = __ldg(w_dst + e - EE);
        sv = (unsigned)__ldg(w_src + e - EE) | 0x80000000u;
    }
    int pos = atomicAdd(&g_cur[d], 1);
    g_esrc[pos] = sv;
}

// ---------------------------------------------------------------------------
// Pull aggregation + fused finalize. One warp per paper node. 4-wide gather.
__global__ void __launch_bounds__(256) aggregate_kernel(
    float* __restrict__ out, const float* __restrict__ bias)
{
    int d    = (blockIdx.x * 256 + threadIdx.x) >> 5;
    int lane = threadIdx.x & 31;
    if (d >= NP) return;

    const int n    = g_cnt[d];
    const int base = g_off[d];

    float4 acc = make_float4(0.f, 0.f, 0.f, 0.f);
    int j = 0;
    for (; j + 4 <= n; j += 4) {
        float4 v[4];
        #pragma unroll
        for (int q = 0; q < 4; q++) {
            unsigned s = __ldg(&g_esrc[base + j + q]);
            const float* H = (s & 0x80000000u) ? g_Hw : g_Hc;
            v[q] = ((const float4*)(H + (size_t)(s & 0x7FFFFFFFu) * DIM))[lane];
        }
        acc.x += (v[0].x + v[1].x) + (v[2].x + v[3].x);
        acc.y += (v[0].y + v[1].y) + (v[2].y + v[3].y);
        acc.z += (v[0].z + v[1].z) + (v[2].z + v[3].z);
        acc.w += (v[0].w + v[1].w) + (v[2].w + v[3].w);
    }
    for (; j < n; j++) {
        unsigned s = __ldg(&g_esrc[base + j]);
        const float* H = (s & 0x80000000u) ? g_Hw : g_Hc;
        float4 v = ((const float4*)(H + (size_t)(s & 0x7FFFFFFFu) * DIM))[lane];
        acc.x += v.x; acc.y += v.y; acc.z += v.z; acc.w += v.w;
    }

    const float inv = 1.0f / (float)(n + 1);
    float4* op = (float4*)(out + (size_t)d * DIM) + lane;
    float4 self = *op;
    float4 b = ((const float4*)bias)[lane];
    float4 r;
    r.x = fmaxf(fmaf((self.x + acc.x), inv, b.x), 0.f);
    r.y = fmaxf(fmaf((self.y + acc.y), inv, b.y), 0.f);
    r.z = fmaxf(fmaf((self.z + acc.z), inv, b.z), 0.f);
    r.w = fmaxf(fmaf((self.w + acc.w), inv, b.w), 0.f);
    *op = r;
}

// ---------------------------------------------------------------------------
// ===== Persistent CTA-specialized tf32 GEMM, D double-buffered, async A =====
// SMEM: hdr 1KB | B0 64KB | B1 64KB | A 64KB | sbuf 32KB = 230400.
#define G_MB0  8
#define G_MB1  16
#define G_B0   1024
#define G_B1   (G_B0 + 65536)
#define G_A    (G_B1 + 65536)
#define G_SB   (G_A + 65536)
#define G_TOTAL (G_SB + 32768)      // 230400 <= 232448

__global__ void __launch_bounds__(256, 1) gemm_mega_kernel(
    const float* __restrict__ xp, const float* __restrict__ xa,
    const float* __restrict__ Wc_f, const float* __restrict__ Ww_f,
    const float* __restrict__ Ws_f,
    float* __restrict__ out, float* __restrict__ Hc, float* __restrict__ Hw)
{
    extern __shared__ char smem[];
    const int tid = threadIdx.x, w = tid >> 5, lane = tid & 31;

#if USE_TC
    uint32_t sb = s2u(smem);
    char* sbuf = smem + G_SB;
    const uint32_t sA_u = sb + G_A;

    if (w == 0) {
        TC_ALLOC(sb, 512);
        TC_RELINQ();
    }
    if (tid == 0) {
        MBAR_INIT(sb + G_MB0, 1);
        MBAR_INIT(sb + G_MB1, 1);
    }

    // CTA role
    const int paper = (blockIdx.x < NCTA_P);
    const float* X;
    float *Y1, *Y2;
    int t0, stride, tend, nr;
    if (paper) {
        X = xp; t0 = blockIdx.x;          stride = NCTA_P; tend = NT_P; nr = NP;
        Y1 = out; Y2 = Hc;
    } else {
        X = xa; t0 = blockIdx.x - NCTA_P; stride = NCTA_A; tend = NT_A; nr = NA;
        Y1 = Hw; Y2 = nullptr;
    }

    // Stage B images
    {
        const float* B0s = paper ? g_Wf[2] : g_Wf[1];
        for (int i = tid; i < 4096; i += 256)
            ((float4*)(smem + G_B0))[i] = ((const float4*)B0s)[i];
        if (paper)
            for (int i = tid; i < 4096; i += 256)
                ((float4*)(smem + G_B1))[i] = ((const float4*)g_Wf[0])[i];
    }
    asm volatile("fence.proxy.async.shared::cta;" ::: "memory");
    __syncthreads();

    uint32_t tmem;
    asm volatile("ld.shared.b32 %0, [%1];" : "=r"(tmem) : "r"(sb));

    const uint64_t dB0 = smem_desc(sb + G_B0);
    const uint64_t dB1 = smem_desc(sb + G_B1);
    const uint64_t dA  = smem_desc(sA_u);

    // Prologue: A(t0) + MMA into slot 0
    int t = t0;
    copy_a_async(X, t * 128, nr, sA_u, tid);
    CP_WAIT_ALL();
    asm volatile("fence.proxy.async.shared::cta;" ::: "memory");
    __syncthreads();
    if (w == 0 && elect1()) {
        issue_tf32(tmem + 0, dA, dB0);
        if (paper) issue_tf32(tmem + 128, dA, dB1);
        TC_COMMIT(sb + G_MB0);
    }

    int i = 0;
    for (; t < tend; t += stride, i++) {
        const int s  = i & 1;
        const int ph = (i >> 1) & 1;
        const int row0 = t * 128;

        MBAR_WAIT(sb + (s ? G_MB1 : G_MB0), ph);   // MMA(t) done: A free, D[s] full
        TC_FENCE_AFTER();

        // Launch async copy of A(t+1); it flies under the epilogue below.
        int tn = t + stride;
        if (tn < tend)
            copy_a_async(X, tn * 128, nr, sA_u, tid);

        // Epilogue slot s (overlaps the async A copy)
        store_d_staged(Y1, row0, nr, tmem + (uint32_t)s * 256,
                       sbuf, tid, w, lane);
        if (paper)
            store_d_staged(Y2, row0, nr, tmem + (uint32_t)s * 256 + 128,
                           sbuf, tid, w, lane);
        TC_FENCE_BEFORE();

        // A(t+1) landed -> issue MMA(t+1) into the other slot
        if (tn < tend) {
            CP_WAIT_ALL();
            asm volatile("fence.proxy.async.shared::cta;" ::: "memory");
            __syncthreads();
            if (w == 0 && elect1()) {
                uint32_t ds = (uint32_t)(s ^ 1) * 256;
                issue_tf32(tmem + ds, dA, dB0);
                if (paper) issue_tf32(tmem + ds + 128, dA, dB1);
                TC_COMMIT(sb + ((s ^ 1) ? G_MB1 : G_MB0));
            }
        }
    }

    __syncthreads();
    if (tid == 0) {
        MBAR_INVAL(sb + G_MB0);
        MBAR_INVAL(sb + G_MB1);
    }
    __syncthreads();
    if (w == 0) TC_DEALLOC(tmem, 512);
#else
    // -------- SIMT fallback (non-'a' PTX target only; never runs on GB300) --
    (void)smem;
    for (int t = blockIdx.x; t < NT; t += GRID_PERS) {
        const int paper = (t < NT_P);
        const int row0  = (paper ? t : t - NT_P) * 128;
        const int nr    = paper ? NP : NA;
        const float* X  = paper ? xp : xa;
        const int nw    = paper ? 2 : 1;
        for (int m = 0; m < nw; m++) {
            const float* Wf = paper ? (m ? Wc_f : Ws_f) : Ww_f;
            float* Y = paper ? (m ? g_Hc : out) : g_Hw;
            float acc[16][4];
            #pragma unroll
            for (int r = 0; r < 16; r++)
                acc[r][0] = acc[r][1] = acc[r][2] = acc[r][3] = 0.f;
            for (int k4 = 0; k4 < 32; k4++) {
                float4 w0 = __ldg((const float4*)(Wf + (k4 * 4 + 0) * DIM) + lane);
                float4 w1 = __ldg((const float4*)(Wf + (k4 * 4 + 1) * DIM) + lane);
                float4 w2 = __ldg((const float4*)(Wf + (k4 * 4 + 2) * DIM) + lane);
                float4 w3 = __ldg((const float4*)(Wf + (k4 * 4 + 3) * DIM) + lane);
                for (int r = 0; r < 16; r++) {
                    int gr = row0 + w + 8 * r;
                    float4 xv = (gr < nr)
                        ? __ldg((const float4*)(X + (size_t)gr * DIM) + k4)
                        : make_float4(0.f, 0.f, 0.f, 0.f);
                    acc[r][0] += xv.x * w0.x + xv.y * w1.x + xv.z * w2.x + xv.w * w3.x;
                    acc[r][1] += xv.x * w0.y + xv.y * w1.y + xv.z * w2.y + xv.w * w3.y;
                    acc[r][2] += xv.x * w0.z + xv.y * w1.z + xv.z * w2.z + xv.w * w3.z;
                    acc[r][3] += xv.x * w0.w + xv.y * w1.w + xv.z * w2.w + xv.w * w3.w;
                }
            }
            #pragma unroll
            for (int r = 0; r < 16; r++) {
                int gr = row0 + w + 8 * r;
                if (gr < nr)
                    ((float4*)(Y + (size_t)gr * DIM))[lane] =
                        make_float4(acc[r][0], acc[r][1], acc[r][2], acc[r][3]);
            }
        }
    }
#endif
}

// ---------------------------------------------------------------------------
extern "C" void kernel_launch(void* const* d_in, const int* in_sizes, int n_in,
                              void* d_out, int out_size)
{
    const float* x_paper    = (const float*)d_in[0];
    const float* x_author   = (const float*)d_in[1];
    const float* W_cites    = (const float*)d_in[2];
    const float* W_writes   = (const float*)d_in[3];
    const float* W_self     = (const float*)d_in[4];
    const float* bias       = (const float*)d_in[5];
    const int*   cites_src  = (const int*)d_in[6];
    const int*   cites_dst  = (const int*)d_in[7];
    const int*   writes_src = (const int*)d_in[8];
    const int*   writes_dst = (const int*)d_in[9];
    float*       out        = (float*)d_out;

    cudaFuncSetAttribute(gemm_mega_kernel,
                         cudaFuncAttributeMaxDynamicSharedMemorySize, G_TOTAL);

    void *pHc = nullptr, *pHw = nullptr;
    cudaGetSymbolAddress(&pHc, g_Hc);
    cudaGetSymbolAddress(&pHw, g_Hw);

    // Fork a side stream for the CSR chain (graph-capture-legal fork/join).
    cudaStream_t s2;
    cudaStreamCreateWithFlags(&s2, cudaStreamNonBlocking);
    cudaEvent_t ev_fork, ev_join;
    cudaEventCreateWithFlags(&ev_fork, cudaEventDisableTiming);
    cudaEventCreateWithFlags(&ev_join, cudaEventDisableTiming);

    cudaEventRecord(ev_fork, 0);
    cudaStreamWaitEvent(s2, ev_fork, 0);

    // --- side stream: CSR build ---
    zero_cnt_kernel<<<NBLK, 256, 0, s2>>>();
    hist_kernel<<<(E2 + 255) / 256, 256, 0, s2>>>(cites_dst, writes_dst);
    scan_a_kernel<<<NBLK, 256, 0, s2>>>();
    scan_b_kernel<<<1, 512, 0, s2>>>();
    scan_c_kernel<<<NBLK, 256, 0, s2>>>();
    fill_kernel<<<(E2 + 255) / 256, 256, 0, s2>>>(cites_src, cites_dst,
                                                  writes_src, writes_dst);
    cudaEventRecord(ev_join, s2);

    // --- main stream: W images + persistent pipelined GEMM ---
    wconv_kernel<<<(3 * DIM * DIM + 255) / 256, 256>>>(W_cites, W_writes, W_self);
    gemm_mega_kernel<<<GRID_PERS, 256, G_TOTAL>>>(
        x_paper, x_author, W_cites, W_writes, W_self,
        out, (float*)pHc, (float*)pHw);

    // join: aggregate needs both chains
    cudaStreamWaitEvent(0, ev_join, 0);
    aggregate_kernel<<<(NP * 32 + 255) / 256, 256>>>(out, bias);

    cudaEventDestroy(ev_fork);
    cudaEventDestroy(ev_join);
    cudaStreamDestroy(s2);
}

// round 13
// speedup vs baseline: 3.8707x; 1.1263x over previous
#include <cuda_runtime.h>
#include <cuda_bf16.h>
#include <cuda_fp16.h>
#include <cstdint>

#define NP 100000
#define NA 50000
#define DIM 128
#define EE  500000
#define E2  (2 * EE)

#define NT_P 782            // ceil(NP/128) paper tiles
#define NT_A 391            // ceil(NA/128) author tiles
#define NT   (NT_P + NT_A)
#define NCTA_P 122          // paper CTAs
#define NCTA_A 30           // author CTAs
#define GRID_PERS (NCTA_P + NCTA_A)   // 152 = GB300 SM count

#define NBLK 391            // ceil(NP/256) scan blocks

#if defined(__CUDA_ARCH__) && defined(__CUDA_ARCH_FEAT_SM103_ALL)
#define USE_TC 1
#else
#define USE_TC 0
#endif

// ---------------------------------------------------------------------------
// Scratch (allocation-guard-safe __device__ globals)
__device__ __half g_Hc[(size_t)NP * DIM];         // x_paper  @ W_cites (fp16)
__device__ __half g_Hw[(size_t)NA * DIM];         // x_author @ W_writes (fp16)
__device__ float g_Wf[3][DIM * DIM];              // swizzled f32 W^T images:
                                                  // [0]=cites [1]=writes [2]=self
// CSR-by-dst machinery
__device__ int g_cnt[NP];
__device__ int g_off[NP];
__device__ int g_cur[NP];
__device__ int g_bsum[NBLK + 1];
__device__ int g_boff[NBLK + 1];
__device__ unsigned g_esrc[E2];                   // src | (rel<<31), grouped by dst

// ---------------------------------------------------------------------------
// Swizzled byte offset of f32 element (r,k) in a 128x128 f32 K-major
// blocked-atom tile: atom = 8 rows x 32 f32 (1024B), 16 atom-rows x 4
// atom-cols. SW128 swizzle on top.
__device__ __forceinline__ uint32_t f32_off(int r, int k) {
    uint32_t b = (uint32_t)(((r >> 3) + (k >> 5) * 16) * 1024
                            + (r & 7) * 128 + (k & 31) * 4);
    return b ^ ((b >> 3) & 0x70);
}

#if USE_TC
// ---------------------------------------------------------------------------
// PTX helpers (sm_103a tcgen05, cg1) — only on the 'a' target.
__device__ __forceinline__ uint32_t s2u(const void* p) {
    uint32_t a;
    asm("{ .reg .u64 t; cvta.to.shared.u64 t, %1; cvt.u32.u64 %0, t; }"
        : "=r"(a) : "l"(p));
    return a;
}
__device__ __forceinline__ bool elect1() {
    uint32_t p;
    asm volatile("{ .reg .pred p; elect.sync _|p, 0xFFFFFFFF; selp.b32 %0,1,0,p; }"
                 : "=r"(p));
    return p != 0;
}
// idesc kind::tf32: dtype=F32(1<<4), atype=TF32(2<<7), btype=TF32(2<<10),
// (N/8)<<17, (M/16)<<24  -> M=128, N=128
#define IDESC_TF32_128 0x8200910u

__device__ __forceinline__ void mma_tf32_ss(uint32_t d, uint64_t a, uint64_t b,
                                            uint32_t en) {
    asm volatile(
        "{\n\t.reg .pred p;\n\tsetp.ne.u32 p, %4, 0;\n\t"
        "tcgen05.mma.cta_group::1.kind::tf32 [%0], %1, %2, %3, {%5,%5,%5,%5}, p;\n\t}"
        :: "r"(d), "l"(a), "l"(b), "r"(IDESC_TF32_128), "r"(en), "r"(0u)
        : "memory");
}
#define TC_ALLOC(sa, n)  asm volatile("tcgen05.alloc.cta_group::1.sync.aligned.shared::cta.b32 [%0], %1;" :: "r"(sa), "r"(n) : "memory")
#define TC_DEALLOC(t, n) asm volatile("tcgen05.dealloc.cta_group::1.sync.aligned.b32 %0, %1;" :: "r"(t), "r"(n))
#define TC_RELINQ()      asm volatile("tcgen05.relinquish_alloc_permit.cta_group::1.sync.aligned;")
#define TC_COMMIT(mb)    asm volatile("tcgen05.commit.cta_group::1.mbarrier::arrive::one.shared::cluster.b64 [%0];" :: "r"(mb) : "memory")
#define TC_WAIT_LD()     asm volatile("tcgen05.wait::ld.sync.aligned;" ::: "memory")
#define TC_FENCE_BEFORE() asm volatile("tcgen05.fence::before_thread_sync;" ::: "memory")
#define TC_FENCE_AFTER()  asm volatile("tcgen05.fence::after_thread_sync;" ::: "memory")
#define MBAR_INIT(mb, c) asm volatile("mbarrier.init.shared.b64 [%0], %1;" :: "r"(mb), "r"(c) : "memory")
#define MBAR_INVAL(mb)   asm volatile("mbarrier.inval.shared.b64 [%0];" :: "r"(mb) : "memory")
#define MBAR_WAIT(mb, ph) do {                                                      \
    uint32_t _m = (mb), _p = (ph), _d;                                              \
    asm volatile("{ .reg .pred p; mbarrier.try_wait.parity.acquire.cta.shared::cta.b64 p, [%1], %2; selp.b32 %0,1,0,p; }" \
                 : "=r"(_d) : "r"(_m), "r"(_p) : "memory");                         \
    if (!_d) {                                                                      \
        asm volatile("{ .reg .pred P1; WL_%=: mbarrier.try_wait.parity.acquire.cta.shared::cta.b64 P1, [%0], %1, 0x989680; @P1 bra.uni WD_%=; bra.uni WL_%=; WD_%=: }" \
                     :: "r"(_m), "r"(_p) : "memory");                               \
    }                                                                               \
} while (0)
#define LDTM_X32(r, a)                                                              \
    asm volatile("tcgen05.ld.sync.aligned.32x32b.x32.b32 "                          \
        "{%0,%1,%2,%3,%4,%5,%6,%7,%8,%9,%10,%11,%12,%13,%14,%15,"                   \
        "%16,%17,%18,%19,%20,%21,%22,%23,%24,%25,%26,%27,%28,%29,%30,%31}, [%32];"  \
        : "=r"((r)[0]),"=r"((r)[1]),"=r"((r)[2]),"=r"((r)[3]),                      \
          "=r"((r)[4]),"=r"((r)[5]),"=r"((r)[6]),"=r"((r)[7]),                      \
          "=r"((r)[8]),"=r"((r)[9]),"=r"((r)[10]),"=r"((r)[11]),                    \
          "=r"((r)[12]),"=r"((r)[13]),"=r"((r)[14]),"=r"((r)[15]),                  \
          "=r"((r)[16]),"=r"((r)[17]),"=r"((r)[18]),"=r"((r)[19]),                  \
          "=r"((r)[20]),"=r"((r)[21]),"=r"((r)[22]),"=r"((r)[23]),                  \
          "=r"((r)[24]),"=r"((r)[25]),"=r"((r)[26]),"=r"((r)[27]),                  \
          "=r"((r)[28]),"=r"((r)[29]),"=r"((r)[30]),"=r"((r)[31])                   \
        : "r"(a))

// SMEM descriptor: SW128, version=1(Blackwell), LBO=1, SBO=64 (K-major)
static __device__ __forceinline__ uint64_t smem_desc(uint32_t addr) {
    const uint64_t base = (uint64_t(2) << 61) | (uint64_t(1) << 46)
                        | (uint64_t(64) << 32) | (uint64_t(1) << 16);
    return base | ((uint64_t)(addr >> 4) & 0x3FFF);
}

// Full 128x128 K=128 tf32 gemm into D: 16 K-steps of K=8.
__device__ __forceinline__ void issue_tf32(uint32_t d, uint64_t da, uint64_t db) {
    uint32_t en = 0;
    #pragma unroll
    for (int g = 0; g < 4; g++)
        #pragma unroll
        for (int s = 0; s < 4; s++) {
            uint64_t off = (uint64_t)(g * 1024 + s * 2);
            mma_tf32_ss(d, da + off, db + off, en);
            en = 1;
        }
}

// Non-blocking cp.async of one 128x128 f32 X tile into swizzled SMEM A.
__device__ __forceinline__ void copy_a_async(
    const float* __restrict__ X, int row0, int n_rows, uint32_t sA_u, int tid)
{
    #pragma unroll
    for (int kk = 0; kk < 16; kk++) {
        int i = tid + kk * 256;              // 0..4095 float4
        int r = i >> 5, j = i & 31;
        int gr = row0 + r;
        uint32_t dst = sA_u + f32_off(r, j * 4);
        const float* src = X + (size_t)gr * DIM + j * 4;
        int sz = (gr < n_rows) ? 16 : 0;
        asm volatile("cp.async.cg.shared.global [%0], [%1], 16, %2;"
                     :: "r"(dst), "l"(src), "r"(sz) : "memory");
    }
    asm volatile("cp.async.commit_group;" ::: "memory");
}
#define CP_WAIT_ALL() asm volatile("cp.async.wait_group 0;" ::: "memory")

// Shared staging step: LDTM D -> swizzled f32 STS into sbuf (one 64-row chunk).
__device__ __forceinline__ void stage_chunk(
    uint32_t dtm, int c, char* sbuf, int w, int lane)
{
    int sub = w & 3;
    if ((sub >> 1) == c) {
        uint32_t c0 = (uint32_t)(w >> 2) * 64;
        uint32_t d[64];
        LDTM_X32(d, dtm + c0);
        LDTM_X32(d + 32, dtm + c0 + 32);
        TC_WAIT_LD();
        int lrow = (sub & 1) * 32 + lane;
        #pragma unroll
        for (int j = 0; j < 16; j++) {
            int col4 = (int)(c0 >> 2) + j;
            int g = col4 ^ (lrow & 31);
            *(float4*)(sbuf + lrow * 512 + g * 16) =
                make_float4(__uint_as_float(d[4 * j + 0]),
                            __uint_as_float(d[4 * j + 1]),
                            __uint_as_float(d[4 * j + 2]),
                            __uint_as_float(d[4 * j + 3]));
        }
    }
    __syncthreads();
}

// Staged D store, f32 output (for d_out).
__device__ __forceinline__ void store_d_f32(
    float* __restrict__ Y, int row0, int n_rows, uint32_t dtm,
    char* sbuf, int tid, int w, int lane)
{
    #pragma unroll
    for (int c = 0; c < 2; c++) {
        stage_chunk(dtm, c, sbuf, w, lane);
        #pragma unroll
        for (int k = 0; k < 8; k++) {
            int i = tid + k * 256;
            int r = i >> 5, j = i & 31;
            int gr = row0 + c * 64 + r;
            if (gr < n_rows) {
                int g = j ^ (r & 31);
                float4 v = *(const float4*)(sbuf + r * 512 + g * 16);
                ((float4*)(Y + (size_t)gr * DIM))[j] = v;
            }
        }
        __syncthreads();
    }
}

// Staged D store, fp16 output (for g_Hc / g_Hw). Coalesced 8B stores.
__device__ __forceinline__ void store_d_f16(
    __half* __restrict__ Y, int row0, int n_rows, uint32_t dtm,
    char* sbuf, int tid, int w, int lane)
{
    #pragma unroll
    for (int c = 0; c < 2; c++) {
        stage_chunk(dtm, c, sbuf, w, lane);
        #pragma unroll
        for (int k = 0; k < 8; k++) {
            int i = tid + k * 256;
            int r = i >> 5, j = i & 31;
            int gr = row0 + c * 64 + r;
            if (gr < n_rows) {
                int g = j ^ (r & 31);
                float4 v = *(const float4*)(sbuf + r * 512 + g * 16);
                __half2 h01 = __floats2half2_rn(v.x, v.y);
                __half2 h23 = __floats2half2_rn(v.z, v.w);
                ((uint2*)(Y + (size_t)gr * DIM))[j] =
                    make_uint2(*(uint32_t*)&h01, *(uint32_t*)&h23);
            }
        }
        __syncthreads();
    }
}
#endif // USE_TC

// ---------------------------------------------------------------------------
__global__ void __launch_bounds__(256) zero_cnt_kernel() {
    int i = blockIdx.x * 256 + threadIdx.x;
    if (i < NP) g_cnt[i] = 0;
}

// ---------------------------------------------------------------------------
// All three W matrices -> swizzled f32 W^T images, pre-rounded to tf32 (rna).
__global__ void __launch_bounds__(256) wconv_kernel(
    const float* __restrict__ W0, const float* __restrict__ W1,
    const float* __restrict__ W2)
{
    int i = blockIdx.x * 256 + threadIdx.x;
    if (i >= 3 * DIM * DIM) return;
    int m = i >> 14, e = i & (DIM * DIM - 1);
    const float* W = (m == 0) ? W0 : (m == 1) ? W1 : W2;
    int k = e >> 7, n = e & 127;
    float x = W[e];                                     // W[k][n]
    uint32_t xb;
#if USE_TC
    asm("cvt.rna.tf32.f32 %0, %1;" : "=r"(xb) : "f"(x));
#else
    xb = __float_as_uint(x);
#endif
    g_Wf[m][f32_off(n, k) >> 2] = __uint_as_float(xb);
}

// ---------------------------------------------------------------------------
// CSR build: histogram, 3-step scan, fill.
__global__ void __launch_bounds__(256) hist_kernel(
    const int* __restrict__ c_dst, const int* __restrict__ w_dst)
{
    int e = blockIdx.x * 256 + threadIdx.x;
    if (e >= E2) return;
    int d = (e < EE) ? __ldg(c_dst + e) : __ldg(w_dst + e - EE);
    atomicAdd(&g_cnt[d], 1);
}

__global__ void __launch_bounds__(256) scan_a_kernel() {
    __shared__ int sm[256];
    int b = blockIdx.x, t = threadIdx.x;
    int i = b * 256 + t;
    int v = (i < NP) ? g_cnt[i] : 0;
    sm[t] = v;
    __syncthreads();
    int acc = v;
    #pragma unroll
    for (int s = 1; s < 256; s <<= 1) {
        int add = (t >= s) ? sm[t - s] : 0;
        __syncthreads();
        acc += add;
        sm[t] = acc;
        __syncthreads();
    }
    if (i < NP) g_off[i] = acc - v;
    if (t == 255) g_bsum[b] = acc;
}

__global__ void __launch_bounds__(512) scan_b_kernel() {
    __shared__ int sm[512];
    int t = threadIdx.x;
    int v = (t < NBLK) ? g_bsum[t] : 0;
    sm[t] = v;
    __syncthreads();
    int acc = v;
    #pragma unroll
    for (int s = 1; s < 512; s <<= 1) {
        int add = (t >= s) ? sm[t - s] : 0;
        __syncthreads();
        acc += add;
        sm[t] = acc;
        __syncthreads();
    }
    if (t < NBLK) g_boff[t] = acc - v;
}

__global__ void __launch_bounds__(256) scan_c_kernel() {
    int b = blockIdx.x, t = threadIdx.x;
    int i = b * 256 + t;
    if (i < NP) {
        int o = g_off[i] + g_boff[b];
        g_off[i] = o;
        g_cur[i] = o;
    }
}

__global__ void __launch_bounds__(256) fill_kernel(
    const int* __restrict__ c_src, const int* __restrict__ c_dst,
    const int* __restrict__ w_src, const int* __restrict__ w_dst)
{
    int e = blockIdx.x * 256 + threadIdx.x;
    if (e >= E2) return;
    int d;
    unsigned sv;
    if (e < EE) {
        d = __ldg(c_dst + e);
        sv = (unsigned)__ldg(c_src + e);
    } else {
        d = __ldg(w_dst + e - EE);
        sv = (unsigned)__ldg(w_src + e - EE) | 0x80000000u;
    }
    int pos = atomicAdd(&g_cur[d], 1);
    g_esrc[pos] = sv;
}

// ---------------------------------------------------------------------------
// Pull aggregation + fused finalize. One warp per paper node. fp16 messages
// gathered as uint2 (4 halves = this lane's 4 cols), accumulated in f32.
__global__ void __launch_bounds__(256) aggregate_kernel(
    float* __restrict__ out, const float* __restrict__ bias)
{
    int d    = (blockIdx.x * 256 + threadIdx.x) >> 5;
    int lane = threadIdx.x & 31;
    if (d >= NP) return;

    const int n    = g_cnt[d];
    const int base = g_off[d];

    float4 acc = make_float4(0.f, 0.f, 0.f, 0.f);
    int j = 0;
    for (; j + 4 <= n; j += 4) {
        uint2 u[4];
        #pragma unroll
        for (int q = 0; q < 4; q++) {
            unsigned s = __ldg(&g_esrc[base + j + q]);
            const __half* H = (s & 0x80000000u) ? g_Hw : g_Hc;
            u[q] = __ldg((const uint2*)(H + (size_t)(s & 0x7FFFFFFFu) * DIM)
                         + lane);
        }
        #pragma unroll
        for (int q = 0; q < 4; q++) {
            float2 f01 = __half22float2(*(__half2*)&u[q].x);
            float2 f23 = __half22float2(*(__half2*)&u[q].y);
            acc.x += f01.x; acc.y += f01.y;
            acc.z += f23.x; acc.w += f23.y;
        }
    }
    for (; j < n; j++) {
        unsigned s = __ldg(&g_esrc[base + j]);
        const __half* H = (s & 0x80000000u) ? g_Hw : g_Hc;
        uint2 u = __ldg((const uint2*)(H + (size_t)(s & 0x7FFFFFFFu) * DIM)
                        + lane);
        float2 f01 = __half22float2(*(__half2*)&u.x);
        float2 f23 = __half22float2(*(__half2*)&u.y);
        acc.x += f01.x; acc.y += f01.y;
        acc.z += f23.x; acc.w += f23.y;
    }

    const float inv = 1.0f / (float)(n + 1);
    float4* op = (float4*)(out + (size_t)d * DIM) + lane;
    float4 self = *op;
    float4 b = ((const float4*)bias)[lane];
    float4 r;
    r.x = fmaxf(fmaf((self.x + acc.x), inv, b.x), 0.f);
    r.y = fmaxf(fmaf((self.y + acc.y), inv, b.y), 0.f);
    r.z = fmaxf(fmaf((self.z + acc.z), inv, b.z), 0.f);
    r.w = fmaxf(fmaf((self.w + acc.w), inv, b.w), 0.f);
    *op = r;
}

// ---------------------------------------------------------------------------
// ===== Persistent CTA-specialized tf32 GEMM, D double-buffered, async A =====
// SMEM: hdr 1KB | B0 64KB | B1 64KB | A 64KB | sbuf 32KB = 230400.
#define G_MB0  8
#define G_MB1  16
#define G_B0   1024
#define G_B1   (G_B0 + 65536)
#define G_A    (G_B1 + 65536)
#define G_SB   (G_A + 65536)
#define G_TOTAL (G_SB + 32768)      // 230400 <= 232448

__global__ void __launch_bounds__(256, 1) gemm_mega_kernel(
    const float* __restrict__ xp, const float* __restrict__ xa,
    const float* __restrict__ Wc_f, const float* __restrict__ Ww_f,
    const float* __restrict__ Ws_f,
    float* __restrict__ out, __half* __restrict__ Hc, __half* __restrict__ Hw)
{
    extern __shared__ char smem[];
    const int tid = threadIdx.x, w = tid >> 5, lane = tid & 31;

#if USE_TC
    uint32_t sb = s2u(smem);
    char* sbuf = smem + G_SB;
    const uint32_t sA_u = sb + G_A;

    if (w == 0) {
        TC_ALLOC(sb, 512);
        TC_RELINQ();
    }
    if (tid == 0) {
        MBAR_INIT(sb + G_MB0, 1);
        MBAR_INIT(sb + G_MB1, 1);
    }

    // CTA role
    const int paper = (blockIdx.x < NCTA_P);
    const float* X;
    int t0, stride, tend, nr;
    if (paper) {
        X = xp; t0 = blockIdx.x;          stride = NCTA_P; tend = NT_P; nr = NP;
    } else {
        X = xa; t0 = blockIdx.x - NCTA_P; stride = NCTA_A; tend = NT_A; nr = NA;
    }

    // Stage B images
    {
        const float* B0s = paper ? g_Wf[2] : g_Wf[1];
        for (int i = tid; i < 4096; i += 256)
            ((float4*)(smem + G_B0))[i] = ((const float4*)B0s)[i];
        if (paper)
            for (int i = tid; i < 4096; i += 256)
                ((float4*)(smem + G_B1))[i] = ((const float4*)g_Wf[0])[i];
    }
    asm volatile("fence.proxy.async.shared::cta;" ::: "memory");
    __syncthreads();

    uint32_t tmem;
    asm volatile("ld.shared.b32 %0, [%1];" : "=r"(tmem) : "r"(sb));

    const uint64_t dB0 = smem_desc(sb + G_B0);
    const uint64_t dB1 = smem_desc(sb + G_B1);
    const uint64_t dA  = smem_desc(sA_u);

    // Prologue: A(t0) + MMA into slot 0
    int t = t0;
    copy_a_async(X, t * 128, nr, sA_u, tid);
    CP_WAIT_ALL();
    asm volatile("fence.proxy.async.shared::cta;" ::: "memory");
    __syncthreads();
    if (w == 0 && elect1()) {
        issue_tf32(tmem + 0, dA, dB0);
        if (paper) issue_tf32(tmem + 128, dA, dB1);
        TC_COMMIT(sb + G_MB0);
    }

    int i = 0;
    for (; t < tend; t += stride, i++) {
        const int s  = i & 1;
        const int ph = (i >> 1) & 1;
        const int row0 = t * 128;

        MBAR_WAIT(sb + (s ? G_MB1 : G_MB0), ph);   // MMA(t) done: A free, D[s] full
        TC_FENCE_AFTER();

        // Launch async copy of A(t+1); it flies under the epilogue below.
        int tn = t + stride;
        if (tn < tend)
            copy_a_async(X, tn * 128, nr, sA_u, tid);

        // Epilogue slot s (overlaps the async A copy)
        if (paper) {
            store_d_f32(out, row0, nr, tmem + (uint32_t)s * 256,
                        sbuf, tid, w, lane);
            store_d_f16(Hc, row0, nr, tmem + (uint32_t)s * 256 + 128,
                        sbuf, tid, w, lane);
        } else {
            store_d_f16(Hw, row0, nr, tmem + (uint32_t)s * 256,
                        sbuf, tid, w, lane);
        }
        TC_FENCE_BEFORE();

        // A(t+1) landed -> issue MMA(t+1) into the other slot
        if (tn < tend) {
            CP_WAIT_ALL();
            asm volatile("fence.proxy.async.shared::cta;" ::: "memory");
            __syncthreads();
            if (w == 0 && elect1()) {
                uint32_t ds = (uint32_t)(s ^ 1) * 256;
                issue_tf32(tmem + ds, dA, dB0);
                if (paper) issue_tf32(tmem + ds + 128, dA, dB1);
                TC_COMMIT(sb + ((s ^ 1) ? G_MB1 : G_MB0));
            }
        }
    }

    __syncthreads();
    if (tid == 0) {
        MBAR_INVAL(sb + G_MB0);
        MBAR_INVAL(sb + G_MB1);
    }
    __syncthreads();
    if (w == 0) TC_DEALLOC(tmem, 512);
#else
    // -------- SIMT fallback (non-'a' PTX target only; never runs on GB300) --
    (void)smem;
    for (int t = blockIdx.x; t < NT; t += GRID_PERS) {
        const int paper = (t < NT_P);
        const int row0  = (paper ? t : t - NT_P) * 128;
        const int nr    = paper ? NP : NA;
        const float* X  = paper ? xp : xa;
        const int nw    = paper ? 2 : 1;
        for (int m = 0; m < nw; m++) {
            const float* Wf = paper ? (m ? Wc_f : Ws_f) : Ww_f;
            float acc[16][4];
            #pragma unroll
            for (int r = 0; r < 16; r++)
                acc[r][0] = acc[r][1] = acc[r][2] = acc[r][3] = 0.f;
            for (int k4 = 0; k4 < 32; k4++) {
                float4 w0 = __ldg((const float4*)(Wf + (k4 * 4 + 0) * DIM) + lane);
                float4 w1 = __ldg((const float4*)(Wf + (k4 * 4 + 1) * DIM) + lane);
                float4 w2 = __ldg((const float4*)(Wf + (k4 * 4 + 2) * DIM) + lane);
                float4 w3 = __ldg((const float4*)(Wf + (k4 * 4 + 3) * DIM) + lane);
                for (int r = 0; r < 16; r++) {
                    int gr = row0 + w + 8 * r;
                    float4 xv = (gr < nr)
                        ? __ldg((const float4*)(X + (size_t)gr * DIM) + k4)
                        : make_float4(0.f, 0.f, 0.f, 0.f);
                    acc[r][0] += xv.x * w0.x + xv.y * w1.x + xv.z * w2.x + xv.w * w3.x;
                    acc[r][1] += xv.x * w0.y + xv.y * w1.y + xv.z * w2.y + xv.w * w3.y;
                    acc[r][2] += xv.x * w0.z + xv.y * w1.z + xv.z * w2.z + xv.w * w3.z;
                    acc[r][3] += xv.x * w0.w + xv.y * w1.w + xv.z * w2.w + xv.w * w3.w;
                }
            }
            #pragma unroll
            for (int r = 0; r < 16; r++) {
                int gr = row0 + w + 8 * r;
                if (gr >= nr) continue;
                if (paper && m == 0) {
                    ((float4*)(out + (size_t)gr * DIM))[lane] =
                        make_float4(acc[r][0], acc[r][1], acc[r][2], acc[r][3]);
                } else {
                    __half* Y = paper ? Hc : Hw;
                    __half2 h01 = __floats2half2_rn(acc[r][0], acc[r][1]);
                    __half2 h23 = __floats2half2_rn(acc[r][2], acc[r][3]);
                    ((uint2*)(Y + (size_t)gr * DIM))[lane] =
                        make_uint2(*(uint32_t*)&h01, *(uint32_t*)&h23);
                }
            }
        }
    }
#endif
}

// ---------------------------------------------------------------------------
extern "C" void kernel_launch(void* const* d_in, const int* in_sizes, int n_in,
                              void* d_out, int out_size)
{
    const float* x_paper    = (const float*)d_in[0];
    const float* x_author   = (const float*)d_in[1];
    const float* W_cites    = (const float*)d_in[2];
    const float* W_writes   = (const float*)d_in[3];
    const float* W_self     = (const float*)d_in[4];
    const float* bias       = (const float*)d_in[5];
    const int*   cites_src  = (const int*)d_in[6];
    const int*   cites_dst  = (const int*)d_in[7];
    const int*   writes_src = (const int*)d_in[8];
    const int*   writes_dst = (const int*)d_in[9];
    float*       out        = (float*)d_out;

    cudaFuncSetAttribute(gemm_mega_kernel,
                         cudaFuncAttributeMaxDynamicSharedMemorySize, G_TOTAL);

    void *pHc = nullptr, *pHw = nullptr;
    cudaGetSymbolAddress(&pHc, g_Hc);
    cudaGetSymbolAddress(&pHw, g_Hw);

    // Fork a side stream for the CSR chain (graph-capture-legal fork/join).
    cudaStream_t s2;
    cudaStreamCreateWithFlags(&s2, cudaStreamNonBlocking);
    cudaEvent_t ev_fork, ev_join;
    cudaEventCreateWithFlags(&ev_fork, cudaEventDisableTiming);
    cudaEventCreateWithFlags(&ev_join, cudaEventDisableTiming);

    cudaEventRecord(ev_fork, 0);
    cudaStreamWaitEvent(s2, ev_fork, 0);

    // --- side stream: CSR build ---
    zero_cnt_kernel<<<NBLK, 256, 0, s2>>>();
    hist_kernel<<<(E2 + 255) / 256, 256, 0, s2>>>(cites_dst, writes_dst);
    scan_a_kernel<<<NBLK, 256, 0, s2>>>();
    scan_b_kernel<<<1, 512, 0, s2>>>();
    scan_c_kernel<<<NBLK, 256, 0, s2>>>();
    fill_kernel<<<(E2 + 255) / 256, 256, 0, s2>>>(cites_src, cites_dst,
                                                  writes_src, writes_dst);
    cudaEventRecord(ev_join, s2);

    // --- main stream: W images + persistent pipelined GEMM ---
    wconv_kernel<<<(3 * DIM * DIM + 255) / 256, 256>>>(W_cites, W_writes, W_self);
    gemm_mega_kernel<<<GRID_PERS, 256, G_TOTAL>>>(
        x_paper, x_author, W_cites, W_writes, W_self,
        out, (__half*)pHc, (__half*)pHw);

    // join: aggregate needs both chains
    cudaStreamWaitEvent(0, ev_join, 0);
    aggregate_kernel<<<(NP * 32 + 255) / 256, 256>>>(out, bias);

    cudaEventDestroy(ev_fork);
    cudaEventDestroy(ev_join);
    cudaStreamDestroy(s2);
}